// round 1
// baseline (speedup 1.0000x reference)
#include <cuda_runtime.h>
#include <cuda_bf16.h>
#include <math.h>

#define S_LEN 2048
#define DIN   2048
#define H_Q   32
#define G_KV  8
#define HD    128
#define DOUT  (H_Q*HD)   /* 4096 */
#define GKD   (G_KV*HD)  /* 1024 */

// Scratch (allocation-free rule: __device__ globals)
__device__ float g_q  [S_LEN * (size_t)DOUT];   // 32 MB: Q proj, then normed+roped Q in-place
__device__ float g_k  [S_LEN * (size_t)GKD];    //  8 MB: raw K proj
__device__ float g_ctx[S_LEN * (size_t)DOUT];   // 32 MB: attention context

// ---------------------------------------------------------------------------
// Register-blocked SGEMM: C[M,N] = A[M,K] @ B[K,N], fp32.
// BM=BN=128, BK=16, 256 threads, 8x8 per thread. All dims are multiples of
// the tile sizes for this problem, so no bounds checks.
// vmode==1: scatter-write for the V projection directly into next_v layout
//           [G, S, HD]:  addr = (c/128)*S*128 + r*128 + (c%128)
// ---------------------------------------------------------------------------
__global__ __launch_bounds__(256) void sgemm_kernel(
    const float* __restrict__ A, const float* __restrict__ B,
    float* __restrict__ C, int M, int N, int K, int vmode)
{
    __shared__ float As[16][128];   // transposed A tile
    __shared__ float Bs[16][128];
    const int tid = threadIdx.x;
    const int tx = tid & 15, ty = tid >> 4;
    const int brow = blockIdx.y * 128, bcol = blockIdx.x * 128;

    float acc[8][8];
    #pragma unroll
    for (int i = 0; i < 8; i++)
        #pragma unroll
        for (int j = 0; j < 8; j++) acc[i][j] = 0.f;

    for (int k0 = 0; k0 < K; k0 += 16) {
        #pragma unroll
        for (int u = 0; u < 2; u++) {
            int f  = tid + u * 256;          // float4 id, 512 total per tile
            int r  = f >> 2;                 // A: 4 float4 per row of 16
            int kc = (f & 3) << 2;
            float4 va = *(const float4*)(A + (size_t)(brow + r) * K + k0 + kc);
            As[kc + 0][r] = va.x; As[kc + 1][r] = va.y;
            As[kc + 2][r] = va.z; As[kc + 3][r] = va.w;
            int kr = f >> 5;                 // B: 32 float4 per row of 128
            int nc = (f & 31) << 2;
            *(float4*)(&Bs[kr][nc]) =
                *(const float4*)(B + (size_t)(k0 + kr) * N + bcol + nc);
        }
        __syncthreads();
        #pragma unroll
        for (int kk = 0; kk < 16; kk++) {
            float a[8], b[8];
            *(float4*)(a)     = *(float4*)(&As[kk][ty * 8]);
            *(float4*)(a + 4) = *(float4*)(&As[kk][ty * 8 + 4]);
            *(float4*)(b)     = *(float4*)(&Bs[kk][tx * 8]);
            *(float4*)(b + 4) = *(float4*)(&Bs[kk][tx * 8 + 4]);
            #pragma unroll
            for (int i = 0; i < 8; i++)
                #pragma unroll
                for (int j = 0; j < 8; j++)
                    acc[i][j] = fmaf(a[i], b[j], acc[i][j]);
        }
        __syncthreads();
    }

    #pragma unroll
    for (int i = 0; i < 8; i++) {
        int r = brow + ty * 8 + i;
        if (vmode == 0) {
            float4 v0 = make_float4(acc[i][0], acc[i][1], acc[i][2], acc[i][3]);
            float4 v1 = make_float4(acc[i][4], acc[i][5], acc[i][6], acc[i][7]);
            *(float4*)(C + (size_t)r * N + bcol + tx * 8)     = v0;
            *(float4*)(C + (size_t)r * N + bcol + tx * 8 + 4) = v1;
        } else {
            #pragma unroll
            for (int j = 0; j < 8; j++) {
                int c = bcol + tx * 8 + j;
                C[(size_t)(c >> 7) * S_LEN * HD + (size_t)r * HD + (c & 127)] = acc[i][j];
            }
        }
    }
}

// ---------------------------------------------------------------------------
// RMSNorm (over HD=128) + RoPE, per (token, head). Block = 128 threads.
// kmode==0: write back row-major [S, NH*HD] (Q, in-place)
// kmode==1: write [NH, S, HD] (next_k layout in d_out)
// ---------------------------------------------------------------------------
__global__ __launch_bounds__(128) void norm_rope_kernel(
    const float* __restrict__ in, const float* __restrict__ scale,
    const float* __restrict__ cosp, const float* __restrict__ sinp,
    float* __restrict__ outp, int NH, int kmode)
{
    const int s = blockIdx.x, h = blockIdx.y, d = threadIdx.x;
    const size_t base = ((size_t)s * NH + h) * HD;
    float x = in[base + d];
    float v = x * x;
    #pragma unroll
    for (int off = 16; off; off >>= 1) v += __shfl_xor_sync(0xffffffffu, v, off);
    __shared__ float ws[4];
    __shared__ float ysm[HD];
    if ((d & 31) == 0) ws[d >> 5] = v;
    __syncthreads();
    float var = (ws[0] + ws[1] + ws[2] + ws[3]) * (1.0f / HD);
    float y = x * rsqrtf(var + 1e-6f) * scale[d];
    ysm[d] = y;
    __syncthreads();
    float rot = (d < 64) ? -ysm[d + 64] : ysm[d - 64];
    float r = fmaf(y, cosp[s * HD + d], rot * sinp[s * HD + d]);
    if (kmode == 0) outp[base + d] = r;
    else            outp[((size_t)h * S_LEN + s) * HD + d] = r;
}

// ---------------------------------------------------------------------------
// Flash-style fp32 causal attention. One block per (64-query tile, head).
// 256 threads: thread = (row i in 0..63, quarter q4 in 0..3).
// S-phase: thread computes scores for j = q4 + 4*jj (16 cols, bank-friendly).
// O-phase: thread owns float4 dim-chunks (q4 + 4*c)*4, c in 0..7.
// ---------------------------------------------------------------------------
#define QS_STRIDE 132
#define PS_STRIDE 68
#define ATTN_SMEM ((64*QS_STRIDE*3 + 64*PS_STRIDE)*4)

__global__ __launch_bounds__(256) void attn_kernel(
    const float* __restrict__ Q,   // [S, DOUT] normed+roped
    const float* __restrict__ Kc,  // [G, S, HD] normed+roped (d_out region)
    const float* __restrict__ Vc,  // [G, S, HD] raw V (d_out region)
    float* __restrict__ ctx)       // [S, DOUT]
{
    extern __shared__ float sm[];
    float* Qs = sm;
    float* Ks = Qs + 64 * QS_STRIDE;
    float* Vs = Ks + 64 * QS_STRIDE;
    float* Ps = Vs + 64 * QS_STRIDE;

    const int h  = blockIdx.y;
    const int g  = h >> 2;              // GS = 4
    const int qt = blockIdx.x;
    const int tid = threadIdx.x;
    const int i  = tid >> 2;
    const int q4 = tid & 3;
    const float scale = 0.088388347648318447f;  // 1/sqrt(128)

    // Load + pre-scale Q tile (64 x 128)
    for (int f = tid; f < 64 * 32; f += 256) {
        int r = f >> 5;
        int c = (f & 31) << 2;
        float4 v = *(const float4*)(Q + (size_t)(qt * 64 + r) * DOUT + h * HD + c);
        float* dst = &Qs[r * QS_STRIDE + c];
        dst[0] = v.x * scale; dst[1] = v.y * scale;
        dst[2] = v.z * scale; dst[3] = v.w * scale;
    }

    float4 o4[8];
    #pragma unroll
    for (int c = 0; c < 8; c++) o4[c] = make_float4(0.f, 0.f, 0.f, 0.f);
    float m = -1e30f, l = 0.f;
    const int qi = qt * 64 + i;

    for (int t = 0; t <= qt; t++) {
        __syncthreads();   // previous tile's smem reads done (also covers Q load)
        for (int f = tid; f < 64 * 32; f += 256) {
            int r = f >> 5;
            int c = (f & 31) << 2;
            size_t src = ((size_t)g * S_LEN + t * 64 + r) * HD + c;
            *(float4*)(&Ks[r * QS_STRIDE + c]) = *(const float4*)(Kc + src);
            *(float4*)(&Vs[r * QS_STRIDE + c]) = *(const float4*)(Vc + src);
        }
        __syncthreads();

        // ---- scores: 16 columns per thread ----
        float sj[16];
        #pragma unroll
        for (int jj = 0; jj < 16; jj++) sj[jj] = 0.f;
        #pragma unroll 4
        for (int dq = 0; dq < 32; dq++) {
            float4 qv = *(float4*)(&Qs[i * QS_STRIDE + dq * 4]);
            #pragma unroll
            for (int jj = 0; jj < 16; jj++) {
                float4 kv = *(float4*)(&Ks[(q4 + 4 * jj) * QS_STRIDE + dq * 4]);
                sj[jj] = fmaf(qv.x, kv.x, sj[jj]);
                sj[jj] = fmaf(qv.y, kv.y, sj[jj]);
                sj[jj] = fmaf(qv.z, kv.z, sj[jj]);
                sj[jj] = fmaf(qv.w, kv.w, sj[jj]);
            }
        }

        // ---- causal mask + online softmax (row stats over 4 lanes) ----
        float tmax = -1e30f;
        #pragma unroll
        for (int jj = 0; jj < 16; jj++) {
            int kj = t * 64 + q4 + 4 * jj;
            if (kj > qi) sj[jj] = -1e30f;
            tmax = fmaxf(tmax, sj[jj]);
        }
        tmax = fmaxf(tmax, __shfl_xor_sync(0xffffffffu, tmax, 1));
        tmax = fmaxf(tmax, __shfl_xor_sync(0xffffffffu, tmax, 2));
        float new_m = fmaxf(m, tmax);
        float alpha = __expf(m - new_m);
        m = new_m;
        float lp = 0.f;
        #pragma unroll
        for (int jj = 0; jj < 16; jj++) {
            float p = __expf(sj[jj] - new_m);
            lp += p;
            Ps[i * PS_STRIDE + q4 + 4 * jj] = p;
        }
        lp += __shfl_xor_sync(0xffffffffu, lp, 1);
        lp += __shfl_xor_sync(0xffffffffu, lp, 2);
        l = l * alpha + lp;
        #pragma unroll
        for (int c = 0; c < 8; c++) {
            o4[c].x *= alpha; o4[c].y *= alpha;
            o4[c].z *= alpha; o4[c].w *= alpha;
        }
        __syncwarp();   // P tile (row-local, same warp) visible

        // ---- O accumulate: o += P @ V ----
        for (int j = 0; j < 64; j++) {
            float p = Ps[i * PS_STRIDE + j];
            #pragma unroll
            for (int c = 0; c < 8; c++) {
                float4 vv = *(float4*)(&Vs[j * QS_STRIDE + (q4 + 4 * c) * 4]);
                o4[c].x = fmaf(p, vv.x, o4[c].x);
                o4[c].y = fmaf(p, vv.y, o4[c].y);
                o4[c].z = fmaf(p, vv.z, o4[c].z);
                o4[c].w = fmaf(p, vv.w, o4[c].w);
            }
        }
        __syncwarp();   // Ps reads done before next tile overwrites
    }

    float inv_l = 1.f / l;
    float* cbase = ctx + (size_t)qi * DOUT + h * HD;
    #pragma unroll
    for (int c = 0; c < 8; c++) {
        float4 v = o4[c];
        v.x *= inv_l; v.y *= inv_l; v.z *= inv_l; v.w *= inv_l;
        *(float4*)(cbase + (q4 + 4 * c) * 4) = v;
    }
}

// ---------------------------------------------------------------------------
// Inputs (metadata order): x, mask(ignored), cos, sin, Wq, Wk, Wv, Wo,
//                          q_scale, k_scale
// Output: [ out (2048*2048) | next_k (8*2048*128) | next_v (8*2048*128) ] fp32
// ---------------------------------------------------------------------------
extern "C" void kernel_launch(void* const* d_in, const int* in_sizes, int n_in,
                              void* d_out, int out_size)
{
    const float* x    = (const float*)d_in[0];
    const float* cosp = (const float*)d_in[2];
    const float* sinp = (const float*)d_in[3];
    const float* Wq   = (const float*)d_in[4];
    const float* Wk   = (const float*)d_in[5];
    const float* Wv   = (const float*)d_in[6];
    const float* Wo   = (const float*)d_in[7];
    const float* qsc  = (const float*)d_in[8];
    const float* ksc  = (const float*)d_in[9];

    float* out  = (float*)d_out;
    float* kout = out  + (size_t)S_LEN * DIN;        // next_k [G,S,HD]
    float* vout = kout + (size_t)G_KV * S_LEN * HD;  // next_v [G,S,HD]

    float *gq, *gk, *gctx;
    cudaGetSymbolAddress((void**)&gq,   g_q);
    cudaGetSymbolAddress((void**)&gk,   g_k);
    cudaGetSymbolAddress((void**)&gctx, g_ctx);

    dim3 blk(256);

    // Projections
    sgemm_kernel<<<dim3(DOUT/128, S_LEN/128), blk>>>(x, Wq, gq,   S_LEN, DOUT, DIN, 0);
    sgemm_kernel<<<dim3(GKD /128, S_LEN/128), blk>>>(x, Wk, gk,   S_LEN, GKD,  DIN, 0);
    sgemm_kernel<<<dim3(GKD /128, S_LEN/128), blk>>>(x, Wv, vout, S_LEN, GKD,  DIN, 1);

    // RMSNorm + RoPE
    norm_rope_kernel<<<dim3(S_LEN, H_Q),  128>>>(gq, qsc, cosp, sinp, gq,   H_Q,  0);
    norm_rope_kernel<<<dim3(S_LEN, G_KV), 128>>>(gk, ksc, cosp, sinp, kout, G_KV, 1);

    // Attention
    cudaFuncSetAttribute(attn_kernel, cudaFuncAttributeMaxDynamicSharedMemorySize, ATTN_SMEM);
    attn_kernel<<<dim3(S_LEN/64, H_Q), blk, ATTN_SMEM>>>(gq, kout, vout, gctx);

    // Output projection
    sgemm_kernel<<<dim3(DIN/128, S_LEN/128), blk>>>(gctx, Wo, out, S_LEN, DIN, DOUT, 0);
}

// round 3
// speedup vs baseline: 1.3776x; 1.3776x over previous
#include <cuda_runtime.h>
#include <cuda_bf16.h>
#include <math.h>
#include <stdint.h>

#define S_LEN 2048
#define DIN   2048
#define H_Q   32
#define G_KV  8
#define HD    128
#define DOUT  (H_Q*HD)   /* 4096 */
#define GKD   (G_KV*HD)  /* 1024 */

// ---------------- scratch (__device__ globals; no runtime alloc) ------------
__device__ float g_q  [S_LEN * (size_t)DOUT];
__device__ float g_k  [S_LEN * (size_t)GKD];
__device__ float g_ctx[S_LEN * (size_t)DOUT];

__device__ __nv_bfloat16 g_xhi [S_LEN * (size_t)DIN];
__device__ __nv_bfloat16 g_xlo [S_LEN * (size_t)DIN];
__device__ __nv_bfloat16 g_wqt_hi[(size_t)DOUT * DIN];
__device__ __nv_bfloat16 g_wqt_lo[(size_t)DOUT * DIN];
__device__ __nv_bfloat16 g_wkt_hi[(size_t)GKD  * DIN];
__device__ __nv_bfloat16 g_wkt_lo[(size_t)GKD  * DIN];
__device__ __nv_bfloat16 g_wvt_hi[(size_t)GKD  * DIN];
__device__ __nv_bfloat16 g_wvt_lo[(size_t)GKD  * DIN];
__device__ __nv_bfloat16 g_wot_hi[(size_t)DIN  * DOUT];
__device__ __nv_bfloat16 g_wot_lo[(size_t)DIN  * DOUT];
__device__ __nv_bfloat16 g_chi [S_LEN * (size_t)DOUT];
__device__ __nv_bfloat16 g_clo [S_LEN * (size_t)DOUT];

// ---------------------------- PTX helpers (compute_103-safe) ---------------
__device__ __forceinline__ uint32_t smem_u32(const void* p) {
    uint32_t a;
    asm("{ .reg .u64 t; cvta.to.shared.u64 t, %1; cvt.u32.u64 %0, t; }" : "=r"(a) : "l"(p));
    return a;
}
__device__ __forceinline__ void cp16(uint32_t dst, const void* src) {
    asm volatile("cp.async.cg.shared.global [%0], [%1], 16;\n"
                 :: "r"(dst), "l"(__cvta_generic_to_global(src)));
}
__device__ __forceinline__ void cp_commit() {
    asm volatile("cp.async.commit_group;" ::: "memory");
}
template<int N> __device__ __forceinline__ void cp_wait() {
    asm volatile("cp.async.wait_group %0;" :: "n"(N) : "memory");
}
#define LDSM4(r, addr) \
    asm volatile("ldmatrix.sync.aligned.m8n8.x4.shared.b16 {%0,%1,%2,%3}, [%4];" \
        : "=r"((r)[0]), "=r"((r)[1]), "=r"((r)[2]), "=r"((r)[3]) : "r"(addr))
#define MMA_BF16(d, a, b0, b1) \
    asm volatile("mma.sync.aligned.m16n8k16.row.col.f32.bf16.bf16.f32 " \
        "{%0,%1,%2,%3}, {%4,%5,%6,%7}, {%8,%9}, {%0,%1,%2,%3};" \
        : "+f"((d)[0]), "+f"((d)[1]), "+f"((d)[2]), "+f"((d)[3]) \
        : "r"((a)[0]), "r"((a)[1]), "r"((a)[2]), "r"((a)[3]), "r"(b0), "r"(b1))

// ---------------------------------------------------------------------------
// bf16 hi/lo-split GEMM via mma.sync:
//   C[M,N] = (Ahi+Alo)[M,K] @ (Bhi+Blo)[N,K]^T  (3 product terms, fp32 acc)
// Tile: 128x128x32, 256 threads (8 warps; warp tile 64x32).
// Smem rows padded to 80B (5 x 16B) => ldmatrix 8-row address sets cover all
// 32 banks exactly once (conflict-free).
// vmode==1: scatter C into [G, S, HD] layout.
// ---------------------------------------------------------------------------
#define TILE_B   10240      /* 128 rows * 80 B */
#define STAGE_B  (4*TILE_B) /* Ah, Al, Bh, Bl */
#define GEMM_SMEM (2*STAGE_B)

__global__ __launch_bounds__(256) void gemm_mma_kernel(
    const __nv_bfloat16* __restrict__ Ahi, const __nv_bfloat16* __restrict__ Alo,
    const __nv_bfloat16* __restrict__ Bhi, const __nv_bfloat16* __restrict__ Blo,
    float* __restrict__ C, int N, int K, int vmode)
{
    extern __shared__ __align__(128) char smem[];
    const uint32_t sb = smem_u32(smem);
    const int tid  = threadIdx.x;
    const int wid  = tid >> 5;
    const int lane = tid & 31;
    const int warp_m = wid >> 2;       // 0..1  (64 rows each)
    const int warp_n = wid & 3;        // 0..3  (32 cols each)
    const int m0 = blockIdx.y * 128;
    const int n0 = blockIdx.x * 128;

    float acc[4][4][4];
    #pragma unroll
    for (int mi = 0; mi < 4; mi++)
        #pragma unroll
        for (int ni = 0; ni < 4; ni++)
            #pragma unroll
            for (int q = 0; q < 4; q++) acc[mi][ni][q] = 0.f;

    // stage loader: 4 tiles x 512 chunks(16B) = 2048 chunks, 8 per thread
    auto load_stage = [&](int k0, int buf) {
        uint32_t base = sb + buf * STAGE_B;
        #pragma unroll
        for (int i = 0; i < 8; i++) {
            int c = tid + (i << 8);
            int tile = c >> 9, w = c & 511, row = w >> 2, ch = w & 3;
            const __nv_bfloat16* g;
            if (tile < 2) g = (tile ? Alo : Ahi) + (size_t)(m0 + row) * K + k0 + (ch << 3);
            else          g = ((tile & 1) ? Blo : Bhi) + (size_t)(n0 + row) * K + k0 + (ch << 3);
            cp16(base + tile * TILE_B + row * 80 + (ch << 4), g);
        }
        cp_commit();
    };

    auto compute_stage = [&](int buf) {
        uint32_t base = sb + buf * STAGE_B;
        uint32_t sAh = base, sAl = base + TILE_B, sBh = base + 2*TILE_B, sBl = base + 3*TILE_B;
        #pragma unroll
        for (int kk = 0; kk < 2; kk++) {
            const int kb = kk * 2;   // 16B-chunk index of this k16 within the stage
            uint32_t ah[4][4], al[4][4], bh[2][4], bl[2][4];
            #pragma unroll
            for (int mi = 0; mi < 4; mi++) {
                int row = warp_m * 64 + mi * 16 + (lane & 15);
                uint32_t off = row * 80 + (kb + (lane >> 4)) * 16;
                LDSM4(ah[mi], sAh + off);
                LDSM4(al[mi], sAl + off);
            }
            #pragma unroll
            for (int bi = 0; bi < 2; bi++) {
                int row = warp_n * 32 + bi * 16 + (lane & 7) + ((lane >> 4) << 3);
                uint32_t off = row * 80 + (kb + ((lane >> 3) & 1)) * 16;
                LDSM4(bh[bi], sBh + off);
                LDSM4(bl[bi], sBl + off);
            }
            #pragma unroll
            for (int mi = 0; mi < 4; mi++)
                #pragma unroll
                for (int ni = 0; ni < 4; ni++) {
                    uint32_t* Bh = &bh[ni >> 1][(ni & 1) * 2];
                    uint32_t* Bl = &bl[ni >> 1][(ni & 1) * 2];
                    MMA_BF16(acc[mi][ni], ah[mi], Bh[0], Bh[1]);   // hi*hi
                    MMA_BF16(acc[mi][ni], ah[mi], Bl[0], Bl[1]);   // hi*lo
                    MMA_BF16(acc[mi][ni], al[mi], Bh[0], Bh[1]);   // lo*hi
                }
        }
    };

    const int NS = K >> 5;
    load_stage(0, 0);
    for (int t = 0; t < NS; t++) {
        if (t + 1 < NS) { load_stage((t + 1) << 5, (t + 1) & 1); cp_wait<1>(); }
        else            { cp_wait<0>(); }
        __syncthreads();
        compute_stage(t & 1);
        __syncthreads();
    }

    // epilogue: mma fragment layout (row = lane>>2 [+8], col = (lane&3)*2 [+1])
    #pragma unroll
    for (int mi = 0; mi < 4; mi++) {
        #pragma unroll
        for (int ni = 0; ni < 4; ni++) {
            int r0 = m0 + warp_m * 64 + mi * 16 + (lane >> 2);
            int c0 = n0 + warp_n * 32 + ni * 8 + (lane & 3) * 2;
            if (vmode == 0) {
                *(float2*)(C + (size_t)r0 * N + c0)       = make_float2(acc[mi][ni][0], acc[mi][ni][1]);
                *(float2*)(C + (size_t)(r0 + 8) * N + c0) = make_float2(acc[mi][ni][2], acc[mi][ni][3]);
            } else {
                size_t g = (size_t)(c0 >> 7) * S_LEN * HD;
                int cc = c0 & 127;
                *(float2*)(C + g + (size_t)r0 * HD + cc)       = make_float2(acc[mi][ni][0], acc[mi][ni][1]);
                *(float2*)(C + g + (size_t)(r0 + 8) * HD + cc) = make_float2(acc[mi][ni][2], acc[mi][ni][3]);
            }
        }
    }
}

// ------------------------- conversion kernels ------------------------------
__global__ __launch_bounds__(256) void split_kernel(
    const float4* __restrict__ in, ushort4* __restrict__ hi,
    ushort4* __restrict__ lo, int n4)
{
    int i = blockIdx.x * 256 + threadIdx.x;
    if (i >= n4) return;
    float4 v = in[i];
    float f[4] = {v.x, v.y, v.z, v.w};
    unsigned short h[4], l[4];
    #pragma unroll
    for (int j = 0; j < 4; j++) {
        __nv_bfloat16 hb = __float2bfloat16(f[j]);
        __nv_bfloat16 lb = __float2bfloat16(f[j] - __bfloat162float(hb));
        h[j] = __bfloat16_as_ushort(hb);
        l[j] = __bfloat16_as_ushort(lb);
    }
    hi[i] = make_ushort4(h[0], h[1], h[2], h[3]);
    lo[i] = make_ushort4(l[0], l[1], l[2], l[3]);
}

__global__ __launch_bounds__(256) void transpose_split_kernel(
    const float* __restrict__ W, __nv_bfloat16* __restrict__ Thi,
    __nv_bfloat16* __restrict__ Tlo, int K, int N)
{
    __shared__ float t[32][33];
    const int bn = blockIdx.x * 32, bk = blockIdx.y * 32;
    const int tx = threadIdx.x, ty = threadIdx.y;
    #pragma unroll
    for (int j = 0; j < 32; j += 8)
        t[ty + j][tx] = W[(size_t)(bk + ty + j) * N + bn + tx];
    __syncthreads();
    #pragma unroll
    for (int j = 0; j < 32; j += 8) {
        float v = t[tx][ty + j];
        __nv_bfloat16 h = __float2bfloat16(v);
        __nv_bfloat16 l = __float2bfloat16(v - __bfloat162float(h));
        size_t o = (size_t)(bn + ty + j) * K + bk + tx;
        Thi[o] = h; Tlo[o] = l;
    }
}

// ------------------------- RMSNorm + RoPE ----------------------------------
__global__ __launch_bounds__(128) void norm_rope_kernel(
    const float* __restrict__ in, const float* __restrict__ scale,
    const float* __restrict__ cosp, const float* __restrict__ sinp,
    float* __restrict__ outp, int NH, int kmode)
{
    const int s = blockIdx.x, h = blockIdx.y, d = threadIdx.x;
    const size_t base = ((size_t)s * NH + h) * HD;
    float x = in[base + d];
    float v = x * x;
    #pragma unroll
    for (int off = 16; off; off >>= 1) v += __shfl_xor_sync(0xffffffffu, v, off);
    __shared__ float ws[4];
    __shared__ float ysm[HD];
    if ((d & 31) == 0) ws[d >> 5] = v;
    __syncthreads();
    float var = (ws[0] + ws[1] + ws[2] + ws[3]) * (1.0f / HD);
    float y = x * rsqrtf(var + 1e-6f) * scale[d];
    ysm[d] = y;
    __syncthreads();
    float rot = (d < 64) ? -ysm[d + 64] : ysm[d - 64];
    float r = fmaf(y, cosp[s * HD + d], rot * sinp[s * HD + d]);
    if (kmode == 0) outp[base + d] = r;
    else            outp[((size_t)h * S_LEN + s) * HD + d] = r;
}

// ------------------------- attention (fp32 SIMT) ---------------------------
#define QS_STRIDE 132
#define PS_STRIDE 68
#define ATTN_SMEM ((64*QS_STRIDE*3 + 64*PS_STRIDE)*4)

__global__ __launch_bounds__(256) void attn_kernel(
    const float* __restrict__ Q, const float* __restrict__ Kc,
    const float* __restrict__ Vc, float* __restrict__ ctx)
{
    extern __shared__ float sm[];
    float* Qs = sm;
    float* Ks = Qs + 64 * QS_STRIDE;
    float* Vs = Ks + 64 * QS_STRIDE;
    float* Ps = Vs + 64 * QS_STRIDE;

    const int h  = blockIdx.y;
    const int g  = h >> 2;
    const int qt = blockIdx.x;
    const int tid = threadIdx.x;
    const int i  = tid >> 2;
    const int q4 = tid & 3;
    const float scale = 0.088388347648318447f;

    for (int f = tid; f < 64 * 32; f += 256) {
        int r = f >> 5;
        int c = (f & 31) << 2;
        float4 v = *(const float4*)(Q + (size_t)(qt * 64 + r) * DOUT + h * HD + c);
        float* dst = &Qs[r * QS_STRIDE + c];
        dst[0] = v.x * scale; dst[1] = v.y * scale;
        dst[2] = v.z * scale; dst[3] = v.w * scale;
    }

    float4 o4[8];
    #pragma unroll
    for (int c = 0; c < 8; c++) o4[c] = make_float4(0.f, 0.f, 0.f, 0.f);
    float m = -1e30f, l = 0.f;
    const int qi = qt * 64 + i;

    for (int t = 0; t <= qt; t++) {
        __syncthreads();
        for (int f = tid; f < 64 * 32; f += 256) {
            int r = f >> 5;
            int c = (f & 31) << 2;
            size_t src = ((size_t)g * S_LEN + t * 64 + r) * HD + c;
            *(float4*)(&Ks[r * QS_STRIDE + c]) = *(const float4*)(Kc + src);
            *(float4*)(&Vs[r * QS_STRIDE + c]) = *(const float4*)(Vc + src);
        }
        __syncthreads();

        float sj[16];
        #pragma unroll
        for (int jj = 0; jj < 16; jj++) sj[jj] = 0.f;
        #pragma unroll 4
        for (int dq = 0; dq < 32; dq++) {
            float4 qv = *(float4*)(&Qs[i * QS_STRIDE + dq * 4]);
            #pragma unroll
            for (int jj = 0; jj < 16; jj++) {
                float4 kv = *(float4*)(&Ks[(q4 + 4 * jj) * QS_STRIDE + dq * 4]);
                sj[jj] = fmaf(qv.x, kv.x, sj[jj]);
                sj[jj] = fmaf(qv.y, kv.y, sj[jj]);
                sj[jj] = fmaf(qv.z, kv.z, sj[jj]);
                sj[jj] = fmaf(qv.w, kv.w, sj[jj]);
            }
        }

        float tmax = -1e30f;
        #pragma unroll
        for (int jj = 0; jj < 16; jj++) {
            int kj = t * 64 + q4 + 4 * jj;
            if (kj > qi) sj[jj] = -1e30f;
            tmax = fmaxf(tmax, sj[jj]);
        }
        tmax = fmaxf(tmax, __shfl_xor_sync(0xffffffffu, tmax, 1));
        tmax = fmaxf(tmax, __shfl_xor_sync(0xffffffffu, tmax, 2));
        float new_m = fmaxf(m, tmax);
        float alpha = __expf(m - new_m);
        m = new_m;
        float lp = 0.f;
        #pragma unroll
        for (int jj = 0; jj < 16; jj++) {
            float p = __expf(sj[jj] - new_m);
            lp += p;
            Ps[i * PS_STRIDE + q4 + 4 * jj] = p;
        }
        lp += __shfl_xor_sync(0xffffffffu, lp, 1);
        lp += __shfl_xor_sync(0xffffffffu, lp, 2);
        l = l * alpha + lp;
        #pragma unroll
        for (int c = 0; c < 8; c++) {
            o4[c].x *= alpha; o4[c].y *= alpha;
            o4[c].z *= alpha; o4[c].w *= alpha;
        }
        __syncwarp();

        for (int j = 0; j < 64; j++) {
            float p = Ps[i * PS_STRIDE + j];
            #pragma unroll
            for (int c = 0; c < 8; c++) {
                float4 vv = *(float4*)(&Vs[j * QS_STRIDE + (q4 + 4 * c) * 4]);
                o4[c].x = fmaf(p, vv.x, o4[c].x);
                o4[c].y = fmaf(p, vv.y, o4[c].y);
                o4[c].z = fmaf(p, vv.z, o4[c].z);
                o4[c].w = fmaf(p, vv.w, o4[c].w);
            }
        }
        __syncwarp();
    }

    float inv_l = 1.f / l;
    float* cbase = ctx + (size_t)qi * DOUT + h * HD;
    #pragma unroll
    for (int c = 0; c < 8; c++) {
        float4 v = o4[c];
        v.x *= inv_l; v.y *= inv_l; v.z *= inv_l; v.w *= inv_l;
        *(float4*)(cbase + (q4 + 4 * c) * 4) = v;
    }
}

// ---------------------------------------------------------------------------
extern "C" void kernel_launch(void* const* d_in, const int* in_sizes, int n_in,
                              void* d_out, int out_size)
{
    const float* x    = (const float*)d_in[0];
    const float* cosp = (const float*)d_in[2];
    const float* sinp = (const float*)d_in[3];
    const float* Wq   = (const float*)d_in[4];
    const float* Wk   = (const float*)d_in[5];
    const float* Wv   = (const float*)d_in[6];
    const float* Wo   = (const float*)d_in[7];
    const float* qsc  = (const float*)d_in[8];
    const float* ksc  = (const float*)d_in[9];

    float* out  = (float*)d_out;
    float* kout = out  + (size_t)S_LEN * DIN;
    float* vout = kout + (size_t)G_KV * S_LEN * HD;

    float *gq, *gk, *gctx;
    __nv_bfloat16 *xhi, *xlo, *wqh, *wql, *wkh, *wkl, *wvh, *wvl, *woh, *wol, *chi, *clo;
    cudaGetSymbolAddress((void**)&gq,   g_q);
    cudaGetSymbolAddress((void**)&gk,   g_k);
    cudaGetSymbolAddress((void**)&gctx, g_ctx);
    cudaGetSymbolAddress((void**)&xhi,  g_xhi);
    cudaGetSymbolAddress((void**)&xlo,  g_xlo);
    cudaGetSymbolAddress((void**)&wqh,  g_wqt_hi);
    cudaGetSymbolAddress((void**)&wql,  g_wqt_lo);
    cudaGetSymbolAddress((void**)&wkh,  g_wkt_hi);
    cudaGetSymbolAddress((void**)&wkl,  g_wkt_lo);
    cudaGetSymbolAddress((void**)&wvh,  g_wvt_hi);
    cudaGetSymbolAddress((void**)&wvl,  g_wvt_lo);
    cudaGetSymbolAddress((void**)&woh,  g_wot_hi);
    cudaGetSymbolAddress((void**)&wol,  g_wot_lo);
    cudaGetSymbolAddress((void**)&chi,  g_chi);
    cudaGetSymbolAddress((void**)&clo,  g_clo);

    cudaFuncSetAttribute(gemm_mma_kernel, cudaFuncAttributeMaxDynamicSharedMemorySize, GEMM_SMEM);
    cudaFuncSetAttribute(attn_kernel,     cudaFuncAttributeMaxDynamicSharedMemorySize, ATTN_SMEM);

    dim3 tb(32, 8);

    {
        int n4 = S_LEN * DIN / 4;
        split_kernel<<<(n4 + 255) / 256, 256>>>((const float4*)x, (ushort4*)xhi, (ushort4*)xlo, n4);
    }
    transpose_split_kernel<<<dim3(DOUT/32, DIN/32),  tb>>>(Wq, wqh, wql, DIN,  DOUT);
    transpose_split_kernel<<<dim3(GKD /32, DIN/32),  tb>>>(Wk, wkh, wkl, DIN,  GKD);
    transpose_split_kernel<<<dim3(GKD /32, DIN/32),  tb>>>(Wv, wvh, wvl, DIN,  GKD);
    transpose_split_kernel<<<dim3(DIN /32, DOUT/32), tb>>>(Wo, woh, wol, DOUT, DIN);

    // projections via mma.sync bf16-split
    gemm_mma_kernel<<<dim3(DOUT/128, S_LEN/128), 256, GEMM_SMEM>>>(xhi, xlo, wqh, wql, gq,   DOUT, DIN, 0);
    gemm_mma_kernel<<<dim3(GKD /128, S_LEN/128), 256, GEMM_SMEM>>>(xhi, xlo, wkh, wkl, gk,   GKD,  DIN, 0);
    gemm_mma_kernel<<<dim3(GKD /128, S_LEN/128), 256, GEMM_SMEM>>>(xhi, xlo, wvh, wvl, vout, GKD,  DIN, 1);

    norm_rope_kernel<<<dim3(S_LEN, H_Q),  128>>>(gq, qsc, cosp, sinp, gq,   H_Q,  0);
    norm_rope_kernel<<<dim3(S_LEN, G_KV), 128>>>(gk, ksc, cosp, sinp, kout, G_KV, 1);

    attn_kernel<<<dim3(S_LEN/64, H_Q), 256, ATTN_SMEM>>>(gq, kout, vout, gctx);

    {
        int n4 = S_LEN * DOUT / 4;
        split_kernel<<<(n4 + 255) / 256, 256>>>((const float4*)gctx, (ushort4*)chi, (ushort4*)clo, n4);
    }
    gemm_mma_kernel<<<dim3(DIN/128, S_LEN/128), 256, GEMM_SMEM>>>(chi, clo, woh, wol, out, DIN, DOUT, 0);
}

// round 4
// speedup vs baseline: 3.4772x; 2.5240x over previous
#include <cuda_runtime.h>
#include <cuda_bf16.h>
#include <math.h>
#include <stdint.h>

#define S_LEN 2048
#define DIN   2048
#define H_Q   32
#define G_KV  8
#define HD    128
#define DOUT  (H_Q*HD)   /* 4096 */
#define GKD   (G_KV*HD)  /* 1024 */

// ---------------- scratch (__device__ globals; no runtime alloc) ------------
__device__ float g_q  [S_LEN * (size_t)DOUT];
__device__ float g_k  [S_LEN * (size_t)GKD];

__device__ __nv_bfloat16 g_xhi [S_LEN * (size_t)DIN];
__device__ __nv_bfloat16 g_xlo [S_LEN * (size_t)DIN];
__device__ __nv_bfloat16 g_wqt_hi[(size_t)DOUT * DIN];
__device__ __nv_bfloat16 g_wqt_lo[(size_t)DOUT * DIN];
__device__ __nv_bfloat16 g_wkt_hi[(size_t)GKD  * DIN];
__device__ __nv_bfloat16 g_wkt_lo[(size_t)GKD  * DIN];
__device__ __nv_bfloat16 g_wvt_hi[(size_t)GKD  * DIN];
__device__ __nv_bfloat16 g_wvt_lo[(size_t)GKD  * DIN];
__device__ __nv_bfloat16 g_wot_hi[(size_t)DIN  * DOUT];
__device__ __nv_bfloat16 g_wot_lo[(size_t)DIN  * DOUT];
__device__ __nv_bfloat16 g_chi [S_LEN * (size_t)DOUT];
__device__ __nv_bfloat16 g_clo [S_LEN * (size_t)DOUT];

// attention operands (bf16 hi/lo)
__device__ __nv_bfloat16 g_qh[(size_t)H_Q * S_LEN * HD];
__device__ __nv_bfloat16 g_ql[(size_t)H_Q * S_LEN * HD];
__device__ __nv_bfloat16 g_kh[(size_t)G_KV * S_LEN * HD];
__device__ __nv_bfloat16 g_kl[(size_t)G_KV * S_LEN * HD];
__device__ __nv_bfloat16 g_vh[(size_t)G_KV * S_LEN * HD];
__device__ __nv_bfloat16 g_vl[(size_t)G_KV * S_LEN * HD];

// ---------------------------- PTX helpers (compute_103-safe) ---------------
__device__ __forceinline__ uint32_t smem_u32(const void* p) {
    uint32_t a;
    asm("{ .reg .u64 t; cvta.to.shared.u64 t, %1; cvt.u32.u64 %0, t; }" : "=r"(a) : "l"(p));
    return a;
}
__device__ __forceinline__ void cp16(uint32_t dst, const void* src) {
    asm volatile("cp.async.cg.shared.global [%0], [%1], 16;\n"
                 :: "r"(dst), "l"(__cvta_generic_to_global(src)));
}
__device__ __forceinline__ void cp_commit() {
    asm volatile("cp.async.commit_group;" ::: "memory");
}
template<int N> __device__ __forceinline__ void cp_wait() {
    asm volatile("cp.async.wait_group %0;" :: "n"(N) : "memory");
}
#define LDSM4(r, addr) \
    asm volatile("ldmatrix.sync.aligned.m8n8.x4.shared.b16 {%0,%1,%2,%3}, [%4];" \
        : "=r"((r)[0]), "=r"((r)[1]), "=r"((r)[2]), "=r"((r)[3]) : "r"(addr))
#define LDSM4T(r, addr) \
    asm volatile("ldmatrix.sync.aligned.m8n8.x4.trans.shared.b16 {%0,%1,%2,%3}, [%4];" \
        : "=r"((r)[0]), "=r"((r)[1]), "=r"((r)[2]), "=r"((r)[3]) : "r"(addr))
#define MMA_BF16(d, a, b0, b1) \
    asm volatile("mma.sync.aligned.m16n8k16.row.col.f32.bf16.bf16.f32 " \
        "{%0,%1,%2,%3}, {%4,%5,%6,%7}, {%8,%9}, {%0,%1,%2,%3};" \
        : "+f"((d)[0]), "+f"((d)[1]), "+f"((d)[2]), "+f"((d)[3]) \
        : "r"((a)[0]), "r"((a)[1]), "r"((a)[2]), "r"((a)[3]), "r"(b0), "r"(b1))

__device__ __forceinline__ uint32_t pack_bf16x2(float lo, float hi) {
    uint32_t r;
    asm("cvt.rn.bf16x2.f32 %0, %1, %2;" : "=r"(r) : "f"(hi), "f"(lo));
    return r;
}

// ---------------------------------------------------------------------------
// bf16 hi/lo-split GEMM via mma.sync (unchanged from R3; known-good)
// ---------------------------------------------------------------------------
#define TILE_B   10240
#define STAGE_B  (4*TILE_B)
#define GEMM_SMEM (2*STAGE_B)

__global__ __launch_bounds__(256) void gemm_mma_kernel(
    const __nv_bfloat16* __restrict__ Ahi, const __nv_bfloat16* __restrict__ Alo,
    const __nv_bfloat16* __restrict__ Bhi, const __nv_bfloat16* __restrict__ Blo,
    float* __restrict__ C, int N, int K, int vmode)
{
    extern __shared__ __align__(128) char smem[];
    const uint32_t sb = smem_u32(smem);
    const int tid  = threadIdx.x;
    const int wid  = tid >> 5;
    const int lane = tid & 31;
    const int warp_m = wid >> 2;
    const int warp_n = wid & 3;
    const int m0 = blockIdx.y * 128;
    const int n0 = blockIdx.x * 128;

    float acc[4][4][4];
    #pragma unroll
    for (int mi = 0; mi < 4; mi++)
        #pragma unroll
        for (int ni = 0; ni < 4; ni++)
            #pragma unroll
            for (int q = 0; q < 4; q++) acc[mi][ni][q] = 0.f;

    auto load_stage = [&](int k0, int buf) {
        uint32_t base = sb + buf * STAGE_B;
        #pragma unroll
        for (int i = 0; i < 8; i++) {
            int c = tid + (i << 8);
            int tile = c >> 9, w = c & 511, row = w >> 2, ch = w & 3;
            const __nv_bfloat16* g;
            if (tile < 2) g = (tile ? Alo : Ahi) + (size_t)(m0 + row) * K + k0 + (ch << 3);
            else          g = ((tile & 1) ? Blo : Bhi) + (size_t)(n0 + row) * K + k0 + (ch << 3);
            cp16(base + tile * TILE_B + row * 80 + (ch << 4), g);
        }
        cp_commit();
    };

    auto compute_stage = [&](int buf) {
        uint32_t base = sb + buf * STAGE_B;
        uint32_t sAh = base, sAl = base + TILE_B, sBh = base + 2*TILE_B, sBl = base + 3*TILE_B;
        #pragma unroll
        for (int kk = 0; kk < 2; kk++) {
            const int kb = kk * 2;
            uint32_t ah[4][4], al[4][4], bh[2][4], bl[2][4];
            #pragma unroll
            for (int mi = 0; mi < 4; mi++) {
                int row = warp_m * 64 + mi * 16 + (lane & 15);
                uint32_t off = row * 80 + (kb + (lane >> 4)) * 16;
                LDSM4(ah[mi], sAh + off);
                LDSM4(al[mi], sAl + off);
            }
            #pragma unroll
            for (int bi = 0; bi < 2; bi++) {
                int row = warp_n * 32 + bi * 16 + (lane & 7) + ((lane >> 4) << 3);
                uint32_t off = row * 80 + (kb + ((lane >> 3) & 1)) * 16;
                LDSM4(bh[bi], sBh + off);
                LDSM4(bl[bi], sBl + off);
            }
            #pragma unroll
            for (int mi = 0; mi < 4; mi++)
                #pragma unroll
                for (int ni = 0; ni < 4; ni++) {
                    uint32_t* Bh = &bh[ni >> 1][(ni & 1) * 2];
                    uint32_t* Bl = &bl[ni >> 1][(ni & 1) * 2];
                    MMA_BF16(acc[mi][ni], ah[mi], Bh[0], Bh[1]);
                    MMA_BF16(acc[mi][ni], ah[mi], Bl[0], Bl[1]);
                    MMA_BF16(acc[mi][ni], al[mi], Bh[0], Bh[1]);
                }
        }
    };

    const int NS = K >> 5;
    load_stage(0, 0);
    for (int t = 0; t < NS; t++) {
        if (t + 1 < NS) { load_stage((t + 1) << 5, (t + 1) & 1); cp_wait<1>(); }
        else            { cp_wait<0>(); }
        __syncthreads();
        compute_stage(t & 1);
        __syncthreads();
    }

    #pragma unroll
    for (int mi = 0; mi < 4; mi++) {
        #pragma unroll
        for (int ni = 0; ni < 4; ni++) {
            int r0 = m0 + warp_m * 64 + mi * 16 + (lane >> 2);
            int c0 = n0 + warp_n * 32 + ni * 8 + (lane & 3) * 2;
            if (vmode == 0) {
                *(float2*)(C + (size_t)r0 * N + c0)       = make_float2(acc[mi][ni][0], acc[mi][ni][1]);
                *(float2*)(C + (size_t)(r0 + 8) * N + c0) = make_float2(acc[mi][ni][2], acc[mi][ni][3]);
            } else {
                size_t g = (size_t)(c0 >> 7) * S_LEN * HD;
                int cc = c0 & 127;
                *(float2*)(C + g + (size_t)r0 * HD + cc)       = make_float2(acc[mi][ni][0], acc[mi][ni][1]);
                *(float2*)(C + g + (size_t)(r0 + 8) * HD + cc) = make_float2(acc[mi][ni][2], acc[mi][ni][3]);
            }
        }
    }
}

// ------------------------- conversion kernels ------------------------------
__global__ __launch_bounds__(256) void split_kernel(
    const float4* __restrict__ in, ushort4* __restrict__ hi,
    ushort4* __restrict__ lo, int n4)
{
    int i = blockIdx.x * 256 + threadIdx.x;
    if (i >= n4) return;
    float4 v = in[i];
    float f[4] = {v.x, v.y, v.z, v.w};
    unsigned short h[4], l[4];
    #pragma unroll
    for (int j = 0; j < 4; j++) {
        __nv_bfloat16 hb = __float2bfloat16(f[j]);
        __nv_bfloat16 lb = __float2bfloat16(f[j] - __bfloat162float(hb));
        h[j] = __bfloat16_as_ushort(hb);
        l[j] = __bfloat16_as_ushort(lb);
    }
    hi[i] = make_ushort4(h[0], h[1], h[2], h[3]);
    lo[i] = make_ushort4(l[0], l[1], l[2], l[3]);
}

__global__ __launch_bounds__(256) void transpose_split_kernel(
    const float* __restrict__ W, __nv_bfloat16* __restrict__ Thi,
    __nv_bfloat16* __restrict__ Tlo, int K, int N)
{
    __shared__ float t[32][33];
    const int bn = blockIdx.x * 32, bk = blockIdx.y * 32;
    const int tx = threadIdx.x, ty = threadIdx.y;
    #pragma unroll
    for (int j = 0; j < 32; j += 8)
        t[ty + j][tx] = W[(size_t)(bk + ty + j) * N + bn + tx];
    __syncthreads();
    #pragma unroll
    for (int j = 0; j < 32; j += 8) {
        float v = t[tx][ty + j];
        __nv_bfloat16 h = __float2bfloat16(v);
        __nv_bfloat16 l = __float2bfloat16(v - __bfloat162float(h));
        size_t o = (size_t)(bn + ty + j) * K + bk + tx;
        Thi[o] = h; Tlo[o] = l;
    }
}

// ------------------------- RMSNorm + RoPE variants -------------------------
// Q: in [S,H,HD] fp32 -> bf16 hi/lo in [H,S,HD], pre-scaled by 1/sqrt(HD)
__global__ __launch_bounds__(128) void norm_rope_q_kernel(
    const float* __restrict__ in, const float* __restrict__ scale,
    const float* __restrict__ cosp, const float* __restrict__ sinp,
    __nv_bfloat16* __restrict__ qh, __nv_bfloat16* __restrict__ ql)
{
    const int s = blockIdx.x, h = blockIdx.y, d = threadIdx.x;
    const size_t base = ((size_t)s * H_Q + h) * HD;
    float x = in[base + d];
    float v = x * x;
    #pragma unroll
    for (int off = 16; off; off >>= 1) v += __shfl_xor_sync(0xffffffffu, v, off);
    __shared__ float ws[4];
    __shared__ float ysm[HD];
    if ((d & 31) == 0) ws[d >> 5] = v;
    __syncthreads();
    float var = (ws[0] + ws[1] + ws[2] + ws[3]) * (1.0f / HD);
    float y = x * rsqrtf(var + 1e-6f) * scale[d];
    ysm[d] = y;
    __syncthreads();
    float rot = (d < 64) ? -ysm[d + 64] : ysm[d - 64];
    float r = fmaf(y, cosp[s * HD + d], rot * sinp[s * HD + d]) * 0.088388347648318447f;
    __nv_bfloat16 hb = __float2bfloat16(r);
    __nv_bfloat16 lb = __float2bfloat16(r - __bfloat162float(hb));
    size_t o = ((size_t)h * S_LEN + s) * HD + d;
    qh[o] = hb; ql[o] = lb;
}

// K: in [S,G,HD] fp32 -> fp32 [G,S,HD] (d_out) + bf16 hi/lo [G,S,HD]
__global__ __launch_bounds__(128) void norm_rope_k_kernel(
    const float* __restrict__ in, const float* __restrict__ scale,
    const float* __restrict__ cosp, const float* __restrict__ sinp,
    float* __restrict__ kout, __nv_bfloat16* __restrict__ kh,
    __nv_bfloat16* __restrict__ kl)
{
    const int s = blockIdx.x, h = blockIdx.y, d = threadIdx.x;
    const size_t base = ((size_t)s * G_KV + h) * HD;
    float x = in[base + d];
    float v = x * x;
    #pragma unroll
    for (int off = 16; off; off >>= 1) v += __shfl_xor_sync(0xffffffffu, v, off);
    __shared__ float ws[4];
    __shared__ float ysm[HD];
    if ((d & 31) == 0) ws[d >> 5] = v;
    __syncthreads();
    float var = (ws[0] + ws[1] + ws[2] + ws[3]) * (1.0f / HD);
    float y = x * rsqrtf(var + 1e-6f) * scale[d];
    ysm[d] = y;
    __syncthreads();
    float rot = (d < 64) ? -ysm[d + 64] : ysm[d - 64];
    float r = fmaf(y, cosp[s * HD + d], rot * sinp[s * HD + d]);
    size_t o = ((size_t)h * S_LEN + s) * HD + d;
    kout[o] = r;
    __nv_bfloat16 hb = __float2bfloat16(r);
    __nv_bfloat16 lb = __float2bfloat16(r - __bfloat162float(hb));
    kh[o] = hb; kl[o] = lb;
}

// ---------------------------------------------------------------------------
// Tensor-core flash attention, bf16 hi/lo split QK^T and PV, fp32 softmax.
// BM=128 q rows per block, BN=64 keys per tile, 8 warps (warp = 16 q rows).
// smem: Qh,Ql (128x128) + double-buffered {Kh,Kl,Vh,Vl} (64x128 each).
// Row stride 272 B -> conflict-free ldmatrix.
// Emits context directly as bf16 hi/lo splits (chi/clo) for the Wo GEMM.
// ---------------------------------------------------------------------------
#define SQA      272
#define Q_BYTES  (128*SQA)     /* 34816 */
#define KV_TILE  (64*SQA)      /* 17408 */
#define ATT_SMEM (2*Q_BYTES + 2*4*KV_TILE)  /* 208896 */

__global__ __launch_bounds__(256) void attn_mma_kernel(
    const __nv_bfloat16* __restrict__ Qh, const __nv_bfloat16* __restrict__ Ql,
    const __nv_bfloat16* __restrict__ Kh, const __nv_bfloat16* __restrict__ Kl,
    const __nv_bfloat16* __restrict__ Vh, const __nv_bfloat16* __restrict__ Vl,
    __nv_bfloat16* __restrict__ Chi, __nv_bfloat16* __restrict__ Clo)
{
    extern __shared__ __align__(128) char smem[];
    const uint32_t sb = smem_u32(smem);
    const int h  = blockIdx.y;
    const int g  = h >> 2;
    const int qt = gridDim.x - 1 - blockIdx.x;   // big tiles first
    const int tid = threadIdx.x, wid = tid >> 5, lane = tid & 31;
    const int qbase = qt * 128;

    const uint32_t sQh = sb, sQl = sb + Q_BYTES;
    const uint32_t sKV0 = sb + 2 * Q_BYTES;

    // ---- Q tile load (once) ----
    {
        const __nv_bfloat16* bh = Qh + ((size_t)h * S_LEN + qbase) * HD;
        const __nv_bfloat16* bl = Ql + ((size_t)h * S_LEN + qbase) * HD;
        #pragma unroll
        for (int i = 0; i < 8; i++) {
            int c = tid + (i << 8);          // 0..2047
            int r = c >> 4, ch = c & 15;
            cp16(sQh + r * SQA + ch * 16, bh + r * HD + ch * 8);
            cp16(sQl + r * SQA + ch * 16, bl + r * HD + ch * 8);
        }
    }
    auto load_kv = [&](int kt, int buf) {
        uint32_t base = sKV0 + buf * 4 * KV_TILE;
        const size_t gb = ((size_t)g * S_LEN + kt * 64) * HD;
        #pragma unroll
        for (int i = 0; i < 16; i++) {
            int c = tid + (i << 8);          // 0..4095
            int arr = c >> 10, w = c & 1023, r = w >> 4, ch = w & 15;
            const __nv_bfloat16* src =
                (arr == 0 ? Kh : arr == 1 ? Kl : arr == 2 ? Vh : Vl) + gb + r * HD + ch * 8;
            cp16(base + arr * KV_TILE + r * SQA + ch * 16, src);
        }
    };
    load_kv(0, 0);
    cp_commit();

    float o[16][4];
    #pragma unroll
    for (int nj = 0; nj < 16; nj++)
        #pragma unroll
        for (int q = 0; q < 4; q++) o[nj][q] = 0.f;
    float mA = -1e30f, mB = -1e30f, lA = 0.f, lB = 0.f;

    const int rA = lane >> 2;
    const int colq = (lane & 3) * 2;
    const int ktmax = 2 * qt + 1;

    for (int kt = 0; kt <= ktmax; kt++) {
        if (kt < ktmax) { load_kv(kt + 1, (kt + 1) & 1); cp_commit(); cp_wait<1>(); }
        else            { cp_wait<0>(); }
        __syncthreads();

        const uint32_t bKh = sKV0 + (kt & 1) * 4 * KV_TILE;
        const uint32_t bKl = bKh + KV_TILE;
        const uint32_t bVh = bKh + 2 * KV_TILE;
        const uint32_t bVl = bKh + 3 * KV_TILE;

        // ---- QK^T (3-term split) ----
        float acc[8][4];
        #pragma unroll
        for (int ni = 0; ni < 8; ni++)
            #pragma unroll
            for (int q = 0; q < 4; q++) acc[ni][q] = 0.f;

        #pragma unroll
        for (int ks = 0; ks < 8; ks++) {
            uint32_t ah[4], al[4];
            {
                int row = wid * 16 + (lane & 15);
                uint32_t off = row * SQA + (ks * 2 + (lane >> 4)) * 16;
                LDSM4(ah, sQh + off);
                LDSM4(al, sQl + off);
            }
            #pragma unroll
            for (int nb = 0; nb < 4; nb++) {
                uint32_t bh[4], bl[4];
                int row = nb * 16 + (lane & 7) + ((lane >> 4) << 3);
                uint32_t off = row * SQA + (ks * 2 + ((lane >> 3) & 1)) * 16;
                LDSM4(bh, bKh + off);
                LDSM4(bl, bKl + off);
                MMA_BF16(acc[2*nb],   ah, bh[0], bh[1]);
                MMA_BF16(acc[2*nb],   ah, bl[0], bl[1]);
                MMA_BF16(acc[2*nb],   al, bh[0], bh[1]);
                MMA_BF16(acc[2*nb+1], ah, bh[2], bh[3]);
                MMA_BF16(acc[2*nb+1], ah, bl[2], bl[3]);
                MMA_BF16(acc[2*nb+1], al, bh[2], bh[3]);
            }
        }

        // ---- causal mask (only near-diagonal tiles) ----
        if (kt >= 2 * qt) {
            int qrA = qbase + wid * 16 + rA;
            #pragma unroll
            for (int ni = 0; ni < 8; ni++) {
                int key = kt * 64 + ni * 8 + colq;
                if (key     > qrA)     acc[ni][0] = -1e30f;
                if (key + 1 > qrA)     acc[ni][1] = -1e30f;
                if (key     > qrA + 8) acc[ni][2] = -1e30f;
                if (key + 1 > qrA + 8) acc[ni][3] = -1e30f;
            }
        }

        // ---- online softmax ----
        float mxA = -1e30f, mxB = -1e30f;
        #pragma unroll
        for (int ni = 0; ni < 8; ni++) {
            mxA = fmaxf(mxA, fmaxf(acc[ni][0], acc[ni][1]));
            mxB = fmaxf(mxB, fmaxf(acc[ni][2], acc[ni][3]));
        }
        mxA = fmaxf(mxA, __shfl_xor_sync(0xffffffffu, mxA, 1));
        mxA = fmaxf(mxA, __shfl_xor_sync(0xffffffffu, mxA, 2));
        mxB = fmaxf(mxB, __shfl_xor_sync(0xffffffffu, mxB, 1));
        mxB = fmaxf(mxB, __shfl_xor_sync(0xffffffffu, mxB, 2));
        float nmA = fmaxf(mA, mxA), nmB = fmaxf(mB, mxB);
        float aA = __expf(mA - nmA), aB = __expf(mB - nmB);
        mA = nmA; mB = nmB;
        float sA = 0.f, sB = 0.f;
        #pragma unroll
        for (int ni = 0; ni < 8; ni++) {
            acc[ni][0] = __expf(acc[ni][0] - nmA);
            acc[ni][1] = __expf(acc[ni][1] - nmA);
            acc[ni][2] = __expf(acc[ni][2] - nmB);
            acc[ni][3] = __expf(acc[ni][3] - nmB);
            sA += acc[ni][0] + acc[ni][1];
            sB += acc[ni][2] + acc[ni][3];
        }
        lA = lA * aA + sA;
        lB = lB * aB + sB;
        #pragma unroll
        for (int nj = 0; nj < 16; nj++) {
            o[nj][0] *= aA; o[nj][1] *= aA;
            o[nj][2] *= aB; o[nj][3] *= aB;
        }

        // ---- PV (3-term split), P fragments built in-register ----
        #pragma unroll
        for (int ks = 0; ks < 4; ks++) {
            uint32_t ph[4], pl[4];
            #pragma unroll
            for (int j = 0; j < 4; j++) {
                const float* pr = acc[2 * ks + (j >> 1)];
                float p0 = pr[(j & 1) ? 2 : 0];
                float p1 = pr[(j & 1) ? 3 : 1];
                float h0 = __bfloat162float(__float2bfloat16(p0));
                float h1 = __bfloat162float(__float2bfloat16(p1));
                ph[j] = pack_bf16x2(h0, h1);
                pl[j] = pack_bf16x2(p0 - h0, p1 - h1);
            }
            #pragma unroll
            for (int nj = 0; nj < 8; nj++) {
                uint32_t vh[4], vl[4];
                int row = ks * 16 + (lane & 7) + (((lane >> 3) & 1) << 3);
                uint32_t off = row * SQA + nj * 32 + (lane >> 4) * 16;
                LDSM4T(vh, bVh + off);
                LDSM4T(vl, bVl + off);
                MMA_BF16(o[2*nj],   ph, vh[0], vh[1]);
                MMA_BF16(o[2*nj],   ph, vl[0], vl[1]);
                MMA_BF16(o[2*nj],   pl, vh[0], vh[1]);
                MMA_BF16(o[2*nj+1], ph, vh[2], vh[3]);
                MMA_BF16(o[2*nj+1], ph, vl[2], vl[3]);
                MMA_BF16(o[2*nj+1], pl, vh[2], vh[3]);
            }
        }
        __syncthreads();
    }

    // ---- epilogue: normalize, split hi/lo, store ----
    float lAt = lA + __shfl_xor_sync(0xffffffffu, lA, 1);
    lAt += __shfl_xor_sync(0xffffffffu, lAt, 2);
    float lBt = lB + __shfl_xor_sync(0xffffffffu, lB, 1);
    lBt += __shfl_xor_sync(0xffffffffu, lBt, 2);
    float invA = 1.f / lAt, invB = 1.f / lBt;

    const int rowA = qbase + wid * 16 + rA;
    uint32_t* Ch32 = (uint32_t*)Chi;
    uint32_t* Cl32 = (uint32_t*)Clo;
    #pragma unroll
    for (int nj = 0; nj < 16; nj++) {
        int col = h * HD + nj * 8 + colq;
        float v0 = o[nj][0] * invA, v1 = o[nj][1] * invA;
        float v2 = o[nj][2] * invB, v3 = o[nj][3] * invB;
        float h0 = __bfloat162float(__float2bfloat16(v0));
        float h1 = __bfloat162float(__float2bfloat16(v1));
        float h2 = __bfloat162float(__float2bfloat16(v2));
        float h3 = __bfloat162float(__float2bfloat16(v3));
        size_t iA = (size_t)rowA * (DOUT/2) + (col >> 1);
        size_t iB = (size_t)(rowA + 8) * (DOUT/2) + (col >> 1);
        Ch32[iA] = pack_bf16x2(h0, h1);
        Cl32[iA] = pack_bf16x2(v0 - h0, v1 - h1);
        Ch32[iB] = pack_bf16x2(h2, h3);
        Cl32[iB] = pack_bf16x2(v2 - h2, v3 - h3);
    }
}

// ---------------------------------------------------------------------------
extern "C" void kernel_launch(void* const* d_in, const int* in_sizes, int n_in,
                              void* d_out, int out_size)
{
    const float* x    = (const float*)d_in[0];
    const float* cosp = (const float*)d_in[2];
    const float* sinp = (const float*)d_in[3];
    const float* Wq   = (const float*)d_in[4];
    const float* Wk   = (const float*)d_in[5];
    const float* Wv   = (const float*)d_in[6];
    const float* Wo   = (const float*)d_in[7];
    const float* qsc  = (const float*)d_in[8];
    const float* ksc  = (const float*)d_in[9];

    float* out  = (float*)d_out;
    float* kout = out  + (size_t)S_LEN * DIN;
    float* vout = kout + (size_t)G_KV * S_LEN * HD;

    float *gq, *gk;
    __nv_bfloat16 *xhi, *xlo, *wqh, *wql, *wkh, *wkl, *wvh, *wvl, *woh, *wol, *chi, *clo;
    __nv_bfloat16 *qh, *ql, *kh, *kl, *vh, *vl;
    cudaGetSymbolAddress((void**)&gq,   g_q);
    cudaGetSymbolAddress((void**)&gk,   g_k);
    cudaGetSymbolAddress((void**)&xhi,  g_xhi);
    cudaGetSymbolAddress((void**)&xlo,  g_xlo);
    cudaGetSymbolAddress((void**)&wqh,  g_wqt_hi);
    cudaGetSymbolAddress((void**)&wql,  g_wqt_lo);
    cudaGetSymbolAddress((void**)&wkh,  g_wkt_hi);
    cudaGetSymbolAddress((void**)&wkl,  g_wkt_lo);
    cudaGetSymbolAddress((void**)&wvh,  g_wvt_hi);
    cudaGetSymbolAddress((void**)&wvl,  g_wvt_lo);
    cudaGetSymbolAddress((void**)&woh,  g_wot_hi);
    cudaGetSymbolAddress((void**)&wol,  g_wot_lo);
    cudaGetSymbolAddress((void**)&chi,  g_chi);
    cudaGetSymbolAddress((void**)&clo,  g_clo);
    cudaGetSymbolAddress((void**)&qh,   g_qh);
    cudaGetSymbolAddress((void**)&ql,   g_ql);
    cudaGetSymbolAddress((void**)&kh,   g_kh);
    cudaGetSymbolAddress((void**)&kl,   g_kl);
    cudaGetSymbolAddress((void**)&vh,   g_vh);
    cudaGetSymbolAddress((void**)&vl,   g_vl);

    cudaFuncSetAttribute(gemm_mma_kernel, cudaFuncAttributeMaxDynamicSharedMemorySize, GEMM_SMEM);
    cudaFuncSetAttribute(attn_mma_kernel, cudaFuncAttributeMaxDynamicSharedMemorySize, ATT_SMEM);

    dim3 tb(32, 8);

    {
        int n4 = S_LEN * DIN / 4;
        split_kernel<<<(n4 + 255) / 256, 256>>>((const float4*)x, (ushort4*)xhi, (ushort4*)xlo, n4);
    }
    transpose_split_kernel<<<dim3(DOUT/32, DIN/32),  tb>>>(Wq, wqh, wql, DIN,  DOUT);
    transpose_split_kernel<<<dim3(GKD /32, DIN/32),  tb>>>(Wk, wkh, wkl, DIN,  GKD);
    transpose_split_kernel<<<dim3(GKD /32, DIN/32),  tb>>>(Wv, wvh, wvl, DIN,  GKD);
    transpose_split_kernel<<<dim3(DIN /32, DOUT/32), tb>>>(Wo, woh, wol, DOUT, DIN);

    gemm_mma_kernel<<<dim3(DOUT/128, S_LEN/128), 256, GEMM_SMEM>>>(xhi, xlo, wqh, wql, gq,   DOUT, DIN, 0);
    gemm_mma_kernel<<<dim3(GKD /128, S_LEN/128), 256, GEMM_SMEM>>>(xhi, xlo, wkh, wkl, gk,   GKD,  DIN, 0);
    gemm_mma_kernel<<<dim3(GKD /128, S_LEN/128), 256, GEMM_SMEM>>>(xhi, xlo, wvh, wvl, vout, GKD,  DIN, 1);

    norm_rope_q_kernel<<<dim3(S_LEN, H_Q),  128>>>(gq, qsc, cosp, sinp, qh, ql);
    norm_rope_k_kernel<<<dim3(S_LEN, G_KV), 128>>>(gk, ksc, cosp, sinp, kout, kh, kl);
    {
        int n4 = G_KV * S_LEN * HD / 4;
        split_kernel<<<(n4 + 255) / 256, 256>>>((const float4*)vout, (ushort4*)vh, (ushort4*)vl, n4);
    }

    attn_mma_kernel<<<dim3(S_LEN/128, H_Q), 256, ATT_SMEM>>>(qh, ql, kh, kl, vh, vl, chi, clo);

    gemm_mma_kernel<<<dim3(DIN/128, S_LEN/128), 256, GEMM_SMEM>>>(chi, clo, woh, wol, out, DIN, DOUT, 0);
}

// round 5
// speedup vs baseline: 5.0969x; 1.4658x over previous
#include <cuda_runtime.h>
#include <cuda_bf16.h>
#include <cuda_fp16.h>
#include <math.h>
#include <stdint.h>

#define S_LEN 2048
#define DIN   2048
#define H_Q   32
#define G_KV  8
#define HD    128
#define DOUT  (H_Q*HD)   /* 4096 */
#define GKD   (G_KV*HD)  /* 1024 */

// ---------------- scratch (__device__ globals; no runtime alloc) ------------
__device__ float g_q  [S_LEN * (size_t)DOUT];
__device__ float g_k  [S_LEN * (size_t)GKD];

__device__ __half g_xf16 [S_LEN * (size_t)DIN];          // x, single fp16
__device__ __half g_cf16 [S_LEN * (size_t)DOUT];         // ctx, single fp16
__device__ __half g_wqt_hi[(size_t)DOUT * DIN];
__device__ __half g_wqt_lo[(size_t)DOUT * DIN];
__device__ __half g_wkt_hi[(size_t)GKD  * DIN];
__device__ __half g_wkt_lo[(size_t)GKD  * DIN];
__device__ __half g_wvt_hi[(size_t)GKD  * DIN];
__device__ __half g_wvt_lo[(size_t)GKD  * DIN];
__device__ __half g_wot_hi[(size_t)DIN  * DOUT];
__device__ __half g_wot_lo[(size_t)DIN  * DOUT];

// attention operands (bf16 hi/lo, unchanged path)
__device__ __nv_bfloat16 g_qh[(size_t)H_Q * S_LEN * HD];
__device__ __nv_bfloat16 g_ql[(size_t)H_Q * S_LEN * HD];
__device__ __nv_bfloat16 g_kh[(size_t)G_KV * S_LEN * HD];
__device__ __nv_bfloat16 g_kl[(size_t)G_KV * S_LEN * HD];
__device__ __nv_bfloat16 g_vh[(size_t)G_KV * S_LEN * HD];
__device__ __nv_bfloat16 g_vl[(size_t)G_KV * S_LEN * HD];

// ---------------------------- PTX helpers (compute_103-safe) ---------------
__device__ __forceinline__ uint32_t smem_u32(const void* p) {
    uint32_t a;
    asm("{ .reg .u64 t; cvta.to.shared.u64 t, %1; cvt.u32.u64 %0, t; }" : "=r"(a) : "l"(p));
    return a;
}
__device__ __forceinline__ void cp16(uint32_t dst, const void* src) {
    asm volatile("cp.async.cg.shared.global [%0], [%1], 16;\n"
                 :: "r"(dst), "l"(__cvta_generic_to_global(src)));
}
__device__ __forceinline__ void cp_commit() {
    asm volatile("cp.async.commit_group;" ::: "memory");
}
template<int N> __device__ __forceinline__ void cp_wait() {
    asm volatile("cp.async.wait_group %0;" :: "n"(N) : "memory");
}
#define LDSM4(r, addr) \
    asm volatile("ldmatrix.sync.aligned.m8n8.x4.shared.b16 {%0,%1,%2,%3}, [%4];" \
        : "=r"((r)[0]), "=r"((r)[1]), "=r"((r)[2]), "=r"((r)[3]) : "r"(addr))
#define LDSM4T(r, addr) \
    asm volatile("ldmatrix.sync.aligned.m8n8.x4.trans.shared.b16 {%0,%1,%2,%3}, [%4];" \
        : "=r"((r)[0]), "=r"((r)[1]), "=r"((r)[2]), "=r"((r)[3]) : "r"(addr))
#define MMA_BF16(d, a, b0, b1) \
    asm volatile("mma.sync.aligned.m16n8k16.row.col.f32.bf16.bf16.f32 " \
        "{%0,%1,%2,%3}, {%4,%5,%6,%7}, {%8,%9}, {%0,%1,%2,%3};" \
        : "+f"((d)[0]), "+f"((d)[1]), "+f"((d)[2]), "+f"((d)[3]) \
        : "r"((a)[0]), "r"((a)[1]), "r"((a)[2]), "r"((a)[3]), "r"(b0), "r"(b1))
#define MMA_F16(d, a, b0, b1) \
    asm volatile("mma.sync.aligned.m16n8k16.row.col.f32.f16.f16.f32 " \
        "{%0,%1,%2,%3}, {%4,%5,%6,%7}, {%8,%9}, {%0,%1,%2,%3};" \
        : "+f"((d)[0]), "+f"((d)[1]), "+f"((d)[2]), "+f"((d)[3]) \
        : "r"((a)[0]), "r"((a)[1]), "r"((a)[2]), "r"((a)[3]), "r"(b0), "r"(b1))

__device__ __forceinline__ uint32_t pack_bf16x2(float lo, float hi) {
    uint32_t r;
    asm("cvt.rn.bf16x2.f32 %0, %1, %2;" : "=r"(r) : "f"(hi), "f"(lo));
    return r;
}
__device__ __forceinline__ uint32_t pack_f16x2(float lo, float hi) {
    uint32_t r;
    asm("cvt.rn.f16x2.f32 %0, %1, %2;" : "=r"(r) : "f"(hi), "f"(lo));
    return r;
}

// ---------------------------------------------------------------------------
// fp16 2-term GEMM via mma.sync:  C[M,N] = A[M,K] @ (Bhi+Blo)[N,K]^T
// Tile 128x128x32, 256 threads, warp tile 64x32.
// 3-stage cp.async ring, ONE __syncthreads per K-stage (loads issued after
// compute; the barrier guarantees compute(t-1) finished before buf (t-1)%3
// is overwritten by load(t+2)).
// vmode==1: scatter C into [G, S, HD] layout.
// ---------------------------------------------------------------------------
#define TILE_B   10240             /* 128 rows * 80 B */
#define STAGE_B  (3*TILE_B)        /* A, Bh, Bl */
#define GEMM_SMEM (3*STAGE_B)      /* 92160 */

__global__ __launch_bounds__(256) void gemm_mma_kernel(
    const __half* __restrict__ A,
    const __half* __restrict__ Bhi, const __half* __restrict__ Blo,
    float* __restrict__ C, int N, int K, int vmode)
{
    extern __shared__ __align__(128) char smem[];
    const uint32_t sb = smem_u32(smem);
    const int tid  = threadIdx.x;
    const int wid  = tid >> 5;
    const int lane = tid & 31;
    const int warp_m = wid >> 2;
    const int warp_n = wid & 3;
    const int m0 = blockIdx.y * 128;
    const int n0 = blockIdx.x * 128;

    float acc[4][4][4];
    #pragma unroll
    for (int mi = 0; mi < 4; mi++)
        #pragma unroll
        for (int ni = 0; ni < 4; ni++)
            #pragma unroll
            for (int q = 0; q < 4; q++) acc[mi][ni][q] = 0.f;

    // 1536 chunks (16B) per stage, 6 per thread
    auto load_stage = [&](int k0, int buf) {
        uint32_t base = sb + buf * STAGE_B;
        #pragma unroll
        for (int i = 0; i < 6; i++) {
            int c = tid + (i << 8);
            int tile = c >> 9, w = c & 511, row = w >> 2, ch = w & 3;
            const __half* g;
            if (tile == 0)      g = A   + (size_t)(m0 + row) * K + k0 + (ch << 3);
            else if (tile == 1) g = Bhi + (size_t)(n0 + row) * K + k0 + (ch << 3);
            else                g = Blo + (size_t)(n0 + row) * K + k0 + (ch << 3);
            cp16(base + tile * TILE_B + row * 80 + (ch << 4), g);
        }
        cp_commit();
    };

    auto compute_stage = [&](int buf) {
        uint32_t base = sb + buf * STAGE_B;
        uint32_t sA = base, sBh = base + TILE_B, sBl = base + 2*TILE_B;
        #pragma unroll
        for (int kk = 0; kk < 2; kk++) {
            const int kb = kk * 2;
            uint32_t a[4][4], bh[2][4], bl[2][4];
            #pragma unroll
            for (int mi = 0; mi < 4; mi++) {
                int row = warp_m * 64 + mi * 16 + (lane & 15);
                LDSM4(a[mi], sA + row * 80 + (kb + (lane >> 4)) * 16);
            }
            #pragma unroll
            for (int bi = 0; bi < 2; bi++) {
                int row = warp_n * 32 + bi * 16 + (lane & 7) + ((lane >> 4) << 3);
                uint32_t off = row * 80 + (kb + ((lane >> 3) & 1)) * 16;
                LDSM4(bh[bi], sBh + off);
                LDSM4(bl[bi], sBl + off);
            }
            #pragma unroll
            for (int mi = 0; mi < 4; mi++)
                #pragma unroll
                for (int ni = 0; ni < 4; ni++) {
                    uint32_t* Bh = &bh[ni >> 1][(ni & 1) * 2];
                    uint32_t* Bl = &bl[ni >> 1][(ni & 1) * 2];
                    MMA_F16(acc[mi][ni], a[mi], Bh[0], Bh[1]);
                    MMA_F16(acc[mi][ni], a[mi], Bl[0], Bl[1]);
                }
        }
    };

    const int NS = K >> 5;
    load_stage(0, 0);
    load_stage(32, 1);
    for (int t = 0; t < NS; t++) {
        if (t + 1 < NS) cp_wait<1>(); else cp_wait<0>();
        __syncthreads();
        compute_stage(t % 3);
        if (t + 2 < NS) load_stage((t + 2) << 5, (t + 2) % 3);
    }

    #pragma unroll
    for (int mi = 0; mi < 4; mi++) {
        #pragma unroll
        for (int ni = 0; ni < 4; ni++) {
            int r0 = m0 + warp_m * 64 + mi * 16 + (lane >> 2);
            int c0 = n0 + warp_n * 32 + ni * 8 + (lane & 3) * 2;
            if (vmode == 0) {
                *(float2*)(C + (size_t)r0 * N + c0)       = make_float2(acc[mi][ni][0], acc[mi][ni][1]);
                *(float2*)(C + (size_t)(r0 + 8) * N + c0) = make_float2(acc[mi][ni][2], acc[mi][ni][3]);
            } else {
                size_t g = (size_t)(c0 >> 7) * S_LEN * HD;
                int cc = c0 & 127;
                *(float2*)(C + g + (size_t)r0 * HD + cc)       = make_float2(acc[mi][ni][0], acc[mi][ni][1]);
                *(float2*)(C + g + (size_t)(r0 + 8) * HD + cc) = make_float2(acc[mi][ni][2], acc[mi][ni][3]);
            }
        }
    }
}

// ------------------------- conversion kernels ------------------------------
__global__ __launch_bounds__(256) void split_f16_kernel(
    const float4* __restrict__ in, ushort4* __restrict__ o16, int n4)
{
    int i = blockIdx.x * 256 + threadIdx.x;
    if (i >= n4) return;
    float4 v = in[i];
    o16[i] = make_ushort4(__half_as_ushort(__float2half_rn(v.x)),
                          __half_as_ushort(__float2half_rn(v.y)),
                          __half_as_ushort(__float2half_rn(v.z)),
                          __half_as_ushort(__float2half_rn(v.w)));
}

__global__ __launch_bounds__(256) void split_bf16_kernel(
    const float4* __restrict__ in, ushort4* __restrict__ hi,
    ushort4* __restrict__ lo, int n4)
{
    int i = blockIdx.x * 256 + threadIdx.x;
    if (i >= n4) return;
    float4 v = in[i];
    float f[4] = {v.x, v.y, v.z, v.w};
    unsigned short h[4], l[4];
    #pragma unroll
    for (int j = 0; j < 4; j++) {
        __nv_bfloat16 hb = __float2bfloat16(f[j]);
        __nv_bfloat16 lb = __float2bfloat16(f[j] - __bfloat162float(hb));
        h[j] = __bfloat16_as_ushort(hb);
        l[j] = __bfloat16_as_ushort(lb);
    }
    hi[i] = make_ushort4(h[0], h[1], h[2], h[3]);
    lo[i] = make_ushort4(l[0], l[1], l[2], l[3]);
}

__global__ __launch_bounds__(256) void transpose_split_kernel(
    const float* __restrict__ W, __half* __restrict__ Thi,
    __half* __restrict__ Tlo, int K, int N)
{
    __shared__ float t[32][33];
    const int bn = blockIdx.x * 32, bk = blockIdx.y * 32;
    const int tx = threadIdx.x, ty = threadIdx.y;
    #pragma unroll
    for (int j = 0; j < 32; j += 8)
        t[ty + j][tx] = W[(size_t)(bk + ty + j) * N + bn + tx];
    __syncthreads();
    #pragma unroll
    for (int j = 0; j < 32; j += 8) {
        float v = t[tx][ty + j];
        __half h = __float2half_rn(v);
        __half l = __float2half_rn(v - __half2float(h));
        size_t o = (size_t)(bn + ty + j) * K + bk + tx;
        Thi[o] = h; Tlo[o] = l;
    }
}

// ------------------------- RMSNorm + RoPE variants -------------------------
__global__ __launch_bounds__(128) void norm_rope_q_kernel(
    const float* __restrict__ in, const float* __restrict__ scale,
    const float* __restrict__ cosp, const float* __restrict__ sinp,
    __nv_bfloat16* __restrict__ qh, __nv_bfloat16* __restrict__ ql)
{
    const int s = blockIdx.x, h = blockIdx.y, d = threadIdx.x;
    const size_t base = ((size_t)s * H_Q + h) * HD;
    float x = in[base + d];
    float v = x * x;
    #pragma unroll
    for (int off = 16; off; off >>= 1) v += __shfl_xor_sync(0xffffffffu, v, off);
    __shared__ float ws[4];
    __shared__ float ysm[HD];
    if ((d & 31) == 0) ws[d >> 5] = v;
    __syncthreads();
    float var = (ws[0] + ws[1] + ws[2] + ws[3]) * (1.0f / HD);
    float y = x * rsqrtf(var + 1e-6f) * scale[d];
    ysm[d] = y;
    __syncthreads();
    float rot = (d < 64) ? -ysm[d + 64] : ysm[d - 64];
    float r = fmaf(y, cosp[s * HD + d], rot * sinp[s * HD + d]) * 0.088388347648318447f;
    __nv_bfloat16 hb = __float2bfloat16(r);
    __nv_bfloat16 lb = __float2bfloat16(r - __bfloat162float(hb));
    size_t o = ((size_t)h * S_LEN + s) * HD + d;
    qh[o] = hb; ql[o] = lb;
}

__global__ __launch_bounds__(128) void norm_rope_k_kernel(
    const float* __restrict__ in, const float* __restrict__ scale,
    const float* __restrict__ cosp, const float* __restrict__ sinp,
    float* __restrict__ kout, __nv_bfloat16* __restrict__ kh,
    __nv_bfloat16* __restrict__ kl)
{
    const int s = blockIdx.x, h = blockIdx.y, d = threadIdx.x;
    const size_t base = ((size_t)s * G_KV + h) * HD;
    float x = in[base + d];
    float v = x * x;
    #pragma unroll
    for (int off = 16; off; off >>= 1) v += __shfl_xor_sync(0xffffffffu, v, off);
    __shared__ float ws[4];
    __shared__ float ysm[HD];
    if ((d & 31) == 0) ws[d >> 5] = v;
    __syncthreads();
    float var = (ws[0] + ws[1] + ws[2] + ws[3]) * (1.0f / HD);
    float y = x * rsqrtf(var + 1e-6f) * scale[d];
    ysm[d] = y;
    __syncthreads();
    float rot = (d < 64) ? -ysm[d + 64] : ysm[d - 64];
    float r = fmaf(y, cosp[s * HD + d], rot * sinp[s * HD + d]);
    size_t o = ((size_t)h * S_LEN + s) * HD + d;
    kout[o] = r;
    __nv_bfloat16 hb = __float2bfloat16(r);
    __nv_bfloat16 lb = __float2bfloat16(r - __bfloat162float(hb));
    kh[o] = hb; kl[o] = lb;
}

// ---------------------------------------------------------------------------
// Tensor-core flash attention (bf16 3-term, unchanged from R4 except the
// epilogue now emits single fp16 ctx for the Wo GEMM).
// ---------------------------------------------------------------------------
#define SQA      272
#define Q_BYTES  (128*SQA)
#define KV_TILE  (64*SQA)
#define ATT_SMEM (2*Q_BYTES + 2*4*KV_TILE)

__global__ __launch_bounds__(256) void attn_mma_kernel(
    const __nv_bfloat16* __restrict__ Qh, const __nv_bfloat16* __restrict__ Ql,
    const __nv_bfloat16* __restrict__ Kh, const __nv_bfloat16* __restrict__ Kl,
    const __nv_bfloat16* __restrict__ Vh, const __nv_bfloat16* __restrict__ Vl,
    __half* __restrict__ Cf)
{
    extern __shared__ __align__(128) char smem[];
    const uint32_t sb = smem_u32(smem);
    const int h  = blockIdx.y;
    const int g  = h >> 2;
    const int qt = gridDim.x - 1 - blockIdx.x;
    const int tid = threadIdx.x, wid = tid >> 5, lane = tid & 31;
    const int qbase = qt * 128;

    const uint32_t sQh = sb, sQl = sb + Q_BYTES;
    const uint32_t sKV0 = sb + 2 * Q_BYTES;

    {
        const __nv_bfloat16* bh = Qh + ((size_t)h * S_LEN + qbase) * HD;
        const __nv_bfloat16* bl = Ql + ((size_t)h * S_LEN + qbase) * HD;
        #pragma unroll
        for (int i = 0; i < 8; i++) {
            int c = tid + (i << 8);
            int r = c >> 4, ch = c & 15;
            cp16(sQh + r * SQA + ch * 16, bh + r * HD + ch * 8);
            cp16(sQl + r * SQA + ch * 16, bl + r * HD + ch * 8);
        }
    }
    auto load_kv = [&](int kt, int buf) {
        uint32_t base = sKV0 + buf * 4 * KV_TILE;
        const size_t gb = ((size_t)g * S_LEN + kt * 64) * HD;
        #pragma unroll
        for (int i = 0; i < 16; i++) {
            int c = tid + (i << 8);
            int arr = c >> 10, w = c & 1023, r = w >> 4, ch = w & 15;
            const __nv_bfloat16* src =
                (arr == 0 ? Kh : arr == 1 ? Kl : arr == 2 ? Vh : Vl) + gb + r * HD + ch * 8;
            cp16(base + arr * KV_TILE + r * SQA + ch * 16, src);
        }
    };
    load_kv(0, 0);
    cp_commit();

    float o[16][4];
    #pragma unroll
    for (int nj = 0; nj < 16; nj++)
        #pragma unroll
        for (int q = 0; q < 4; q++) o[nj][q] = 0.f;
    float mA = -1e30f, mB = -1e30f, lA = 0.f, lB = 0.f;

    const int rA = lane >> 2;
    const int colq = (lane & 3) * 2;
    const int ktmax = 2 * qt + 1;

    for (int kt = 0; kt <= ktmax; kt++) {
        if (kt < ktmax) { load_kv(kt + 1, (kt + 1) & 1); cp_commit(); cp_wait<1>(); }
        else            { cp_wait<0>(); }
        __syncthreads();

        const uint32_t bKh = sKV0 + (kt & 1) * 4 * KV_TILE;
        const uint32_t bKl = bKh + KV_TILE;
        const uint32_t bVh = bKh + 2 * KV_TILE;
        const uint32_t bVl = bKh + 3 * KV_TILE;

        float acc[8][4];
        #pragma unroll
        for (int ni = 0; ni < 8; ni++)
            #pragma unroll
            for (int q = 0; q < 4; q++) acc[ni][q] = 0.f;

        #pragma unroll
        for (int ks = 0; ks < 8; ks++) {
            uint32_t ah[4], al[4];
            {
                int row = wid * 16 + (lane & 15);
                uint32_t off = row * SQA + (ks * 2 + (lane >> 4)) * 16;
                LDSM4(ah, sQh + off);
                LDSM4(al, sQl + off);
            }
            #pragma unroll
            for (int nb = 0; nb < 4; nb++) {
                uint32_t bh[4], bl[4];
                int row = nb * 16 + (lane & 7) + ((lane >> 4) << 3);
                uint32_t off = row * SQA + (ks * 2 + ((lane >> 3) & 1)) * 16;
                LDSM4(bh, bKh + off);
                LDSM4(bl, bKl + off);
                MMA_BF16(acc[2*nb],   ah, bh[0], bh[1]);
                MMA_BF16(acc[2*nb],   ah, bl[0], bl[1]);
                MMA_BF16(acc[2*nb],   al, bh[0], bh[1]);
                MMA_BF16(acc[2*nb+1], ah, bh[2], bh[3]);
                MMA_BF16(acc[2*nb+1], ah, bl[2], bl[3]);
                MMA_BF16(acc[2*nb+1], al, bh[2], bh[3]);
            }
        }

        if (kt >= 2 * qt) {
            int qrA = qbase + wid * 16 + rA;
            #pragma unroll
            for (int ni = 0; ni < 8; ni++) {
                int key = kt * 64 + ni * 8 + colq;
                if (key     > qrA)     acc[ni][0] = -1e30f;
                if (key + 1 > qrA)     acc[ni][1] = -1e30f;
                if (key     > qrA + 8) acc[ni][2] = -1e30f;
                if (key + 1 > qrA + 8) acc[ni][3] = -1e30f;
            }
        }

        float mxA = -1e30f, mxB = -1e30f;
        #pragma unroll
        for (int ni = 0; ni < 8; ni++) {
            mxA = fmaxf(mxA, fmaxf(acc[ni][0], acc[ni][1]));
            mxB = fmaxf(mxB, fmaxf(acc[ni][2], acc[ni][3]));
        }
        mxA = fmaxf(mxA, __shfl_xor_sync(0xffffffffu, mxA, 1));
        mxA = fmaxf(mxA, __shfl_xor_sync(0xffffffffu, mxA, 2));
        mxB = fmaxf(mxB, __shfl_xor_sync(0xffffffffu, mxB, 1));
        mxB = fmaxf(mxB, __shfl_xor_sync(0xffffffffu, mxB, 2));
        float nmA = fmaxf(mA, mxA), nmB = fmaxf(mB, mxB);
        float aA = __expf(mA - nmA), aB = __expf(mB - nmB);
        mA = nmA; mB = nmB;
        float sA = 0.f, sB = 0.f;
        #pragma unroll
        for (int ni = 0; ni < 8; ni++) {
            acc[ni][0] = __expf(acc[ni][0] - nmA);
            acc[ni][1] = __expf(acc[ni][1] - nmA);
            acc[ni][2] = __expf(acc[ni][2] - nmB);
            acc[ni][3] = __expf(acc[ni][3] - nmB);
            sA += acc[ni][0] + acc[ni][1];
            sB += acc[ni][2] + acc[ni][3];
        }
        lA = lA * aA + sA;
        lB = lB * aB + sB;
        #pragma unroll
        for (int nj = 0; nj < 16; nj++) {
            o[nj][0] *= aA; o[nj][1] *= aA;
            o[nj][2] *= aB; o[nj][3] *= aB;
        }

        #pragma unroll
        for (int ks = 0; ks < 4; ks++) {
            uint32_t ph[4], pl[4];
            #pragma unroll
            for (int j = 0; j < 4; j++) {
                const float* pr = acc[2 * ks + (j >> 1)];
                float p0 = pr[(j & 1) ? 2 : 0];
                float p1 = pr[(j & 1) ? 3 : 1];
                float h0 = __bfloat162float(__float2bfloat16(p0));
                float h1 = __bfloat162float(__float2bfloat16(p1));
                ph[j] = pack_bf16x2(h0, h1);
                pl[j] = pack_bf16x2(p0 - h0, p1 - h1);
            }
            #pragma unroll
            for (int nj = 0; nj < 8; nj++) {
                uint32_t vh[4], vl[4];
                int row = ks * 16 + (lane & 7) + (((lane >> 3) & 1) << 3);
                uint32_t off = row * SQA + nj * 32 + (lane >> 4) * 16;
                LDSM4T(vh, bVh + off);
                LDSM4T(vl, bVl + off);
                MMA_BF16(o[2*nj],   ph, vh[0], vh[1]);
                MMA_BF16(o[2*nj],   ph, vl[0], vl[1]);
                MMA_BF16(o[2*nj],   pl, vh[0], vh[1]);
                MMA_BF16(o[2*nj+1], ph, vh[2], vh[3]);
                MMA_BF16(o[2*nj+1], ph, vl[2], vl[3]);
                MMA_BF16(o[2*nj+1], pl, vh[2], vh[3]);
            }
        }
        __syncthreads();
    }

    float lAt = lA + __shfl_xor_sync(0xffffffffu, lA, 1);
    lAt += __shfl_xor_sync(0xffffffffu, lAt, 2);
    float lBt = lB + __shfl_xor_sync(0xffffffffu, lB, 1);
    lBt += __shfl_xor_sync(0xffffffffu, lBt, 2);
    float invA = 1.f / lAt, invB = 1.f / lBt;

    const int rowA = qbase + wid * 16 + rA;
    uint32_t* C32 = (uint32_t*)Cf;
    #pragma unroll
    for (int nj = 0; nj < 16; nj++) {
        int col = h * HD + nj * 8 + colq;
        float v0 = o[nj][0] * invA, v1 = o[nj][1] * invA;
        float v2 = o[nj][2] * invB, v3 = o[nj][3] * invB;
        C32[(size_t)rowA * (DOUT/2) + (col >> 1)]       = pack_f16x2(v0, v1);
        C32[(size_t)(rowA + 8) * (DOUT/2) + (col >> 1)] = pack_f16x2(v2, v3);
    }
}

// ---------------------------------------------------------------------------
extern "C" void kernel_launch(void* const* d_in, const int* in_sizes, int n_in,
                              void* d_out, int out_size)
{
    const float* x    = (const float*)d_in[0];
    const float* cosp = (const float*)d_in[2];
    const float* sinp = (const float*)d_in[3];
    const float* Wq   = (const float*)d_in[4];
    const float* Wk   = (const float*)d_in[5];
    const float* Wv   = (const float*)d_in[6];
    const float* Wo   = (const float*)d_in[7];
    const float* qsc  = (const float*)d_in[8];
    const float* ksc  = (const float*)d_in[9];

    float* out  = (float*)d_out;
    float* kout = out  + (size_t)S_LEN * DIN;
    float* vout = kout + (size_t)G_KV * S_LEN * HD;

    float *gq, *gk;
    __half *xf, *cf, *wqh, *wql, *wkh, *wkl, *wvh, *wvl, *woh, *wol;
    __nv_bfloat16 *qh, *ql, *kh, *kl, *vh, *vl;
    cudaGetSymbolAddress((void**)&gq,  g_q);
    cudaGetSymbolAddress((void**)&gk,  g_k);
    cudaGetSymbolAddress((void**)&xf,  g_xf16);
    cudaGetSymbolAddress((void**)&cf,  g_cf16);
    cudaGetSymbolAddress((void**)&wqh, g_wqt_hi);
    cudaGetSymbolAddress((void**)&wql, g_wqt_lo);
    cudaGetSymbolAddress((void**)&wkh, g_wkt_hi);
    cudaGetSymbolAddress((void**)&wkl, g_wkt_lo);
    cudaGetSymbolAddress((void**)&wvh, g_wvt_hi);
    cudaGetSymbolAddress((void**)&wvl, g_wvt_lo);
    cudaGetSymbolAddress((void**)&woh, g_wot_hi);
    cudaGetSymbolAddress((void**)&wol, g_wot_lo);
    cudaGetSymbolAddress((void**)&qh,  g_qh);
    cudaGetSymbolAddress((void**)&ql,  g_ql);
    cudaGetSymbolAddress((void**)&kh,  g_kh);
    cudaGetSymbolAddress((void**)&kl,  g_kl);
    cudaGetSymbolAddress((void**)&vh,  g_vh);
    cudaGetSymbolAddress((void**)&vl,  g_vl);

    cudaFuncSetAttribute(gemm_mma_kernel, cudaFuncAttributeMaxDynamicSharedMemorySize, GEMM_SMEM);
    cudaFuncSetAttribute(attn_mma_kernel, cudaFuncAttributeMaxDynamicSharedMemorySize, ATT_SMEM);

    dim3 tb(32, 8);

    {
        int n4 = S_LEN * DIN / 4;
        split_f16_kernel<<<(n4 + 255) / 256, 256>>>((const float4*)x, (ushort4*)xf, n4);
    }
    transpose_split_kernel<<<dim3(DOUT/32, DIN/32),  tb>>>(Wq, wqh, wql, DIN,  DOUT);
    transpose_split_kernel<<<dim3(GKD /32, DIN/32),  tb>>>(Wk, wkh, wkl, DIN,  GKD);
    transpose_split_kernel<<<dim3(GKD /32, DIN/32),  tb>>>(Wv, wvh, wvl, DIN,  GKD);
    transpose_split_kernel<<<dim3(DIN /32, DOUT/32), tb>>>(Wo, woh, wol, DOUT, DIN);

    gemm_mma_kernel<<<dim3(DOUT/128, S_LEN/128), 256, GEMM_SMEM>>>(xf, wqh, wql, gq,   DOUT, DIN, 0);
    gemm_mma_kernel<<<dim3(GKD /128, S_LEN/128), 256, GEMM_SMEM>>>(xf, wkh, wkl, gk,   GKD,  DIN, 0);
    gemm_mma_kernel<<<dim3(GKD /128, S_LEN/128), 256, GEMM_SMEM>>>(xf, wvh, wvl, vout, GKD,  DIN, 1);

    norm_rope_q_kernel<<<dim3(S_LEN, H_Q),  128>>>(gq, qsc, cosp, sinp, qh, ql);
    norm_rope_k_kernel<<<dim3(S_LEN, G_KV), 128>>>(gk, ksc, cosp, sinp, kout, kh, kl);
    {
        int n4 = G_KV * S_LEN * HD / 4;
        split_bf16_kernel<<<(n4 + 255) / 256, 256>>>((const float4*)vout, (ushort4*)vh, (ushort4*)vl, n4);
    }

    attn_mma_kernel<<<dim3(S_LEN/128, H_Q), 256, ATT_SMEM>>>(qh, ql, kh, kl, vh, vl, cf);

    gemm_mma_kernel<<<dim3(DIN/128, S_LEN/128), 256, GEMM_SMEM>>>(cf, woh, wol, out, DIN, DOUT, 0);
}

// round 6
// speedup vs baseline: 5.2311x; 1.0263x over previous
#include <cuda_runtime.h>
#include <cuda_bf16.h>
#include <cuda_fp16.h>
#include <math.h>
#include <stdint.h>

#define S_LEN 2048
#define DIN   2048
#define H_Q   32
#define G_KV  8
#define HD    128
#define DOUT  (H_Q*HD)   /* 4096 */
#define GKD   (G_KV*HD)  /* 1024 */
#define QKV_N (DOUT + 2*GKD)  /* 6144 */

// ---------------- scratch (__device__ globals; no runtime alloc) ------------
__device__ float g_q  [S_LEN * (size_t)DOUT];
__device__ float g_k  [S_LEN * (size_t)GKD];

__device__ __half g_xf16 [S_LEN * (size_t)DIN];
__device__ __half g_cf16 [S_LEN * (size_t)DOUT];
__device__ __half g_wqt_hi[(size_t)DOUT * DIN];
__device__ __half g_wqt_lo[(size_t)DOUT * DIN];
__device__ __half g_wkt_hi[(size_t)GKD  * DIN];
__device__ __half g_wkt_lo[(size_t)GKD  * DIN];
__device__ __half g_wvt_hi[(size_t)GKD  * DIN];
__device__ __half g_wvt_lo[(size_t)GKD  * DIN];
__device__ __half g_wot_hi[(size_t)DIN  * DOUT];
__device__ __half g_wot_lo[(size_t)DIN  * DOUT];

// attention operands (bf16 hi/lo)
__device__ __nv_bfloat16 g_qh[(size_t)H_Q * S_LEN * HD];
__device__ __nv_bfloat16 g_ql[(size_t)H_Q * S_LEN * HD];
__device__ __nv_bfloat16 g_kh[(size_t)G_KV * S_LEN * HD];
__device__ __nv_bfloat16 g_kl[(size_t)G_KV * S_LEN * HD];
__device__ __nv_bfloat16 g_vh[(size_t)G_KV * S_LEN * HD];
__device__ __nv_bfloat16 g_vl[(size_t)G_KV * S_LEN * HD];

// ---------------------------- PTX helpers (compute_103-safe) ---------------
__device__ __forceinline__ uint32_t smem_u32(const void* p) {
    uint32_t a;
    asm("{ .reg .u64 t; cvta.to.shared.u64 t, %1; cvt.u32.u64 %0, t; }" : "=r"(a) : "l"(p));
    return a;
}
__device__ __forceinline__ void cp16(uint32_t dst, const void* src) {
    asm volatile("cp.async.cg.shared.global [%0], [%1], 16;\n"
                 :: "r"(dst), "l"(__cvta_generic_to_global(src)));
}
__device__ __forceinline__ void cp_commit() {
    asm volatile("cp.async.commit_group;" ::: "memory");
}
template<int N> __device__ __forceinline__ void cp_wait() {
    asm volatile("cp.async.wait_group %0;" :: "n"(N) : "memory");
}
#define LDSM4(r, addr) \
    asm volatile("ldmatrix.sync.aligned.m8n8.x4.shared.b16 {%0,%1,%2,%3}, [%4];" \
        : "=r"((r)[0]), "=r"((r)[1]), "=r"((r)[2]), "=r"((r)[3]) : "r"(addr))
#define LDSM4T(r, addr) \
    asm volatile("ldmatrix.sync.aligned.m8n8.x4.trans.shared.b16 {%0,%1,%2,%3}, [%4];" \
        : "=r"((r)[0]), "=r"((r)[1]), "=r"((r)[2]), "=r"((r)[3]) : "r"(addr))
#define MMA_BF16(d, a, b0, b1) \
    asm volatile("mma.sync.aligned.m16n8k16.row.col.f32.bf16.bf16.f32 " \
        "{%0,%1,%2,%3}, {%4,%5,%6,%7}, {%8,%9}, {%0,%1,%2,%3};" \
        : "+f"((d)[0]), "+f"((d)[1]), "+f"((d)[2]), "+f"((d)[3]) \
        : "r"((a)[0]), "r"((a)[1]), "r"((a)[2]), "r"((a)[3]), "r"(b0), "r"(b1))
#define MMA_F16(d, a, b0, b1) \
    asm volatile("mma.sync.aligned.m16n8k16.row.col.f32.f16.f16.f32 " \
        "{%0,%1,%2,%3}, {%4,%5,%6,%7}, {%8,%9}, {%0,%1,%2,%3};" \
        : "+f"((d)[0]), "+f"((d)[1]), "+f"((d)[2]), "+f"((d)[3]) \
        : "r"((a)[0]), "r"((a)[1]), "r"((a)[2]), "r"((a)[3]), "r"(b0), "r"(b1))

__device__ __forceinline__ uint32_t pack_bf16x2(float lo, float hi) {
    uint32_t r;
    asm("cvt.rn.bf16x2.f32 %0, %1, %2;" : "=r"(r) : "f"(hi), "f"(lo));
    return r;
}
__device__ __forceinline__ uint32_t pack_f16x2(float lo, float hi) {
    uint32_t r;
    asm("cvt.rn.f16x2.f32 %0, %1, %2;" : "=r"(r) : "f"(hi), "f"(lo));
    return r;
}

// ---------------------------------------------------------------------------
// fp16 2-term GEMM core (tile 128x128x32, 256 thr, warp tile 64x32,
// 3-stage cp.async ring, one __syncthreads per K-stage).
// ---------------------------------------------------------------------------
#define TILE_B   10240             /* 128 rows * 80 B */
#define STAGE_B  (3*TILE_B)        /* A, Bh, Bl */
#define GEMM_SMEM (3*STAGE_B)      /* 92160 */

// main loop shared by both GEMM kernels via macro (A/Bhi/Blo/K in scope;
// leaves fp32 accs in acc[4][4][4])
#define GEMM_MAINLOOP(Aptr, BhiPtr, BloPtr, Kdim, m0v, n0v)                         \
    float acc[4][4][4];                                                             \
    _Pragma("unroll")                                                               \
    for (int mi = 0; mi < 4; mi++)                                                  \
        _Pragma("unroll")                                                           \
        for (int ni = 0; ni < 4; ni++)                                              \
            _Pragma("unroll")                                                       \
            for (int q = 0; q < 4; q++) acc[mi][ni][q] = 0.f;                       \
    auto load_stage = [&](int k0, int buf) {                                        \
        uint32_t base = sb + buf * STAGE_B;                                         \
        _Pragma("unroll")                                                           \
        for (int i = 0; i < 6; i++) {                                               \
            int c = tid + (i << 8);                                                 \
            int tile = c >> 9, w = c & 511, row = w >> 2, ch = w & 3;               \
            const __half* gp;                                                       \
            if (tile == 0)      gp = (Aptr)   + (size_t)((m0v) + row) * (Kdim) + k0 + (ch << 3); \
            else if (tile == 1) gp = (BhiPtr) + (size_t)row * (Kdim) + k0 + (ch << 3); \
            else                gp = (BloPtr) + (size_t)row * (Kdim) + k0 + (ch << 3); \
            cp16(base + tile * TILE_B + row * 80 + (ch << 4), gp);                  \
        }                                                                           \
        cp_commit();                                                                \
    };                                                                              \
    auto compute_stage = [&](int buf) {                                             \
        uint32_t base = sb + buf * STAGE_B;                                         \
        uint32_t sA = base, sBh = base + TILE_B, sBl = base + 2*TILE_B;             \
        _Pragma("unroll")                                                           \
        for (int kk = 0; kk < 2; kk++) {                                            \
            const int kb = kk * 2;                                                  \
            uint32_t a[4][4], bh[2][4], bl[2][4];                                   \
            _Pragma("unroll")                                                       \
            for (int mi = 0; mi < 4; mi++) {                                        \
                int row = warp_m * 64 + mi * 16 + (lane & 15);                      \
                LDSM4(a[mi], sA + row * 80 + (kb + (lane >> 4)) * 16);              \
            }                                                                       \
            _Pragma("unroll")                                                       \
            for (int bi = 0; bi < 2; bi++) {                                        \
                int row = warp_n * 32 + bi * 16 + (lane & 7) + ((lane >> 4) << 3);  \
                uint32_t off = row * 80 + (kb + ((lane >> 3) & 1)) * 16;            \
                LDSM4(bh[bi], sBh + off);                                           \
                LDSM4(bl[bi], sBl + off);                                           \
            }                                                                       \
            _Pragma("unroll")                                                       \
            for (int mi = 0; mi < 4; mi++)                                          \
                _Pragma("unroll")                                                   \
                for (int ni = 0; ni < 4; ni++) {                                    \
                    uint32_t* Bh = &bh[ni >> 1][(ni & 1) * 2];                      \
                    uint32_t* Bl = &bl[ni >> 1][(ni & 1) * 2];                      \
                    MMA_F16(acc[mi][ni], a[mi], Bh[0], Bh[1]);                      \
                    MMA_F16(acc[mi][ni], a[mi], Bl[0], Bl[1]);                      \
                }                                                                   \
        }                                                                           \
    };                                                                              \
    const int NS = (Kdim) >> 5;                                                     \
    load_stage(0, 0);                                                               \
    load_stage(32, 1);                                                              \
    for (int t = 0; t < NS; t++) {                                                  \
        if (t + 1 < NS) cp_wait<1>(); else cp_wait<0>();                            \
        __syncthreads();                                                            \
        compute_stage(t % 3);                                                       \
        if (t + 2 < NS) load_stage((t + 2) << 5, (t + 2) % 3);                      \
    }

// ---- merged QKV projection: N = 6144 segments [Q:4096 | K:1024 | V:1024] ----
__global__ __launch_bounds__(256, 2) void gemm_qkv_kernel(
    const __half* __restrict__ A,
    const __half* __restrict__ WqH, const __half* __restrict__ WqL,
    const __half* __restrict__ WkH, const __half* __restrict__ WkL,
    const __half* __restrict__ WvH, const __half* __restrict__ WvL,
    float* __restrict__ Cq, float* __restrict__ Ck, float* __restrict__ Cv,
    __nv_bfloat16* __restrict__ Vh, __nv_bfloat16* __restrict__ Vl)
{
    extern __shared__ __align__(128) char smem[];
    const uint32_t sb = smem_u32(smem);
    const int tid  = threadIdx.x;
    const int wid  = tid >> 5;
    const int lane = tid & 31;
    const int warp_m = wid >> 2;
    const int warp_n = wid & 3;
    const int m0 = blockIdx.y * 128;
    const int n0g = blockIdx.x * 128;

    int seg, nloc;
    const __half *Bhi, *Blo;
    if (n0g < DOUT)            { seg = 0; nloc = n0g;
                                 Bhi = WqH + (size_t)nloc * DIN; Blo = WqL + (size_t)nloc * DIN; }
    else if (n0g < DOUT + GKD) { seg = 1; nloc = n0g - DOUT;
                                 Bhi = WkH + (size_t)nloc * DIN; Blo = WkL + (size_t)nloc * DIN; }
    else                       { seg = 2; nloc = n0g - DOUT - GKD;
                                 Bhi = WvH + (size_t)nloc * DIN; Blo = WvL + (size_t)nloc * DIN; }

    GEMM_MAINLOOP(A, Bhi, Blo, DIN, m0, n0g)

    #pragma unroll
    for (int mi = 0; mi < 4; mi++) {
        #pragma unroll
        for (int ni = 0; ni < 4; ni++) {
            int r0 = m0 + warp_m * 64 + mi * 16 + (lane >> 2);
            int cl = nloc + warp_n * 32 + ni * 8 + (lane & 3) * 2;
            float2 v01 = make_float2(acc[mi][ni][0], acc[mi][ni][1]);
            float2 v23 = make_float2(acc[mi][ni][2], acc[mi][ni][3]);
            if (seg == 0) {
                *(float2*)(Cq + (size_t)r0 * DOUT + cl)       = v01;
                *(float2*)(Cq + (size_t)(r0 + 8) * DOUT + cl) = v23;
            } else if (seg == 1) {
                *(float2*)(Ck + (size_t)r0 * GKD + cl)       = v01;
                *(float2*)(Ck + (size_t)(r0 + 8) * GKD + cl) = v23;
            } else {
                size_t gb = (size_t)(cl >> 7) * S_LEN * HD;
                int cc = cl & 127;
                size_t iA = gb + (size_t)r0 * HD + cc;
                size_t iB = gb + (size_t)(r0 + 8) * HD + cc;
                *(float2*)(Cv + iA) = v01;
                *(float2*)(Cv + iB) = v23;
                // fused bf16 hi/lo split for attention V
                float h0 = __bfloat162float(__float2bfloat16(v01.x));
                float h1 = __bfloat162float(__float2bfloat16(v01.y));
                float h2 = __bfloat162float(__float2bfloat16(v23.x));
                float h3 = __bfloat162float(__float2bfloat16(v23.y));
                ((uint32_t*)Vh)[iA >> 1] = pack_bf16x2(h0, h1);
                ((uint32_t*)Vl)[iA >> 1] = pack_bf16x2(v01.x - h0, v01.y - h1);
                ((uint32_t*)Vh)[iB >> 1] = pack_bf16x2(h2, h3);
                ((uint32_t*)Vl)[iB >> 1] = pack_bf16x2(v23.x - h2, v23.y - h3);
            }
        }
    }
}

// ---- Wo GEMM: C[M,N] = A @ (Bh+Bl)^T, plain row-major output ----
__global__ __launch_bounds__(256, 2) void gemm_wo_kernel(
    const __half* __restrict__ A,
    const __half* __restrict__ BhiP, const __half* __restrict__ BloP,
    float* __restrict__ C, int N, int K)
{
    extern __shared__ __align__(128) char smem[];
    const uint32_t sb = smem_u32(smem);
    const int tid  = threadIdx.x;
    const int wid  = tid >> 5;
    const int lane = tid & 31;
    const int warp_m = wid >> 2;
    const int warp_n = wid & 3;
    const int m0 = blockIdx.y * 128;
    const int n0 = blockIdx.x * 128;
    const __half* Bhi = BhiP + (size_t)n0 * K;
    const __half* Blo = BloP + (size_t)n0 * K;

    GEMM_MAINLOOP(A, Bhi, Blo, K, m0, n0)

    #pragma unroll
    for (int mi = 0; mi < 4; mi++) {
        #pragma unroll
        for (int ni = 0; ni < 4; ni++) {
            int r0 = m0 + warp_m * 64 + mi * 16 + (lane >> 2);
            int c0 = n0 + warp_n * 32 + ni * 8 + (lane & 3) * 2;
            *(float2*)(C + (size_t)r0 * N + c0)       = make_float2(acc[mi][ni][0], acc[mi][ni][1]);
            *(float2*)(C + (size_t)(r0 + 8) * N + c0) = make_float2(acc[mi][ni][2], acc[mi][ni][3]);
        }
    }
}

// ------------------------- conversion kernels ------------------------------
__global__ __launch_bounds__(256) void split_f16_kernel(
    const float4* __restrict__ in, ushort4* __restrict__ o16, int n4)
{
    int i = blockIdx.x * 256 + threadIdx.x;
    if (i >= n4) return;
    float4 v = in[i];
    o16[i] = make_ushort4(__half_as_ushort(__float2half_rn(v.x)),
                          __half_as_ushort(__float2half_rn(v.y)),
                          __half_as_ushort(__float2half_rn(v.z)),
                          __half_as_ushort(__float2half_rn(v.w)));
}

__global__ __launch_bounds__(256) void transpose_split_kernel(
    const float* __restrict__ W, __half* __restrict__ Thi,
    __half* __restrict__ Tlo, int K, int N)
{
    __shared__ float t[32][33];
    const int bn = blockIdx.x * 32, bk = blockIdx.y * 32;
    const int tx = threadIdx.x, ty = threadIdx.y;
    #pragma unroll
    for (int j = 0; j < 32; j += 8)
        t[ty + j][tx] = W[(size_t)(bk + ty + j) * N + bn + tx];
    __syncthreads();
    #pragma unroll
    for (int j = 0; j < 32; j += 8) {
        float v = t[tx][ty + j];
        __half h = __float2half_rn(v);
        __half l = __float2half_rn(v - __half2float(h));
        size_t o = (size_t)(bn + ty + j) * K + bk + tx;
        Thi[o] = h; Tlo[o] = l;
    }
}

// ------------------------- RMSNorm + RoPE variants -------------------------
__global__ __launch_bounds__(128) void norm_rope_q_kernel(
    const float* __restrict__ in, const float* __restrict__ scale,
    const float* __restrict__ cosp, const float* __restrict__ sinp,
    __nv_bfloat16* __restrict__ qh, __nv_bfloat16* __restrict__ ql)
{
    const int s = blockIdx.x, h = blockIdx.y, d = threadIdx.x;
    const size_t base = ((size_t)s * H_Q + h) * HD;
    float x = in[base + d];
    float v = x * x;
    #pragma unroll
    for (int off = 16; off; off >>= 1) v += __shfl_xor_sync(0xffffffffu, v, off);
    __shared__ float ws[4];
    __shared__ float ysm[HD];
    if ((d & 31) == 0) ws[d >> 5] = v;
    __syncthreads();
    float var = (ws[0] + ws[1] + ws[2] + ws[3]) * (1.0f / HD);
    float y = x * rsqrtf(var + 1e-6f) * scale[d];
    ysm[d] = y;
    __syncthreads();
    float rot = (d < 64) ? -ysm[d + 64] : ysm[d - 64];
    float r = fmaf(y, cosp[s * HD + d], rot * sinp[s * HD + d]) * 0.088388347648318447f;
    __nv_bfloat16 hb = __float2bfloat16(r);
    __nv_bfloat16 lb = __float2bfloat16(r - __bfloat162float(hb));
    size_t o = ((size_t)h * S_LEN + s) * HD + d;
    qh[o] = hb; ql[o] = lb;
}

__global__ __launch_bounds__(128) void norm_rope_k_kernel(
    const float* __restrict__ in, const float* __restrict__ scale,
    const float* __restrict__ cosp, const float* __restrict__ sinp,
    float* __restrict__ kout, __nv_bfloat16* __restrict__ kh,
    __nv_bfloat16* __restrict__ kl)
{
    const int s = blockIdx.x, h = blockIdx.y, d = threadIdx.x;
    const size_t base = ((size_t)s * G_KV + h) * HD;
    float x = in[base + d];
    float v = x * x;
    #pragma unroll
    for (int off = 16; off; off >>= 1) v += __shfl_xor_sync(0xffffffffu, v, off);
    __shared__ float ws[4];
    __shared__ float ysm[HD];
    if ((d & 31) == 0) ws[d >> 5] = v;
    __syncthreads();
    float var = (ws[0] + ws[1] + ws[2] + ws[3]) * (1.0f / HD);
    float y = x * rsqrtf(var + 1e-6f) * scale[d];
    ysm[d] = y;
    __syncthreads();
    float rot = (d < 64) ? -ysm[d + 64] : ysm[d - 64];
    float r = fmaf(y, cosp[s * HD + d], rot * sinp[s * HD + d]);
    size_t o = ((size_t)h * S_LEN + s) * HD + d;
    kout[o] = r;
    __nv_bfloat16 hb = __float2bfloat16(r);
    __nv_bfloat16 lb = __float2bfloat16(r - __bfloat162float(hb));
    kh[o] = hb; kl[o] = lb;
}

// ---------------------------------------------------------------------------
// Tensor-core flash attention (bf16 3-term, unchanged from R5)
// ---------------------------------------------------------------------------
#define SQA      272
#define Q_BYTES  (128*SQA)
#define KV_TILE  (64*SQA)
#define ATT_SMEM (2*Q_BYTES + 2*4*KV_TILE)

__global__ __launch_bounds__(256) void attn_mma_kernel(
    const __nv_bfloat16* __restrict__ Qh, const __nv_bfloat16* __restrict__ Ql,
    const __nv_bfloat16* __restrict__ Kh, const __nv_bfloat16* __restrict__ Kl,
    const __nv_bfloat16* __restrict__ Vh, const __nv_bfloat16* __restrict__ Vl,
    __half* __restrict__ Cf)
{
    extern __shared__ __align__(128) char smem[];
    const uint32_t sb = smem_u32(smem);
    const int h  = blockIdx.y;
    const int g  = h >> 2;
    const int qt = gridDim.x - 1 - blockIdx.x;
    const int tid = threadIdx.x, wid = tid >> 5, lane = tid & 31;
    const int qbase = qt * 128;

    const uint32_t sQh = sb, sQl = sb + Q_BYTES;
    const uint32_t sKV0 = sb + 2 * Q_BYTES;

    {
        const __nv_bfloat16* bh = Qh + ((size_t)h * S_LEN + qbase) * HD;
        const __nv_bfloat16* bl = Ql + ((size_t)h * S_LEN + qbase) * HD;
        #pragma unroll
        for (int i = 0; i < 8; i++) {
            int c = tid + (i << 8);
            int r = c >> 4, ch = c & 15;
            cp16(sQh + r * SQA + ch * 16, bh + r * HD + ch * 8);
            cp16(sQl + r * SQA + ch * 16, bl + r * HD + ch * 8);
        }
    }
    auto load_kv = [&](int kt, int buf) {
        uint32_t base = sKV0 + buf * 4 * KV_TILE;
        const size_t gb = ((size_t)g * S_LEN + kt * 64) * HD;
        #pragma unroll
        for (int i = 0; i < 16; i++) {
            int c = tid + (i << 8);
            int arr = c >> 10, w = c & 1023, r = w >> 4, ch = w & 15;
            const __nv_bfloat16* src =
                (arr == 0 ? Kh : arr == 1 ? Kl : arr == 2 ? Vh : Vl) + gb + r * HD + ch * 8;
            cp16(base + arr * KV_TILE + r * SQA + ch * 16, src);
        }
    };
    load_kv(0, 0);
    cp_commit();

    float o[16][4];
    #pragma unroll
    for (int nj = 0; nj < 16; nj++)
        #pragma unroll
        for (int q = 0; q < 4; q++) o[nj][q] = 0.f;
    float mA = -1e30f, mB = -1e30f, lA = 0.f, lB = 0.f;

    const int rA = lane >> 2;
    const int colq = (lane & 3) * 2;
    const int ktmax = 2 * qt + 1;

    for (int kt = 0; kt <= ktmax; kt++) {
        if (kt < ktmax) { load_kv(kt + 1, (kt + 1) & 1); cp_commit(); cp_wait<1>(); }
        else            { cp_wait<0>(); }
        __syncthreads();

        const uint32_t bKh = sKV0 + (kt & 1) * 4 * KV_TILE;
        const uint32_t bKl = bKh + KV_TILE;
        const uint32_t bVh = bKh + 2 * KV_TILE;
        const uint32_t bVl = bKh + 3 * KV_TILE;

        float acc[8][4];
        #pragma unroll
        for (int ni = 0; ni < 8; ni++)
            #pragma unroll
            for (int q = 0; q < 4; q++) acc[ni][q] = 0.f;

        #pragma unroll
        for (int ks = 0; ks < 8; ks++) {
            uint32_t ah[4], al[4];
            {
                int row = wid * 16 + (lane & 15);
                uint32_t off = row * SQA + (ks * 2 + (lane >> 4)) * 16;
                LDSM4(ah, sQh + off);
                LDSM4(al, sQl + off);
            }
            #pragma unroll
            for (int nb = 0; nb < 4; nb++) {
                uint32_t bh[4], bl[4];
                int row = nb * 16 + (lane & 7) + ((lane >> 4) << 3);
                uint32_t off = row * SQA + (ks * 2 + ((lane >> 3) & 1)) * 16;
                LDSM4(bh, bKh + off);
                LDSM4(bl, bKl + off);
                MMA_BF16(acc[2*nb],   ah, bh[0], bh[1]);
                MMA_BF16(acc[2*nb],   ah, bl[0], bl[1]);
                MMA_BF16(acc[2*nb],   al, bh[0], bh[1]);
                MMA_BF16(acc[2*nb+1], ah, bh[2], bh[3]);
                MMA_BF16(acc[2*nb+1], ah, bl[2], bl[3]);
                MMA_BF16(acc[2*nb+1], al, bh[2], bh[3]);
            }
        }

        if (kt >= 2 * qt) {
            int qrA = qbase + wid * 16 + rA;
            #pragma unroll
            for (int ni = 0; ni < 8; ni++) {
                int key = kt * 64 + ni * 8 + colq;
                if (key     > qrA)     acc[ni][0] = -1e30f;
                if (key + 1 > qrA)     acc[ni][1] = -1e30f;
                if (key     > qrA + 8) acc[ni][2] = -1e30f;
                if (key + 1 > qrA + 8) acc[ni][3] = -1e30f;
            }
        }

        float mxA = -1e30f, mxB = -1e30f;
        #pragma unroll
        for (int ni = 0; ni < 8; ni++) {
            mxA = fmaxf(mxA, fmaxf(acc[ni][0], acc[ni][1]));
            mxB = fmaxf(mxB, fmaxf(acc[ni][2], acc[ni][3]));
        }
        mxA = fmaxf(mxA, __shfl_xor_sync(0xffffffffu, mxA, 1));
        mxA = fmaxf(mxA, __shfl_xor_sync(0xffffffffu, mxA, 2));
        mxB = fmaxf(mxB, __shfl_xor_sync(0xffffffffu, mxB, 1));
        mxB = fmaxf(mxB, __shfl_xor_sync(0xffffffffu, mxB, 2));
        float nmA = fmaxf(mA, mxA), nmB = fmaxf(mB, mxB);
        float aA = __expf(mA - nmA), aB = __expf(mB - nmB);
        mA = nmA; mB = nmB;
        float sA = 0.f, sB = 0.f;
        #pragma unroll
        for (int ni = 0; ni < 8; ni++) {
            acc[ni][0] = __expf(acc[ni][0] - nmA);
            acc[ni][1] = __expf(acc[ni][1] - nmA);
            acc[ni][2] = __expf(acc[ni][2] - nmB);
            acc[ni][3] = __expf(acc[ni][3] - nmB);
            sA += acc[ni][0] + acc[ni][1];
            sB += acc[ni][2] + acc[ni][3];
        }
        lA = lA * aA + sA;
        lB = lB * aB + sB;
        #pragma unroll
        for (int nj = 0; nj < 16; nj++) {
            o[nj][0] *= aA; o[nj][1] *= aA;
            o[nj][2] *= aB; o[nj][3] *= aB;
        }

        #pragma unroll
        for (int ks = 0; ks < 4; ks++) {
            uint32_t ph[4], pl[4];
            #pragma unroll
            for (int j = 0; j < 4; j++) {
                const float* pr = acc[2 * ks + (j >> 1)];
                float p0 = pr[(j & 1) ? 2 : 0];
                float p1 = pr[(j & 1) ? 3 : 1];
                float h0 = __bfloat162float(__float2bfloat16(p0));
                float h1 = __bfloat162float(__float2bfloat16(p1));
                ph[j] = pack_bf16x2(h0, h1);
                pl[j] = pack_bf16x2(p0 - h0, p1 - h1);
            }
            #pragma unroll
            for (int nj = 0; nj < 8; nj++) {
                uint32_t vh[4], vl[4];
                int row = ks * 16 + (lane & 7) + (((lane >> 3) & 1) << 3);
                uint32_t off = row * SQA + nj * 32 + (lane >> 4) * 16;
                LDSM4T(vh, bVh + off);
                LDSM4T(vl, bVl + off);
                MMA_BF16(o[2*nj],   ph, vh[0], vh[1]);
                MMA_BF16(o[2*nj],   ph, vl[0], vl[1]);
                MMA_BF16(o[2*nj],   pl, vh[0], vh[1]);
                MMA_BF16(o[2*nj+1], ph, vh[2], vh[3]);
                MMA_BF16(o[2*nj+1], ph, vl[2], vl[3]);
                MMA_BF16(o[2*nj+1], pl, vh[2], vh[3]);
            }
        }
        __syncthreads();
    }

    float lAt = lA + __shfl_xor_sync(0xffffffffu, lA, 1);
    lAt += __shfl_xor_sync(0xffffffffu, lAt, 2);
    float lBt = lB + __shfl_xor_sync(0xffffffffu, lB, 1);
    lBt += __shfl_xor_sync(0xffffffffu, lBt, 2);
    float invA = 1.f / lAt, invB = 1.f / lBt;

    const int rowA = qbase + wid * 16 + rA;
    uint32_t* C32 = (uint32_t*)Cf;
    #pragma unroll
    for (int nj = 0; nj < 16; nj++) {
        int col = h * HD + nj * 8 + colq;
        float v0 = o[nj][0] * invA, v1 = o[nj][1] * invA;
        float v2 = o[nj][2] * invB, v3 = o[nj][3] * invB;
        C32[(size_t)rowA * (DOUT/2) + (col >> 1)]       = pack_f16x2(v0, v1);
        C32[(size_t)(rowA + 8) * (DOUT/2) + (col >> 1)] = pack_f16x2(v2, v3);
    }
}

// ---------------------------------------------------------------------------
extern "C" void kernel_launch(void* const* d_in, const int* in_sizes, int n_in,
                              void* d_out, int out_size)
{
    const float* x    = (const float*)d_in[0];
    const float* cosp = (const float*)d_in[2];
    const float* sinp = (const float*)d_in[3];
    const float* Wq   = (const float*)d_in[4];
    const float* Wk   = (const float*)d_in[5];
    const float* Wv   = (const float*)d_in[6];
    const float* Wo   = (const float*)d_in[7];
    const float* qsc  = (const float*)d_in[8];
    const float* ksc  = (const float*)d_in[9];

    float* out  = (float*)d_out;
    float* kout = out  + (size_t)S_LEN * DIN;
    float* vout = kout + (size_t)G_KV * S_LEN * HD;

    float *gq, *gk;
    __half *xf, *cf, *wqh, *wql, *wkh, *wkl, *wvh, *wvl, *woh, *wol;
    __nv_bfloat16 *qh, *ql, *kh, *kl, *vh, *vl;
    cudaGetSymbolAddress((void**)&gq,  g_q);
    cudaGetSymbolAddress((void**)&gk,  g_k);
    cudaGetSymbolAddress((void**)&xf,  g_xf16);
    cudaGetSymbolAddress((void**)&cf,  g_cf16);
    cudaGetSymbolAddress((void**)&wqh, g_wqt_hi);
    cudaGetSymbolAddress((void**)&wql, g_wqt_lo);
    cudaGetSymbolAddress((void**)&wkh, g_wkt_hi);
    cudaGetSymbolAddress((void**)&wkl, g_wkt_lo);
    cudaGetSymbolAddress((void**)&wvh, g_wvt_hi);
    cudaGetSymbolAddress((void**)&wvl, g_wvt_lo);
    cudaGetSymbolAddress((void**)&woh, g_wot_hi);
    cudaGetSymbolAddress((void**)&wol, g_wot_lo);
    cudaGetSymbolAddress((void**)&qh,  g_qh);
    cudaGetSymbolAddress((void**)&ql,  g_ql);
    cudaGetSymbolAddress((void**)&kh,  g_kh);
    cudaGetSymbolAddress((void**)&kl,  g_kl);
    cudaGetSymbolAddress((void**)&vh,  g_vh);
    cudaGetSymbolAddress((void**)&vl,  g_vl);

    cudaFuncSetAttribute(gemm_qkv_kernel, cudaFuncAttributeMaxDynamicSharedMemorySize, GEMM_SMEM);
    cudaFuncSetAttribute(gemm_wo_kernel,  cudaFuncAttributeMaxDynamicSharedMemorySize, GEMM_SMEM);
    cudaFuncSetAttribute(attn_mma_kernel, cudaFuncAttributeMaxDynamicSharedMemorySize, ATT_SMEM);

    dim3 tb(32, 8);

    {
        int n4 = S_LEN * DIN / 4;
        split_f16_kernel<<<(n4 + 255) / 256, 256>>>((const float4*)x, (ushort4*)xf, n4);
    }
    transpose_split_kernel<<<dim3(DOUT/32, DIN/32),  tb>>>(Wq, wqh, wql, DIN,  DOUT);
    transpose_split_kernel<<<dim3(GKD /32, DIN/32),  tb>>>(Wk, wkh, wkl, DIN,  GKD);
    transpose_split_kernel<<<dim3(GKD /32, DIN/32),  tb>>>(Wv, wvh, wvl, DIN,  GKD);
    transpose_split_kernel<<<dim3(DIN /32, DOUT/32), tb>>>(Wo, woh, wol, DOUT, DIN);

    // merged Q/K/V projections (V emits fp32 + fused bf16 hi/lo)
    gemm_qkv_kernel<<<dim3(QKV_N/128, S_LEN/128), 256, GEMM_SMEM>>>(
        xf, wqh, wql, wkh, wkl, wvh, wvl, gq, gk, vout, vh, vl);

    norm_rope_q_kernel<<<dim3(S_LEN, H_Q),  128>>>(gq, qsc, cosp, sinp, qh, ql);
    norm_rope_k_kernel<<<dim3(S_LEN, G_KV), 128>>>(gk, ksc, cosp, sinp, kout, kh, kl);

    attn_mma_kernel<<<dim3(S_LEN/128, H_Q), 256, ATT_SMEM>>>(qh, ql, kh, kl, vh, vl, cf);

    gemm_wo_kernel<<<dim3(DIN/128, S_LEN/128), 256, GEMM_SMEM>>>(cf, woh, wol, out, DIN, DOUT);
}

// round 7
// speedup vs baseline: 5.5574x; 1.0624x over previous
#include <cuda_runtime.h>
#include <cuda_bf16.h>
#include <cuda_fp16.h>
#include <math.h>
#include <stdint.h>

#define S_LEN 2048
#define DIN   2048
#define H_Q   32
#define G_KV  8
#define HD    128
#define DOUT  (H_Q*HD)   /* 4096 */
#define GKD   (G_KV*HD)  /* 1024 */
#define QKV_N (DOUT + 2*GKD)  /* 6144 */

// ---------------- scratch (__device__ globals; no runtime alloc) ------------
__device__ float g_q  [S_LEN * (size_t)DOUT];
__device__ float g_k  [S_LEN * (size_t)GKD];

__device__ __half g_xf16 [S_LEN * (size_t)DIN];
__device__ __half g_cf16 [S_LEN * (size_t)DOUT];
__device__ __half g_wqt_hi[(size_t)DOUT * DIN];
__device__ __half g_wqt_lo[(size_t)DOUT * DIN];
__device__ __half g_wkt_hi[(size_t)GKD  * DIN];
__device__ __half g_wkt_lo[(size_t)GKD  * DIN];
__device__ __half g_wvt_hi[(size_t)GKD  * DIN];
__device__ __half g_wvt_lo[(size_t)GKD  * DIN];
__device__ __half g_wot_hi[(size_t)DIN  * DOUT];
__device__ __half g_wot_lo[(size_t)DIN  * DOUT];

// attention operands (fp16: Q single, K/V hi/lo)
__device__ __half g_qf [(size_t)H_Q * S_LEN * HD];
__device__ __half g_kh [(size_t)G_KV * S_LEN * HD];
__device__ __half g_kl [(size_t)G_KV * S_LEN * HD];
__device__ __half g_vh [(size_t)G_KV * S_LEN * HD];
__device__ __half g_vl [(size_t)G_KV * S_LEN * HD];

// ---------------------------- PTX helpers (compute_103-safe) ---------------
__device__ __forceinline__ uint32_t smem_u32(const void* p) {
    uint32_t a;
    asm("{ .reg .u64 t; cvta.to.shared.u64 t, %1; cvt.u32.u64 %0, t; }" : "=r"(a) : "l"(p));
    return a;
}
__device__ __forceinline__ void cp16(uint32_t dst, const void* src) {
    asm volatile("cp.async.cg.shared.global [%0], [%1], 16;\n"
                 :: "r"(dst), "l"(__cvta_generic_to_global(src)));
}
__device__ __forceinline__ void cp_commit() {
    asm volatile("cp.async.commit_group;" ::: "memory");
}
template<int N> __device__ __forceinline__ void cp_wait() {
    asm volatile("cp.async.wait_group %0;" :: "n"(N) : "memory");
}
#define LDSM4(r, addr) \
    asm volatile("ldmatrix.sync.aligned.m8n8.x4.shared.b16 {%0,%1,%2,%3}, [%4];" \
        : "=r"((r)[0]), "=r"((r)[1]), "=r"((r)[2]), "=r"((r)[3]) : "r"(addr))
#define LDSM4T(r, addr) \
    asm volatile("ldmatrix.sync.aligned.m8n8.x4.trans.shared.b16 {%0,%1,%2,%3}, [%4];" \
        : "=r"((r)[0]), "=r"((r)[1]), "=r"((r)[2]), "=r"((r)[3]) : "r"(addr))
#define MMA_F16(d, a, b0, b1) \
    asm volatile("mma.sync.aligned.m16n8k16.row.col.f32.f16.f16.f32 " \
        "{%0,%1,%2,%3}, {%4,%5,%6,%7}, {%8,%9}, {%0,%1,%2,%3};" \
        : "+f"((d)[0]), "+f"((d)[1]), "+f"((d)[2]), "+f"((d)[3]) \
        : "r"((a)[0]), "r"((a)[1]), "r"((a)[2]), "r"((a)[3]), "r"(b0), "r"(b1))

__device__ __forceinline__ uint32_t pack_f16x2(float lo, float hi) {
    uint32_t r;
    asm("cvt.rn.f16x2.f32 %0, %1, %2;" : "=r"(r) : "f"(hi), "f"(lo));
    return r;
}

// ---------------------------------------------------------------------------
// fp16 2-term GEMM core (tile 128x128x32, 256 thr, warp tile 64x32,
// 3-stage cp.async ring, one __syncthreads per K-stage).
// ---------------------------------------------------------------------------
#define TILE_B   10240             /* 128 rows * 80 B */
#define STAGE_B  (3*TILE_B)        /* A, Bh, Bl */
#define GEMM_SMEM (3*STAGE_B)      /* 92160 */

#define GEMM_MAINLOOP(Aptr, BhiPtr, BloPtr, Kdim, m0v, n0v)                         \
    float acc[4][4][4];                                                             \
    _Pragma("unroll")                                                               \
    for (int mi = 0; mi < 4; mi++)                                                  \
        _Pragma("unroll")                                                           \
        for (int ni = 0; ni < 4; ni++)                                              \
            _Pragma("unroll")                                                       \
            for (int q = 0; q < 4; q++) acc[mi][ni][q] = 0.f;                       \
    auto load_stage = [&](int k0, int buf) {                                        \
        uint32_t base = sb + buf * STAGE_B;                                         \
        _Pragma("unroll")                                                           \
        for (int i = 0; i < 6; i++) {                                               \
            int c = tid + (i << 8);                                                 \
            int tile = c >> 9, w = c & 511, row = w >> 2, ch = w & 3;               \
            const __half* gp;                                                       \
            if (tile == 0)      gp = (Aptr)   + (size_t)((m0v) + row) * (Kdim) + k0 + (ch << 3); \
            else if (tile == 1) gp = (BhiPtr) + (size_t)row * (Kdim) + k0 + (ch << 3); \
            else                gp = (BloPtr) + (size_t)row * (Kdim) + k0 + (ch << 3); \
            cp16(base + tile * TILE_B + row * 80 + (ch << 4), gp);                  \
        }                                                                           \
        cp_commit();                                                                \
    };                                                                              \
    auto compute_stage = [&](int buf) {                                             \
        uint32_t base = sb + buf * STAGE_B;                                         \
        uint32_t sA = base, sBh = base + TILE_B, sBl = base + 2*TILE_B;             \
        _Pragma("unroll")                                                           \
        for (int kk = 0; kk < 2; kk++) {                                            \
            const int kb = kk * 2;                                                  \
            uint32_t a[4][4], bh[2][4], bl[2][4];                                   \
            _Pragma("unroll")                                                       \
            for (int mi = 0; mi < 4; mi++) {                                        \
                int row = warp_m * 64 + mi * 16 + (lane & 15);                      \
                LDSM4(a[mi], sA + row * 80 + (kb + (lane >> 4)) * 16);              \
            }                                                                       \
            _Pragma("unroll")                                                       \
            for (int bi = 0; bi < 2; bi++) {                                        \
                int row = warp_n * 32 + bi * 16 + (lane & 7) + ((lane >> 4) << 3);  \
                uint32_t off = row * 80 + (kb + ((lane >> 3) & 1)) * 16;            \
                LDSM4(bh[bi], sBh + off);                                           \
                LDSM4(bl[bi], sBl + off);                                           \
            }                                                                       \
            _Pragma("unroll")                                                       \
            for (int mi = 0; mi < 4; mi++)                                          \
                _Pragma("unroll")                                                   \
                for (int ni = 0; ni < 4; ni++) {                                    \
                    uint32_t* Bh = &bh[ni >> 1][(ni & 1) * 2];                      \
                    uint32_t* Bl = &bl[ni >> 1][(ni & 1) * 2];                      \
                    MMA_F16(acc[mi][ni], a[mi], Bh[0], Bh[1]);                      \
                    MMA_F16(acc[mi][ni], a[mi], Bl[0], Bl[1]);                      \
                }                                                                   \
        }                                                                           \
    };                                                                              \
    const int NS = (Kdim) >> 5;                                                     \
    load_stage(0, 0);                                                               \
    load_stage(32, 1);                                                              \
    for (int t = 0; t < NS; t++) {                                                  \
        if (t + 1 < NS) cp_wait<1>(); else cp_wait<0>();                            \
        __syncthreads();                                                            \
        compute_stage(t % 3);                                                       \
        if (t + 2 < NS) load_stage((t + 2) << 5, (t + 2) % 3);                      \
    }

// ---- merged QKV projection: N = 6144 segments [Q:4096 | K:1024 | V:1024] ----
__global__ __launch_bounds__(256, 2) void gemm_qkv_kernel(
    const __half* __restrict__ A,
    const __half* __restrict__ WqH, const __half* __restrict__ WqL,
    const __half* __restrict__ WkH, const __half* __restrict__ WkL,
    const __half* __restrict__ WvH, const __half* __restrict__ WvL,
    float* __restrict__ Cq, float* __restrict__ Ck, float* __restrict__ Cv,
    __half* __restrict__ Vh, __half* __restrict__ Vl)
{
    extern __shared__ __align__(128) char smem[];
    const uint32_t sb = smem_u32(smem);
    const int tid  = threadIdx.x;
    const int wid  = tid >> 5;
    const int lane = tid & 31;
    const int warp_m = wid >> 2;
    const int warp_n = wid & 3;
    const int m0 = blockIdx.y * 128;
    const int n0g = blockIdx.x * 128;

    int seg, nloc;
    const __half *Bhi, *Blo;
    if (n0g < DOUT)            { seg = 0; nloc = n0g;
                                 Bhi = WqH + (size_t)nloc * DIN; Blo = WqL + (size_t)nloc * DIN; }
    else if (n0g < DOUT + GKD) { seg = 1; nloc = n0g - DOUT;
                                 Bhi = WkH + (size_t)nloc * DIN; Blo = WkL + (size_t)nloc * DIN; }
    else                       { seg = 2; nloc = n0g - DOUT - GKD;
                                 Bhi = WvH + (size_t)nloc * DIN; Blo = WvL + (size_t)nloc * DIN; }

    GEMM_MAINLOOP(A, Bhi, Blo, DIN, m0, n0g)

    #pragma unroll
    for (int mi = 0; mi < 4; mi++) {
        #pragma unroll
        for (int ni = 0; ni < 4; ni++) {
            int r0 = m0 + warp_m * 64 + mi * 16 + (lane >> 2);
            int cl = nloc + warp_n * 32 + ni * 8 + (lane & 3) * 2;
            float2 v01 = make_float2(acc[mi][ni][0], acc[mi][ni][1]);
            float2 v23 = make_float2(acc[mi][ni][2], acc[mi][ni][3]);
            if (seg == 0) {
                *(float2*)(Cq + (size_t)r0 * DOUT + cl)       = v01;
                *(float2*)(Cq + (size_t)(r0 + 8) * DOUT + cl) = v23;
            } else if (seg == 1) {
                *(float2*)(Ck + (size_t)r0 * GKD + cl)       = v01;
                *(float2*)(Ck + (size_t)(r0 + 8) * GKD + cl) = v23;
            } else {
                size_t gb = (size_t)(cl >> 7) * S_LEN * HD;
                int cc = cl & 127;
                size_t iA = gb + (size_t)r0 * HD + cc;
                size_t iB = gb + (size_t)(r0 + 8) * HD + cc;
                *(float2*)(Cv + iA) = v01;
                *(float2*)(Cv + iB) = v23;
                // fused fp16 hi/lo split for attention V
                float h0 = __half2float(__float2half_rn(v01.x));
                float h1 = __half2float(__float2half_rn(v01.y));
                float h2 = __half2float(__float2half_rn(v23.x));
                float h3 = __half2float(__float2half_rn(v23.y));
                ((uint32_t*)Vh)[iA >> 1] = pack_f16x2(h0, h1);
                ((uint32_t*)Vl)[iA >> 1] = pack_f16x2(v01.x - h0, v01.y - h1);
                ((uint32_t*)Vh)[iB >> 1] = pack_f16x2(h2, h3);
                ((uint32_t*)Vl)[iB >> 1] = pack_f16x2(v23.x - h2, v23.y - h3);
            }
        }
    }
}

// ---- Wo GEMM ----
__global__ __launch_bounds__(256, 2) void gemm_wo_kernel(
    const __half* __restrict__ A,
    const __half* __restrict__ BhiP, const __half* __restrict__ BloP,
    float* __restrict__ C, int N, int K)
{
    extern __shared__ __align__(128) char smem[];
    const uint32_t sb = smem_u32(smem);
    const int tid  = threadIdx.x;
    const int wid  = tid >> 5;
    const int lane = tid & 31;
    const int warp_m = wid >> 2;
    const int warp_n = wid & 3;
    const int m0 = blockIdx.y * 128;
    const int n0 = blockIdx.x * 128;
    const __half* Bhi = BhiP + (size_t)n0 * K;
    const __half* Blo = BloP + (size_t)n0 * K;

    GEMM_MAINLOOP(A, Bhi, Blo, K, m0, n0)

    #pragma unroll
    for (int mi = 0; mi < 4; mi++) {
        #pragma unroll
        for (int ni = 0; ni < 4; ni++) {
            int r0 = m0 + warp_m * 64 + mi * 16 + (lane >> 2);
            int c0 = n0 + warp_n * 32 + ni * 8 + (lane & 3) * 2;
            *(float2*)(C + (size_t)r0 * N + c0)       = make_float2(acc[mi][ni][0], acc[mi][ni][1]);
            *(float2*)(C + (size_t)(r0 + 8) * N + c0) = make_float2(acc[mi][ni][2], acc[mi][ni][3]);
        }
    }
}

// ------------------------- conversion kernels ------------------------------
__global__ __launch_bounds__(256) void split_f16_kernel(
    const float4* __restrict__ in, ushort4* __restrict__ o16, int n4)
{
    int i = blockIdx.x * 256 + threadIdx.x;
    if (i >= n4) return;
    float4 v = in[i];
    o16[i] = make_ushort4(__half_as_ushort(__float2half_rn(v.x)),
                          __half_as_ushort(__float2half_rn(v.y)),
                          __half_as_ushort(__float2half_rn(v.z)),
                          __half_as_ushort(__float2half_rn(v.w)));
}

__global__ __launch_bounds__(256) void transpose_split_kernel(
    const float* __restrict__ W, __half* __restrict__ Thi,
    __half* __restrict__ Tlo, int K, int N)
{
    __shared__ float t[32][33];
    const int bn = blockIdx.x * 32, bk = blockIdx.y * 32;
    const int tx = threadIdx.x, ty = threadIdx.y;
    #pragma unroll
    for (int j = 0; j < 32; j += 8)
        t[ty + j][tx] = W[(size_t)(bk + ty + j) * N + bn + tx];
    __syncthreads();
    #pragma unroll
    for (int j = 0; j < 32; j += 8) {
        float v = t[tx][ty + j];
        __half h = __float2half_rn(v);
        __half l = __float2half_rn(v - __half2float(h));
        size_t o = (size_t)(bn + ty + j) * K + bk + tx;
        Thi[o] = h; Tlo[o] = l;
    }
}

// ------------------------- RMSNorm + RoPE variants -------------------------
// Q: fp32 [S,H,HD] -> single fp16 [H,S,HD], pre-scaled by 1/sqrt(HD)
__global__ __launch_bounds__(128) void norm_rope_q_kernel(
    const float* __restrict__ in, const float* __restrict__ scale,
    const float* __restrict__ cosp, const float* __restrict__ sinp,
    __half* __restrict__ qf)
{
    const int s = blockIdx.x, h = blockIdx.y, d = threadIdx.x;
    const size_t base = ((size_t)s * H_Q + h) * HD;
    float x = in[base + d];
    float v = x * x;
    #pragma unroll
    for (int off = 16; off; off >>= 1) v += __shfl_xor_sync(0xffffffffu, v, off);
    __shared__ float ws[4];
    __shared__ float ysm[HD];
    if ((d & 31) == 0) ws[d >> 5] = v;
    __syncthreads();
    float var = (ws[0] + ws[1] + ws[2] + ws[3]) * (1.0f / HD);
    float y = x * rsqrtf(var + 1e-6f) * scale[d];
    ysm[d] = y;
    __syncthreads();
    float rot = (d < 64) ? -ysm[d + 64] : ysm[d - 64];
    float r = fmaf(y, cosp[s * HD + d], rot * sinp[s * HD + d]) * 0.088388347648318447f;
    qf[((size_t)h * S_LEN + s) * HD + d] = __float2half_rn(r);
}

// K: fp32 [S,G,HD] -> fp32 [G,S,HD] (d_out) + fp16 hi/lo [G,S,HD]
__global__ __launch_bounds__(128) void norm_rope_k_kernel(
    const float* __restrict__ in, const float* __restrict__ scale,
    const float* __restrict__ cosp, const float* __restrict__ sinp,
    float* __restrict__ kout, __half* __restrict__ kh, __half* __restrict__ kl)
{
    const int s = blockIdx.x, h = blockIdx.y, d = threadIdx.x;
    const size_t base = ((size_t)s * G_KV + h) * HD;
    float x = in[base + d];
    float v = x * x;
    #pragma unroll
    for (int off = 16; off; off >>= 1) v += __shfl_xor_sync(0xffffffffu, v, off);
    __shared__ float ws[4];
    __shared__ float ysm[HD];
    if ((d & 31) == 0) ws[d >> 5] = v;
    __syncthreads();
    float var = (ws[0] + ws[1] + ws[2] + ws[3]) * (1.0f / HD);
    float y = x * rsqrtf(var + 1e-6f) * scale[d];
    ysm[d] = y;
    __syncthreads();
    float rot = (d < 64) ? -ysm[d + 64] : ysm[d - 64];
    float r = fmaf(y, cosp[s * HD + d], rot * sinp[s * HD + d]);
    size_t o = ((size_t)h * S_LEN + s) * HD + d;
    kout[o] = r;
    __half hb = __float2half_rn(r);
    kh[o] = hb;
    kl[o] = __float2half_rn(r - __half2float(hb));
}

// ---------------------------------------------------------------------------
// Tensor-core flash attention, fp16 2-term (Q single x (Kh+Kl);
// P single x (Vh+Vl)), fp32 softmax.
// ---------------------------------------------------------------------------
#define SQA      272
#define Q_BYTES  (128*SQA)
#define KV_TILE  (64*SQA)
#define ATT_SMEM (Q_BYTES + 2*4*KV_TILE)   /* 174080 */

__global__ __launch_bounds__(256) void attn_mma_kernel(
    const __half* __restrict__ Qf,
    const __half* __restrict__ Kh, const __half* __restrict__ Kl,
    const __half* __restrict__ Vh, const __half* __restrict__ Vl,
    __half* __restrict__ Cf)
{
    extern __shared__ __align__(128) char smem[];
    const uint32_t sb = smem_u32(smem);
    const int h  = blockIdx.y;
    const int g  = h >> 2;
    const int qt = gridDim.x - 1 - blockIdx.x;
    const int tid = threadIdx.x, wid = tid >> 5, lane = tid & 31;
    const int qbase = qt * 128;

    const uint32_t sQf = sb;
    const uint32_t sKV0 = sb + Q_BYTES;

    {
        const __half* bq = Qf + ((size_t)h * S_LEN + qbase) * HD;
        #pragma unroll
        for (int i = 0; i < 8; i++) {
            int c = tid + (i << 8);
            int r = c >> 4, ch = c & 15;
            cp16(sQf + r * SQA + ch * 16, bq + r * HD + ch * 8);
        }
    }
    auto load_kv = [&](int kt, int buf) {
        uint32_t base = sKV0 + buf * 4 * KV_TILE;
        const size_t gb = ((size_t)g * S_LEN + kt * 64) * HD;
        #pragma unroll
        for (int i = 0; i < 16; i++) {
            int c = tid + (i << 8);
            int arr = c >> 10, w = c & 1023, r = w >> 4, ch = w & 15;
            const __half* src =
                (arr == 0 ? Kh : arr == 1 ? Kl : arr == 2 ? Vh : Vl) + gb + r * HD + ch * 8;
            cp16(base + arr * KV_TILE + r * SQA + ch * 16, src);
        }
    };
    load_kv(0, 0);
    cp_commit();

    float o[16][4];
    #pragma unroll
    for (int nj = 0; nj < 16; nj++)
        #pragma unroll
        for (int q = 0; q < 4; q++) o[nj][q] = 0.f;
    float mA = -1e30f, mB = -1e30f, lA = 0.f, lB = 0.f;

    const int rA = lane >> 2;
    const int colq = (lane & 3) * 2;
    const int ktmax = 2 * qt + 1;

    for (int kt = 0; kt <= ktmax; kt++) {
        if (kt < ktmax) { load_kv(kt + 1, (kt + 1) & 1); cp_commit(); cp_wait<1>(); }
        else            { cp_wait<0>(); }
        __syncthreads();

        const uint32_t bKh = sKV0 + (kt & 1) * 4 * KV_TILE;
        const uint32_t bKl = bKh + KV_TILE;
        const uint32_t bVh = bKh + 2 * KV_TILE;
        const uint32_t bVl = bKh + 3 * KV_TILE;

        float acc[8][4];
        #pragma unroll
        for (int ni = 0; ni < 8; ni++)
            #pragma unroll
            for (int q = 0; q < 4; q++) acc[ni][q] = 0.f;

        // ---- QK^T: Qf x (Kh + Kl) ----
        #pragma unroll
        for (int ks = 0; ks < 8; ks++) {
            uint32_t a[4];
            {
                int row = wid * 16 + (lane & 15);
                LDSM4(a, sQf + row * SQA + (ks * 2 + (lane >> 4)) * 16);
            }
            #pragma unroll
            for (int nb = 0; nb < 4; nb++) {
                uint32_t bh[4], bl[4];
                int row = nb * 16 + (lane & 7) + ((lane >> 4) << 3);
                uint32_t off = row * SQA + (ks * 2 + ((lane >> 3) & 1)) * 16;
                LDSM4(bh, bKh + off);
                LDSM4(bl, bKl + off);
                MMA_F16(acc[2*nb],   a, bh[0], bh[1]);
                MMA_F16(acc[2*nb],   a, bl[0], bl[1]);
                MMA_F16(acc[2*nb+1], a, bh[2], bh[3]);
                MMA_F16(acc[2*nb+1], a, bl[2], bl[3]);
            }
        }

        if (kt >= 2 * qt) {
            int qrA = qbase + wid * 16 + rA;
            #pragma unroll
            for (int ni = 0; ni < 8; ni++) {
                int key = kt * 64 + ni * 8 + colq;
                if (key     > qrA)     acc[ni][0] = -1e30f;
                if (key + 1 > qrA)     acc[ni][1] = -1e30f;
                if (key     > qrA + 8) acc[ni][2] = -1e30f;
                if (key + 1 > qrA + 8) acc[ni][3] = -1e30f;
            }
        }

        float mxA = -1e30f, mxB = -1e30f;
        #pragma unroll
        for (int ni = 0; ni < 8; ni++) {
            mxA = fmaxf(mxA, fmaxf(acc[ni][0], acc[ni][1]));
            mxB = fmaxf(mxB, fmaxf(acc[ni][2], acc[ni][3]));
        }
        mxA = fmaxf(mxA, __shfl_xor_sync(0xffffffffu, mxA, 1));
        mxA = fmaxf(mxA, __shfl_xor_sync(0xffffffffu, mxA, 2));
        mxB = fmaxf(mxB, __shfl_xor_sync(0xffffffffu, mxB, 1));
        mxB = fmaxf(mxB, __shfl_xor_sync(0xffffffffu, mxB, 2));
        float nmA = fmaxf(mA, mxA), nmB = fmaxf(mB, mxB);
        float aA = __expf(mA - nmA), aB = __expf(mB - nmB);
        mA = nmA; mB = nmB;
        float sA = 0.f, sB = 0.f;
        #pragma unroll
        for (int ni = 0; ni < 8; ni++) {
            acc[ni][0] = __expf(acc[ni][0] - nmA);
            acc[ni][1] = __expf(acc[ni][1] - nmA);
            acc[ni][2] = __expf(acc[ni][2] - nmB);
            acc[ni][3] = __expf(acc[ni][3] - nmB);
            sA += acc[ni][0] + acc[ni][1];
            sB += acc[ni][2] + acc[ni][3];
        }
        lA = lA * aA + sA;
        lB = lB * aB + sB;
        #pragma unroll
        for (int nj = 0; nj < 16; nj++) {
            o[nj][0] *= aA; o[nj][1] *= aA;
            o[nj][2] *= aB; o[nj][3] *= aB;
        }

        // ---- PV: P (single fp16) x (Vh + Vl) ----
        #pragma unroll
        for (int ks = 0; ks < 4; ks++) {
            uint32_t p[4];
            #pragma unroll
            for (int j = 0; j < 4; j++) {
                const float* pr = acc[2 * ks + (j >> 1)];
                p[j] = pack_f16x2(pr[(j & 1) ? 2 : 0], pr[(j & 1) ? 3 : 1]);
            }
            #pragma unroll
            for (int nj = 0; nj < 8; nj++) {
                uint32_t vh[4], vl[4];
                int row = ks * 16 + (lane & 7) + (((lane >> 3) & 1) << 3);
                uint32_t off = row * SQA + nj * 32 + (lane >> 4) * 16;
                LDSM4T(vh, bVh + off);
                LDSM4T(vl, bVl + off);
                MMA_F16(o[2*nj],   p, vh[0], vh[1]);
                MMA_F16(o[2*nj],   p, vl[0], vl[1]);
                MMA_F16(o[2*nj+1], p, vh[2], vh[3]);
                MMA_F16(o[2*nj+1], p, vl[2], vl[3]);
            }
        }
        __syncthreads();
    }

    float lAt = lA + __shfl_xor_sync(0xffffffffu, lA, 1);
    lAt += __shfl_xor_sync(0xffffffffu, lAt, 2);
    float lBt = lB + __shfl_xor_sync(0xffffffffu, lB, 1);
    lBt += __shfl_xor_sync(0xffffffffu, lBt, 2);
    float invA = 1.f / lAt, invB = 1.f / lBt;

    const int rowA = qbase + wid * 16 + rA;
    uint32_t* C32 = (uint32_t*)Cf;
    #pragma unroll
    for (int nj = 0; nj < 16; nj++) {
        int col = h * HD + nj * 8 + colq;
        float v0 = o[nj][0] * invA, v1 = o[nj][1] * invA;
        float v2 = o[nj][2] * invB, v3 = o[nj][3] * invB;
        C32[(size_t)rowA * (DOUT/2) + (col >> 1)]       = pack_f16x2(v0, v1);
        C32[(size_t)(rowA + 8) * (DOUT/2) + (col >> 1)] = pack_f16x2(v2, v3);
    }
}

// ---------------------------------------------------------------------------
extern "C" void kernel_launch(void* const* d_in, const int* in_sizes, int n_in,
                              void* d_out, int out_size)
{
    const float* x    = (const float*)d_in[0];
    const float* cosp = (const float*)d_in[2];
    const float* sinp = (const float*)d_in[3];
    const float* Wq   = (const float*)d_in[4];
    const float* Wk   = (const float*)d_in[5];
    const float* Wv   = (const float*)d_in[6];
    const float* Wo   = (const float*)d_in[7];
    const float* qsc  = (const float*)d_in[8];
    const float* ksc  = (const float*)d_in[9];

    float* out  = (float*)d_out;
    float* kout = out  + (size_t)S_LEN * DIN;
    float* vout = kout + (size_t)G_KV * S_LEN * HD;

    float *gq, *gk;
    __half *xf, *cf, *wqh, *wql, *wkh, *wkl, *wvh, *wvl, *woh, *wol;
    __half *qf, *kh, *kl, *vh, *vl;
    cudaGetSymbolAddress((void**)&gq,  g_q);
    cudaGetSymbolAddress((void**)&gk,  g_k);
    cudaGetSymbolAddress((void**)&xf,  g_xf16);
    cudaGetSymbolAddress((void**)&cf,  g_cf16);
    cudaGetSymbolAddress((void**)&wqh, g_wqt_hi);
    cudaGetSymbolAddress((void**)&wql, g_wqt_lo);
    cudaGetSymbolAddress((void**)&wkh, g_wkt_hi);
    cudaGetSymbolAddress((void**)&wkl, g_wkt_lo);
    cudaGetSymbolAddress((void**)&wvh, g_wvt_hi);
    cudaGetSymbolAddress((void**)&wvl, g_wvt_lo);
    cudaGetSymbolAddress((void**)&woh, g_wot_hi);
    cudaGetSymbolAddress((void**)&wol, g_wot_lo);
    cudaGetSymbolAddress((void**)&qf,  g_qf);
    cudaGetSymbolAddress((void**)&kh,  g_kh);
    cudaGetSymbolAddress((void**)&kl,  g_kl);
    cudaGetSymbolAddress((void**)&vh,  g_vh);
    cudaGetSymbolAddress((void**)&vl,  g_vl);

    cudaFuncSetAttribute(gemm_qkv_kernel, cudaFuncAttributeMaxDynamicSharedMemorySize, GEMM_SMEM);
    cudaFuncSetAttribute(gemm_wo_kernel,  cudaFuncAttributeMaxDynamicSharedMemorySize, GEMM_SMEM);
    cudaFuncSetAttribute(attn_mma_kernel, cudaFuncAttributeMaxDynamicSharedMemorySize, ATT_SMEM);

    dim3 tb(32, 8);

    {
        int n4 = S_LEN * DIN / 4;
        split_f16_kernel<<<(n4 + 255) / 256, 256>>>((const float4*)x, (ushort4*)xf, n4);
    }
    transpose_split_kernel<<<dim3(DOUT/32, DIN/32),  tb>>>(Wq, wqh, wql, DIN,  DOUT);
    transpose_split_kernel<<<dim3(GKD /32, DIN/32),  tb>>>(Wk, wkh, wkl, DIN,  GKD);
    transpose_split_kernel<<<dim3(GKD /32, DIN/32),  tb>>>(Wv, wvh, wvl, DIN,  GKD);
    transpose_split_kernel<<<dim3(DIN /32, DOUT/32), tb>>>(Wo, woh, wol, DOUT, DIN);

    gemm_qkv_kernel<<<dim3(QKV_N/128, S_LEN/128), 256, GEMM_SMEM>>>(
        xf, wqh, wql, wkh, wkl, wvh, wvl, gq, gk, vout, vh, vl);

    norm_rope_q_kernel<<<dim3(S_LEN, H_Q),  128>>>(gq, qsc, cosp, sinp, qf);
    norm_rope_k_kernel<<<dim3(S_LEN, G_KV), 128>>>(gk, ksc, cosp, sinp, kout, kh, kl);

    attn_mma_kernel<<<dim3(S_LEN/128, H_Q), 256, ATT_SMEM>>>(qf, kh, kl, vh, vl, cf);

    gemm_wo_kernel<<<dim3(DIN/128, S_LEN/128), 256, GEMM_SMEM>>>(cf, woh, wol, out, DIN, DOUT);
}

// round 8
// speedup vs baseline: 7.2522x; 1.3050x over previous
#include <cuda_runtime.h>
#include <cuda_bf16.h>
#include <cuda_fp16.h>
#include <math.h>
#include <stdint.h>

#define S_LEN 2048
#define DIN   2048
#define H_Q   32
#define G_KV  8
#define HD    128
#define DOUT  (H_Q*HD)   /* 4096 */
#define GKD   (G_KV*HD)  /* 1024 */
#define QKV_N (DOUT + 2*GKD)  /* 6144 */

// ---------------- scratch (__device__ globals; no runtime alloc) ------------
__device__ float g_q  [S_LEN * (size_t)DOUT];
__device__ float g_k  [S_LEN * (size_t)GKD];

__device__ __half g_xf16 [S_LEN * (size_t)DIN];
__device__ __half g_cf16 [S_LEN * (size_t)DOUT];
__device__ __half g_wqt [(size_t)DOUT * DIN];
__device__ __half g_wkt [(size_t)GKD  * DIN];
__device__ __half g_wvt [(size_t)GKD  * DIN];
__device__ __half g_wot [(size_t)DIN  * DOUT];

// attention operands (fp16: Q single, K/V hi/lo)
__device__ __half g_qf [(size_t)H_Q * S_LEN * HD];
__device__ __half g_kh [(size_t)G_KV * S_LEN * HD];
__device__ __half g_kl [(size_t)G_KV * S_LEN * HD];
__device__ __half g_vh [(size_t)G_KV * S_LEN * HD];
__device__ __half g_vl [(size_t)G_KV * S_LEN * HD];

// ---------------------------- PTX helpers (compute_103-safe) ---------------
__device__ __forceinline__ uint32_t smem_u32(const void* p) {
    uint32_t a;
    asm("{ .reg .u64 t; cvta.to.shared.u64 t, %1; cvt.u32.u64 %0, t; }" : "=r"(a) : "l"(p));
    return a;
}
__device__ __forceinline__ void cp16(uint32_t dst, const void* src) {
    asm volatile("cp.async.cg.shared.global [%0], [%1], 16;\n"
                 :: "r"(dst), "l"(__cvta_generic_to_global(src)));
}
__device__ __forceinline__ void cp_commit() {
    asm volatile("cp.async.commit_group;" ::: "memory");
}
template<int N> __device__ __forceinline__ void cp_wait() {
    asm volatile("cp.async.wait_group %0;" :: "n"(N) : "memory");
}
#define LDSM4(r, addr) \
    asm volatile("ldmatrix.sync.aligned.m8n8.x4.shared.b16 {%0,%1,%2,%3}, [%4];" \
        : "=r"((r)[0]), "=r"((r)[1]), "=r"((r)[2]), "=r"((r)[3]) : "r"(addr))
#define LDSM4T(r, addr) \
    asm volatile("ldmatrix.sync.aligned.m8n8.x4.trans.shared.b16 {%0,%1,%2,%3}, [%4];" \
        : "=r"((r)[0]), "=r"((r)[1]), "=r"((r)[2]), "=r"((r)[3]) : "r"(addr))
#define MMA_F16(d, a, b0, b1) \
    asm volatile("mma.sync.aligned.m16n8k16.row.col.f32.f16.f16.f32 " \
        "{%0,%1,%2,%3}, {%4,%5,%6,%7}, {%8,%9}, {%0,%1,%2,%3};" \
        : "+f"((d)[0]), "+f"((d)[1]), "+f"((d)[2]), "+f"((d)[3]) \
        : "r"((a)[0]), "r"((a)[1]), "r"((a)[2]), "r"((a)[3]), "r"(b0), "r"(b1))

__device__ __forceinline__ uint32_t pack_f16x2(float lo, float hi) {
    uint32_t r;
    asm("cvt.rn.f16x2.f32 %0, %1, %2;" : "=r"(r) : "f"(hi), "f"(lo));
    return r;
}

// ---------------------------------------------------------------------------
// fp16 single-term GEMM core: C = A @ B^T. Tile 128x128x32, 256 thr,
// warp tile 64x32. 4-stage cp.async ring (prefetch 3), one sync per stage.
// ---------------------------------------------------------------------------
#define TILE_B   10240             /* 128 rows * 80 B */
#define STAGE_B  (2*TILE_B)        /* A, B */
#define GEMM_SMEM (4*STAGE_B)      /* 81920 */

#define GEMM_MAINLOOP(Aptr, Bptr, Kdim, m0v)                                        \
    float acc[4][4][4];                                                             \
    _Pragma("unroll")                                                               \
    for (int mi = 0; mi < 4; mi++)                                                  \
        _Pragma("unroll")                                                           \
        for (int ni = 0; ni < 4; ni++)                                              \
            _Pragma("unroll")                                                       \
            for (int q = 0; q < 4; q++) acc[mi][ni][q] = 0.f;                       \
    auto load_stage = [&](int k0, int buf) {                                        \
        uint32_t base = sb + buf * STAGE_B;                                         \
        _Pragma("unroll")                                                           \
        for (int i = 0; i < 4; i++) {                                               \
            int c = tid + (i << 8);                                                 \
            int tile = c >> 9, w = c & 511, row = w >> 2, ch = w & 3;               \
            const __half* gp;                                                       \
            if (tile == 0) gp = (Aptr) + (size_t)((m0v) + row) * (Kdim) + k0 + (ch << 3); \
            else           gp = (Bptr) + (size_t)row * (Kdim) + k0 + (ch << 3);     \
            cp16(base + tile * TILE_B + row * 80 + (ch << 4), gp);                  \
        }                                                                           \
        cp_commit();                                                                \
    };                                                                              \
    auto compute_stage = [&](int buf) {                                             \
        uint32_t base = sb + buf * STAGE_B;                                         \
        uint32_t sA = base, sB = base + TILE_B;                                     \
        _Pragma("unroll")                                                           \
        for (int kk = 0; kk < 2; kk++) {                                            \
            const int kb = kk * 2;                                                  \
            uint32_t a[4][4], b[2][4];                                              \
            _Pragma("unroll")                                                       \
            for (int mi = 0; mi < 4; mi++) {                                        \
                int row = warp_m * 64 + mi * 16 + (lane & 15);                      \
                LDSM4(a[mi], sA + row * 80 + (kb + (lane >> 4)) * 16);              \
            }                                                                       \
            _Pragma("unroll")                                                       \
            for (int bi = 0; bi < 2; bi++) {                                        \
                int row = warp_n * 32 + bi * 16 + (lane & 7) + ((lane >> 4) << 3);  \
                LDSM4(b[bi], sB + row * 80 + (kb + ((lane >> 3) & 1)) * 16);        \
            }                                                                       \
            _Pragma("unroll")                                                       \
            for (int mi = 0; mi < 4; mi++)                                          \
                _Pragma("unroll")                                                   \
                for (int ni = 0; ni < 4; ni++) {                                    \
                    uint32_t* Bp = &b[ni >> 1][(ni & 1) * 2];                       \
                    MMA_F16(acc[mi][ni], a[mi], Bp[0], Bp[1]);                      \
                }                                                                   \
        }                                                                           \
    };                                                                              \
    const int NS = (Kdim) >> 5;                                                     \
    load_stage(0, 0);                                                               \
    load_stage(32, 1);                                                              \
    load_stage(64, 2);                                                              \
    for (int t = 0; t < NS; t++) {                                                  \
        if (t + 2 < NS) cp_wait<2>();                                               \
        else if (t + 1 < NS) cp_wait<1>();                                          \
        else cp_wait<0>();                                                          \
        __syncthreads();                                                            \
        compute_stage(t & 3);                                                       \
        if (t + 3 < NS) load_stage((t + 3) << 5, (t + 3) & 3);                      \
    }

// ---- merged QKV projection: N = 6144 segments [Q:4096 | K:1024 | V:1024] ----
__global__ __launch_bounds__(256, 2) void gemm_qkv_kernel(
    const __half* __restrict__ A,
    const __half* __restrict__ Wq16, const __half* __restrict__ Wk16,
    const __half* __restrict__ Wv16,
    float* __restrict__ Cq, float* __restrict__ Ck, float* __restrict__ Cv,
    __half* __restrict__ Vh, __half* __restrict__ Vl)
{
    extern __shared__ __align__(128) char smem[];
    const uint32_t sb = smem_u32(smem);
    const int tid  = threadIdx.x;
    const int wid  = tid >> 5;
    const int lane = tid & 31;
    const int warp_m = wid >> 2;
    const int warp_n = wid & 3;
    const int m0 = blockIdx.y * 128;
    const int n0g = blockIdx.x * 128;

    int seg, nloc;
    const __half* Bp;
    if (n0g < DOUT)            { seg = 0; nloc = n0g;              Bp = Wq16 + (size_t)nloc * DIN; }
    else if (n0g < DOUT + GKD) { seg = 1; nloc = n0g - DOUT;       Bp = Wk16 + (size_t)nloc * DIN; }
    else                       { seg = 2; nloc = n0g - DOUT - GKD; Bp = Wv16 + (size_t)nloc * DIN; }

    GEMM_MAINLOOP(A, Bp, DIN, m0)

    #pragma unroll
    for (int mi = 0; mi < 4; mi++) {
        #pragma unroll
        for (int ni = 0; ni < 4; ni++) {
            int r0 = m0 + warp_m * 64 + mi * 16 + (lane >> 2);
            int cl = nloc + warp_n * 32 + ni * 8 + (lane & 3) * 2;
            float2 v01 = make_float2(acc[mi][ni][0], acc[mi][ni][1]);
            float2 v23 = make_float2(acc[mi][ni][2], acc[mi][ni][3]);
            if (seg == 0) {
                *(float2*)(Cq + (size_t)r0 * DOUT + cl)       = v01;
                *(float2*)(Cq + (size_t)(r0 + 8) * DOUT + cl) = v23;
            } else if (seg == 1) {
                *(float2*)(Ck + (size_t)r0 * GKD + cl)       = v01;
                *(float2*)(Ck + (size_t)(r0 + 8) * GKD + cl) = v23;
            } else {
                size_t gb = (size_t)(cl >> 7) * S_LEN * HD;
                int cc = cl & 127;
                size_t iA = gb + (size_t)r0 * HD + cc;
                size_t iB = gb + (size_t)(r0 + 8) * HD + cc;
                *(float2*)(Cv + iA) = v01;
                *(float2*)(Cv + iB) = v23;
                float h0 = __half2float(__float2half_rn(v01.x));
                float h1 = __half2float(__float2half_rn(v01.y));
                float h2 = __half2float(__float2half_rn(v23.x));
                float h3 = __half2float(__float2half_rn(v23.y));
                ((uint32_t*)Vh)[iA >> 1] = pack_f16x2(h0, h1);
                ((uint32_t*)Vl)[iA >> 1] = pack_f16x2(v01.x - h0, v01.y - h1);
                ((uint32_t*)Vh)[iB >> 1] = pack_f16x2(h2, h3);
                ((uint32_t*)Vl)[iB >> 1] = pack_f16x2(v23.x - h2, v23.y - h3);
            }
        }
    }
}

// ---- Wo GEMM ----
__global__ __launch_bounds__(256, 2) void gemm_wo_kernel(
    const __half* __restrict__ A, const __half* __restrict__ BP,
    float* __restrict__ C, int N, int K)
{
    extern __shared__ __align__(128) char smem[];
    const uint32_t sb = smem_u32(smem);
    const int tid  = threadIdx.x;
    const int wid  = tid >> 5;
    const int lane = tid & 31;
    const int warp_m = wid >> 2;
    const int warp_n = wid & 3;
    const int m0 = blockIdx.y * 128;
    const int n0 = blockIdx.x * 128;
    const __half* Bp = BP + (size_t)n0 * K;

    GEMM_MAINLOOP(A, Bp, K, m0)

    #pragma unroll
    for (int mi = 0; mi < 4; mi++) {
        #pragma unroll
        for (int ni = 0; ni < 4; ni++) {
            int r0 = m0 + warp_m * 64 + mi * 16 + (lane >> 2);
            int c0 = n0 + warp_n * 32 + ni * 8 + (lane & 3) * 2;
            *(float2*)(C + (size_t)r0 * N + c0)       = make_float2(acc[mi][ni][0], acc[mi][ni][1]);
            *(float2*)(C + (size_t)(r0 + 8) * N + c0) = make_float2(acc[mi][ni][2], acc[mi][ni][3]);
        }
    }
}

// ------------------------- conversion kernels ------------------------------
__global__ __launch_bounds__(256) void split_f16_kernel(
    const float4* __restrict__ in, ushort4* __restrict__ o16, int n4)
{
    int i = blockIdx.x * 256 + threadIdx.x;
    if (i >= n4) return;
    float4 v = in[i];
    o16[i] = make_ushort4(__half_as_ushort(__float2half_rn(v.x)),
                          __half_as_ushort(__float2half_rn(v.y)),
                          __half_as_ushort(__float2half_rn(v.z)),
                          __half_as_ushort(__float2half_rn(v.w)));
}

__global__ __launch_bounds__(256) void transpose_f16_kernel(
    const float* __restrict__ W, __half* __restrict__ T, int K, int N)
{
    __shared__ float t[32][33];
    const int bn = blockIdx.x * 32, bk = blockIdx.y * 32;
    const int tx = threadIdx.x, ty = threadIdx.y;
    #pragma unroll
    for (int j = 0; j < 32; j += 8)
        t[ty + j][tx] = W[(size_t)(bk + ty + j) * N + bn + tx];
    __syncthreads();
    #pragma unroll
    for (int j = 0; j < 32; j += 8) {
        float v = t[tx][ty + j];
        T[(size_t)(bn + ty + j) * K + bk + tx] = __float2half_rn(v);
    }
}

// ------------------------- RMSNorm + RoPE variants -------------------------
__global__ __launch_bounds__(128) void norm_rope_q_kernel(
    const float* __restrict__ in, const float* __restrict__ scale,
    const float* __restrict__ cosp, const float* __restrict__ sinp,
    __half* __restrict__ qf)
{
    const int s = blockIdx.x, h = blockIdx.y, d = threadIdx.x;
    const size_t base = ((size_t)s * H_Q + h) * HD;
    float x = in[base + d];
    float v = x * x;
    #pragma unroll
    for (int off = 16; off; off >>= 1) v += __shfl_xor_sync(0xffffffffu, v, off);
    __shared__ float ws[4];
    __shared__ float ysm[HD];
    if ((d & 31) == 0) ws[d >> 5] = v;
    __syncthreads();
    float var = (ws[0] + ws[1] + ws[2] + ws[3]) * (1.0f / HD);
    float y = x * rsqrtf(var + 1e-6f) * scale[d];
    ysm[d] = y;
    __syncthreads();
    float rot = (d < 64) ? -ysm[d + 64] : ysm[d - 64];
    float r = fmaf(y, cosp[s * HD + d], rot * sinp[s * HD + d]) * 0.088388347648318447f;
    qf[((size_t)h * S_LEN + s) * HD + d] = __float2half_rn(r);
}

__global__ __launch_bounds__(128) void norm_rope_k_kernel(
    const float* __restrict__ in, const float* __restrict__ scale,
    const float* __restrict__ cosp, const float* __restrict__ sinp,
    float* __restrict__ kout, __half* __restrict__ kh, __half* __restrict__ kl)
{
    const int s = blockIdx.x, h = blockIdx.y, d = threadIdx.x;
    const size_t base = ((size_t)s * G_KV + h) * HD;
    float x = in[base + d];
    float v = x * x;
    #pragma unroll
    for (int off = 16; off; off >>= 1) v += __shfl_xor_sync(0xffffffffu, v, off);
    __shared__ float ws[4];
    __shared__ float ysm[HD];
    if ((d & 31) == 0) ws[d >> 5] = v;
    __syncthreads();
    float var = (ws[0] + ws[1] + ws[2] + ws[3]) * (1.0f / HD);
    float y = x * rsqrtf(var + 1e-6f) * scale[d];
    ysm[d] = y;
    __syncthreads();
    float rot = (d < 64) ? -ysm[d + 64] : ysm[d - 64];
    float r = fmaf(y, cosp[s * HD + d], rot * sinp[s * HD + d]);
    size_t o = ((size_t)h * S_LEN + s) * HD + d;
    kout[o] = r;
    __half hb = __float2half_rn(r);
    kh[o] = hb;
    kl[o] = __float2half_rn(r - __half2float(hb));
}

// ---------------------------------------------------------------------------
// Tensor-core flash attention, fp16 2-term (unchanged from R7)
// ---------------------------------------------------------------------------
#define SQA      272
#define Q_BYTES  (128*SQA)
#define KV_TILE  (64*SQA)
#define ATT_SMEM (Q_BYTES + 2*4*KV_TILE)   /* 174080 */

__global__ __launch_bounds__(256) void attn_mma_kernel(
    const __half* __restrict__ Qf,
    const __half* __restrict__ Kh, const __half* __restrict__ Kl,
    const __half* __restrict__ Vh, const __half* __restrict__ Vl,
    __half* __restrict__ Cf)
{
    extern __shared__ __align__(128) char smem[];
    const uint32_t sb = smem_u32(smem);
    const int h  = blockIdx.y;
    const int g  = h >> 2;
    const int qt = gridDim.x - 1 - blockIdx.x;
    const int tid = threadIdx.x, wid = tid >> 5, lane = tid & 31;
    const int qbase = qt * 128;

    const uint32_t sQf = sb;
    const uint32_t sKV0 = sb + Q_BYTES;

    {
        const __half* bq = Qf + ((size_t)h * S_LEN + qbase) * HD;
        #pragma unroll
        for (int i = 0; i < 8; i++) {
            int c = tid + (i << 8);
            int r = c >> 4, ch = c & 15;
            cp16(sQf + r * SQA + ch * 16, bq + r * HD + ch * 8);
        }
    }
    auto load_kv = [&](int kt, int buf) {
        uint32_t base = sKV0 + buf * 4 * KV_TILE;
        const size_t gb = ((size_t)g * S_LEN + kt * 64) * HD;
        #pragma unroll
        for (int i = 0; i < 16; i++) {
            int c = tid + (i << 8);
            int arr = c >> 10, w = c & 1023, r = w >> 4, ch = w & 15;
            const __half* src =
                (arr == 0 ? Kh : arr == 1 ? Kl : arr == 2 ? Vh : Vl) + gb + r * HD + ch * 8;
            cp16(base + arr * KV_TILE + r * SQA + ch * 16, src);
        }
    };
    load_kv(0, 0);
    cp_commit();

    float o[16][4];
    #pragma unroll
    for (int nj = 0; nj < 16; nj++)
        #pragma unroll
        for (int q = 0; q < 4; q++) o[nj][q] = 0.f;
    float mA = -1e30f, mB = -1e30f, lA = 0.f, lB = 0.f;

    const int rA = lane >> 2;
    const int colq = (lane & 3) * 2;
    const int ktmax = 2 * qt + 1;

    for (int kt = 0; kt <= ktmax; kt++) {
        if (kt < ktmax) { load_kv(kt + 1, (kt + 1) & 1); cp_commit(); cp_wait<1>(); }
        else            { cp_wait<0>(); }
        __syncthreads();

        const uint32_t bKh = sKV0 + (kt & 1) * 4 * KV_TILE;
        const uint32_t bKl = bKh + KV_TILE;
        const uint32_t bVh = bKh + 2 * KV_TILE;
        const uint32_t bVl = bKh + 3 * KV_TILE;

        float acc[8][4];
        #pragma unroll
        for (int ni = 0; ni < 8; ni++)
            #pragma unroll
            for (int q = 0; q < 4; q++) acc[ni][q] = 0.f;

        #pragma unroll
        for (int ks = 0; ks < 8; ks++) {
            uint32_t a[4];
            {
                int row = wid * 16 + (lane & 15);
                LDSM4(a, sQf + row * SQA + (ks * 2 + (lane >> 4)) * 16);
            }
            #pragma unroll
            for (int nb = 0; nb < 4; nb++) {
                uint32_t bh[4], bl[4];
                int row = nb * 16 + (lane & 7) + ((lane >> 4) << 3);
                uint32_t off = row * SQA + (ks * 2 + ((lane >> 3) & 1)) * 16;
                LDSM4(bh, bKh + off);
                LDSM4(bl, bKl + off);
                MMA_F16(acc[2*nb],   a, bh[0], bh[1]);
                MMA_F16(acc[2*nb],   a, bl[0], bl[1]);
                MMA_F16(acc[2*nb+1], a, bh[2], bh[3]);
                MMA_F16(acc[2*nb+1], a, bl[2], bl[3]);
            }
        }

        if (kt >= 2 * qt) {
            int qrA = qbase + wid * 16 + rA;
            #pragma unroll
            for (int ni = 0; ni < 8; ni++) {
                int key = kt * 64 + ni * 8 + colq;
                if (key     > qrA)     acc[ni][0] = -1e30f;
                if (key + 1 > qrA)     acc[ni][1] = -1e30f;
                if (key     > qrA + 8) acc[ni][2] = -1e30f;
                if (key + 1 > qrA + 8) acc[ni][3] = -1e30f;
            }
        }

        float mxA = -1e30f, mxB = -1e30f;
        #pragma unroll
        for (int ni = 0; ni < 8; ni++) {
            mxA = fmaxf(mxA, fmaxf(acc[ni][0], acc[ni][1]));
            mxB = fmaxf(mxB, fmaxf(acc[ni][2], acc[ni][3]));
        }
        mxA = fmaxf(mxA, __shfl_xor_sync(0xffffffffu, mxA, 1));
        mxA = fmaxf(mxA, __shfl_xor_sync(0xffffffffu, mxA, 2));
        mxB = fmaxf(mxB, __shfl_xor_sync(0xffffffffu, mxB, 1));
        mxB = fmaxf(mxB, __shfl_xor_sync(0xffffffffu, mxB, 2));
        float nmA = fmaxf(mA, mxA), nmB = fmaxf(mB, mxB);
        float aA = __expf(mA - nmA), aB = __expf(mB - nmB);
        mA = nmA; mB = nmB;
        float sA = 0.f, sB = 0.f;
        #pragma unroll
        for (int ni = 0; ni < 8; ni++) {
            acc[ni][0] = __expf(acc[ni][0] - nmA);
            acc[ni][1] = __expf(acc[ni][1] - nmA);
            acc[ni][2] = __expf(acc[ni][2] - nmB);
            acc[ni][3] = __expf(acc[ni][3] - nmB);
            sA += acc[ni][0] + acc[ni][1];
            sB += acc[ni][2] + acc[ni][3];
        }
        lA = lA * aA + sA;
        lB = lB * aB + sB;
        #pragma unroll
        for (int nj = 0; nj < 16; nj++) {
            o[nj][0] *= aA; o[nj][1] *= aA;
            o[nj][2] *= aB; o[nj][3] *= aB;
        }

        #pragma unroll
        for (int ks = 0; ks < 4; ks++) {
            uint32_t p[4];
            #pragma unroll
            for (int j = 0; j < 4; j++) {
                const float* pr = acc[2 * ks + (j >> 1)];
                p[j] = pack_f16x2(pr[(j & 1) ? 2 : 0], pr[(j & 1) ? 3 : 1]);
            }
            #pragma unroll
            for (int nj = 0; nj < 8; nj++) {
                uint32_t vh[4], vl[4];
                int row = ks * 16 + (lane & 7) + (((lane >> 3) & 1) << 3);
                uint32_t off = row * SQA + nj * 32 + (lane >> 4) * 16;
                LDSM4T(vh, bVh + off);
                LDSM4T(vl, bVl + off);
                MMA_F16(o[2*nj],   p, vh[0], vh[1]);
                MMA_F16(o[2*nj],   p, vl[0], vl[1]);
                MMA_F16(o[2*nj+1], p, vh[2], vh[3]);
                MMA_F16(o[2*nj+1], p, vl[2], vl[3]);
            }
        }
        __syncthreads();
    }

    float lAt = lA + __shfl_xor_sync(0xffffffffu, lA, 1);
    lAt += __shfl_xor_sync(0xffffffffu, lAt, 2);
    float lBt = lB + __shfl_xor_sync(0xffffffffu, lB, 1);
    lBt += __shfl_xor_sync(0xffffffffu, lBt, 2);
    float invA = 1.f / lAt, invB = 1.f / lBt;

    const int rowA = qbase + wid * 16 + rA;
    uint32_t* C32 = (uint32_t*)Cf;
    #pragma unroll
    for (int nj = 0; nj < 16; nj++) {
        int col = h * HD + nj * 8 + colq;
        float v0 = o[nj][0] * invA, v1 = o[nj][1] * invA;
        float v2 = o[nj][2] * invB, v3 = o[nj][3] * invB;
        C32[(size_t)rowA * (DOUT/2) + (col >> 1)]       = pack_f16x2(v0, v1);
        C32[(size_t)(rowA + 8) * (DOUT/2) + (col >> 1)] = pack_f16x2(v2, v3);
    }
}

// ---------------------------------------------------------------------------
extern "C" void kernel_launch(void* const* d_in, const int* in_sizes, int n_in,
                              void* d_out, int out_size)
{
    const float* x    = (const float*)d_in[0];
    const float* cosp = (const float*)d_in[2];
    const float* sinp = (const float*)d_in[3];
    const float* Wq   = (const float*)d_in[4];
    const float* Wk   = (const float*)d_in[5];
    const float* Wv   = (const float*)d_in[6];
    const float* Wo   = (const float*)d_in[7];
    const float* qsc  = (const float*)d_in[8];
    const float* ksc  = (const float*)d_in[9];

    float* out  = (float*)d_out;
    float* kout = out  + (size_t)S_LEN * DIN;
    float* vout = kout + (size_t)G_KV * S_LEN * HD;

    float *gq, *gk;
    __half *xf, *cf, *wq16, *wk16, *wv16, *wo16;
    __half *qf, *kh, *kl, *vh, *vl;
    cudaGetSymbolAddress((void**)&gq,   g_q);
    cudaGetSymbolAddress((void**)&gk,   g_k);
    cudaGetSymbolAddress((void**)&xf,   g_xf16);
    cudaGetSymbolAddress((void**)&cf,   g_cf16);
    cudaGetSymbolAddress((void**)&wq16, g_wqt);
    cudaGetSymbolAddress((void**)&wk16, g_wkt);
    cudaGetSymbolAddress((void**)&wv16, g_wvt);
    cudaGetSymbolAddress((void**)&wo16, g_wot);
    cudaGetSymbolAddress((void**)&qf,   g_qf);
    cudaGetSymbolAddress((void**)&kh,   g_kh);
    cudaGetSymbolAddress((void**)&kl,   g_kl);
    cudaGetSymbolAddress((void**)&vh,   g_vh);
    cudaGetSymbolAddress((void**)&vl,   g_vl);

    cudaFuncSetAttribute(gemm_qkv_kernel, cudaFuncAttributeMaxDynamicSharedMemorySize, GEMM_SMEM);
    cudaFuncSetAttribute(gemm_wo_kernel,  cudaFuncAttributeMaxDynamicSharedMemorySize, GEMM_SMEM);
    cudaFuncSetAttribute(attn_mma_kernel, cudaFuncAttributeMaxDynamicSharedMemorySize, ATT_SMEM);

    dim3 tb(32, 8);

    {
        int n4 = S_LEN * DIN / 4;
        split_f16_kernel<<<(n4 + 255) / 256, 256>>>((const float4*)x, (ushort4*)xf, n4);
    }
    transpose_f16_kernel<<<dim3(DOUT/32, DIN/32),  tb>>>(Wq, wq16, DIN,  DOUT);
    transpose_f16_kernel<<<dim3(GKD /32, DIN/32),  tb>>>(Wk, wk16, DIN,  GKD);
    transpose_f16_kernel<<<dim3(GKD /32, DIN/32),  tb>>>(Wv, wv16, DIN,  GKD);
    transpose_f16_kernel<<<dim3(DIN /32, DOUT/32), tb>>>(Wo, wo16, DOUT, DIN);

    gemm_qkv_kernel<<<dim3(QKV_N/128, S_LEN/128), 256, GEMM_SMEM>>>(
        xf, wq16, wk16, wv16, gq, gk, vout, vh, vl);

    norm_rope_q_kernel<<<dim3(S_LEN, H_Q),  128>>>(gq, qsc, cosp, sinp, qf);
    norm_rope_k_kernel<<<dim3(S_LEN, G_KV), 128>>>(gk, ksc, cosp, sinp, kout, kh, kl);

    attn_mma_kernel<<<dim3(S_LEN/128, H_Q), 256, ATT_SMEM>>>(qf, kh, kl, vh, vl, cf);

    gemm_wo_kernel<<<dim3(DIN/128, S_LEN/128), 256, GEMM_SMEM>>>(cf, wo16, out, DIN, DOUT);
}

// round 9
// speedup vs baseline: 8.4122x; 1.1599x over previous
#include <cuda_runtime.h>
#include <cuda_bf16.h>
#include <cuda_fp16.h>
#include <math.h>
#include <stdint.h>

#define S_LEN 2048
#define DIN   2048
#define H_Q   32
#define G_KV  8
#define HD    128
#define DOUT  (H_Q*HD)   /* 4096 */
#define GKD   (G_KV*HD)  /* 1024 */
#define QKV_N (DOUT + 2*GKD)  /* 6144 */

// ---------------- scratch (__device__ globals; no runtime alloc) ------------
__device__ __half g_xf16 [S_LEN * (size_t)DIN];
__device__ __half g_cf16 [S_LEN * (size_t)DOUT];
__device__ __half g_wqt [(size_t)DOUT * DIN];
__device__ __half g_wkt [(size_t)GKD  * DIN];
__device__ __half g_wvt [(size_t)GKD  * DIN];
__device__ __half g_wot [(size_t)DIN  * DOUT];

// attention operands (fp16: Q single, K single, V hi/lo)
__device__ __half g_qf [(size_t)H_Q * S_LEN * HD];
__device__ __half g_kh [(size_t)G_KV * S_LEN * HD];
__device__ __half g_vh [(size_t)G_KV * S_LEN * HD];
__device__ __half g_vl [(size_t)G_KV * S_LEN * HD];

// ---------------------------- PTX helpers (compute_103-safe) ---------------
__device__ __forceinline__ uint32_t smem_u32(const void* p) {
    uint32_t a;
    asm("{ .reg .u64 t; cvta.to.shared.u64 t, %1; cvt.u32.u64 %0, t; }" : "=r"(a) : "l"(p));
    return a;
}
__device__ __forceinline__ void cp16(uint32_t dst, const void* src) {
    asm volatile("cp.async.cg.shared.global [%0], [%1], 16;\n"
                 :: "r"(dst), "l"(__cvta_generic_to_global(src)));
}
__device__ __forceinline__ void cp_commit() {
    asm volatile("cp.async.commit_group;" ::: "memory");
}
template<int N> __device__ __forceinline__ void cp_wait() {
    asm volatile("cp.async.wait_group %0;" :: "n"(N) : "memory");
}
#define LDSM4(r, addr) \
    asm volatile("ldmatrix.sync.aligned.m8n8.x4.shared.b16 {%0,%1,%2,%3}, [%4];" \
        : "=r"((r)[0]), "=r"((r)[1]), "=r"((r)[2]), "=r"((r)[3]) : "r"(addr))
#define LDSM4T(r, addr) \
    asm volatile("ldmatrix.sync.aligned.m8n8.x4.trans.shared.b16 {%0,%1,%2,%3}, [%4];" \
        : "=r"((r)[0]), "=r"((r)[1]), "=r"((r)[2]), "=r"((r)[3]) : "r"(addr))
#define MMA_F16(d, a, b0, b1) \
    asm volatile("mma.sync.aligned.m16n8k16.row.col.f32.f16.f16.f32 " \
        "{%0,%1,%2,%3}, {%4,%5,%6,%7}, {%8,%9}, {%0,%1,%2,%3};" \
        : "+f"((d)[0]), "+f"((d)[1]), "+f"((d)[2]), "+f"((d)[3]) \
        : "r"((a)[0]), "r"((a)[1]), "r"((a)[2]), "r"((a)[3]), "r"(b0), "r"(b1))

__device__ __forceinline__ uint32_t pack_f16x2(float lo, float hi) {
    uint32_t r;
    asm("cvt.rn.f16x2.f32 %0, %1, %2;" : "=r"(r) : "f"(hi), "f"(lo));
    return r;
}

// ---------------------------------------------------------------------------
// fp16 single-term GEMM core: C = A @ B^T. Tile 128x128x32, 256 thr,
// warp tile 64x32. 4-stage cp.async ring (prefetch 3), one sync per stage.
// ---------------------------------------------------------------------------
#define TILE_B   10240             /* 128 rows * 80 B */
#define STAGE_B  (2*TILE_B)        /* A, B */
#define GEMM_SMEM (4*STAGE_B)      /* 81920 */

#define GEMM_MAINLOOP(Aptr, Bptr, Kdim, m0v)                                        \
    float acc[4][4][4];                                                             \
    _Pragma("unroll")                                                               \
    for (int mi = 0; mi < 4; mi++)                                                  \
        _Pragma("unroll")                                                           \
        for (int ni = 0; ni < 4; ni++)                                              \
            _Pragma("unroll")                                                       \
            for (int q = 0; q < 4; q++) acc[mi][ni][q] = 0.f;                       \
    auto load_stage = [&](int k0, int buf) {                                        \
        uint32_t base = sb + buf * STAGE_B;                                         \
        _Pragma("unroll")                                                           \
        for (int i = 0; i < 4; i++) {                                               \
            int c = tid + (i << 8);                                                 \
            int tile = c >> 9, w = c & 511, row = w >> 2, ch = w & 3;               \
            const __half* gp;                                                       \
            if (tile == 0) gp = (Aptr) + (size_t)((m0v) + row) * (Kdim) + k0 + (ch << 3); \
            else           gp = (Bptr) + (size_t)row * (Kdim) + k0 + (ch << 3);     \
            cp16(base + tile * TILE_B + row * 80 + (ch << 4), gp);                  \
        }                                                                           \
        cp_commit();                                                                \
    };                                                                              \
    auto compute_stage = [&](int buf) {                                             \
        uint32_t base = sb + buf * STAGE_B;                                         \
        uint32_t sA = base, sB = base + TILE_B;                                     \
        _Pragma("unroll")                                                           \
        for (int kk = 0; kk < 2; kk++) {                                            \
            const int kb = kk * 2;                                                  \
            uint32_t a[4][4], b[2][4];                                              \
            _Pragma("unroll")                                                       \
            for (int mi = 0; mi < 4; mi++) {                                        \
                int row = warp_m * 64 + mi * 16 + (lane & 15);                      \
                LDSM4(a[mi], sA + row * 80 + (kb + (lane >> 4)) * 16);              \
            }                                                                       \
            _Pragma("unroll")                                                       \
            for (int bi = 0; bi < 2; bi++) {                                        \
                int row = warp_n * 32 + bi * 16 + (lane & 7) + ((lane >> 4) << 3);  \
                LDSM4(b[bi], sB + row * 80 + (kb + ((lane >> 3) & 1)) * 16);        \
            }                                                                       \
            _Pragma("unroll")                                                       \
            for (int mi = 0; mi < 4; mi++)                                          \
                _Pragma("unroll")                                                   \
                for (int ni = 0; ni < 4; ni++) {                                    \
                    uint32_t* Bp = &b[ni >> 1][(ni & 1) * 2];                       \
                    MMA_F16(acc[mi][ni], a[mi], Bp[0], Bp[1]);                      \
                }                                                                   \
        }                                                                           \
    };                                                                              \
    const int NS = (Kdim) >> 5;                                                     \
    load_stage(0, 0);                                                               \
    load_stage(32, 1);                                                              \
    load_stage(64, 2);                                                              \
    for (int t = 0; t < NS; t++) {                                                  \
        if (t + 2 < NS) cp_wait<2>();                                               \
        else if (t + 1 < NS) cp_wait<1>();                                          \
        else cp_wait<0>();                                                          \
        __syncthreads();                                                            \
        compute_stage(t & 3);                                                       \
        if (t + 3 < NS) load_stage((t + 3) << 5, (t + 3) & 3);                      \
    }

// ---- merged QKV projection with FUSED RMSNorm+RoPE epilogue ----------------
// N segments: [Q:4096 | K:1024 | V:1024]; each 128-wide tile = one head.
// seg0 (Q): norm+rope -> fp16 Qf[H,S,HD] (pre-scaled 1/sqrt(HD))
// seg1 (K): norm+rope -> fp32 Kout[G,S,HD] (d_out) + fp16 Kh
// seg2 (V): fp32 Vout (d_out) + fp16 hi/lo Vh/Vl
#define ST_STRIDE 132   /* fp32 staging row stride (floats) */

__global__ __launch_bounds__(256, 2) void gemm_qkv_kernel(
    const __half* __restrict__ A,
    const __half* __restrict__ Wq16, const __half* __restrict__ Wk16,
    const __half* __restrict__ Wv16,
    const float* __restrict__ qsc, const float* __restrict__ ksc,
    const float* __restrict__ cosp, const float* __restrict__ sinp,
    __half* __restrict__ Qf, float* __restrict__ Kout, __half* __restrict__ Kh,
    float* __restrict__ Cv, __half* __restrict__ Vh, __half* __restrict__ Vl)
{
    extern __shared__ __align__(128) char smem[];
    const uint32_t sb = smem_u32(smem);
    const int tid  = threadIdx.x;
    const int wid  = tid >> 5;
    const int lane = tid & 31;
    const int warp_m = wid >> 2;
    const int warp_n = wid & 3;
    const int m0 = blockIdx.y * 128;
    const int n0g = blockIdx.x * 128;

    int seg, nloc;
    const __half* Bp;
    if (n0g < DOUT)            { seg = 0; nloc = n0g;              Bp = Wq16 + (size_t)nloc * DIN; }
    else if (n0g < DOUT + GKD) { seg = 1; nloc = n0g - DOUT;       Bp = Wk16 + (size_t)nloc * DIN; }
    else                       { seg = 2; nloc = n0g - DOUT - GKD; Bp = Wv16 + (size_t)nloc * DIN; }

    GEMM_MAINLOOP(A, Bp, DIN, m0)

    if (seg == 2) {
        // V: direct epilogue (no norm)
        #pragma unroll
        for (int mi = 0; mi < 4; mi++) {
            #pragma unroll
            for (int ni = 0; ni < 4; ni++) {
                int r0 = m0 + warp_m * 64 + mi * 16 + (lane >> 2);
                int cl = nloc + warp_n * 32 + ni * 8 + (lane & 3) * 2;
                float2 v01 = make_float2(acc[mi][ni][0], acc[mi][ni][1]);
                float2 v23 = make_float2(acc[mi][ni][2], acc[mi][ni][3]);
                size_t gb = (size_t)(cl >> 7) * S_LEN * HD;
                int cc = cl & 127;
                size_t iA = gb + (size_t)r0 * HD + cc;
                size_t iB = gb + (size_t)(r0 + 8) * HD + cc;
                *(float2*)(Cv + iA) = v01;
                *(float2*)(Cv + iB) = v23;
                float h0 = __half2float(__float2half_rn(v01.x));
                float h1 = __half2float(__float2half_rn(v01.y));
                float h2 = __half2float(__float2half_rn(v23.x));
                float h3 = __half2float(__float2half_rn(v23.y));
                ((uint32_t*)Vh)[iA >> 1] = pack_f16x2(h0, h1);
                ((uint32_t*)Vl)[iA >> 1] = pack_f16x2(v01.x - h0, v01.y - h1);
                ((uint32_t*)Vh)[iB >> 1] = pack_f16x2(h2, h3);
                ((uint32_t*)Vl)[iB >> 1] = pack_f16x2(v23.x - h2, v23.y - h3);
            }
        }
        return;
    }

    // Q/K: fused RMSNorm + RoPE. Stage the 128x128 fp32 tile in smem.
    float* st = (float*)smem;
    __syncthreads();    // all warps done reading the ring before we overwrite
    #pragma unroll
    for (int mi = 0; mi < 4; mi++) {
        #pragma unroll
        for (int ni = 0; ni < 4; ni++) {
            int r0 = warp_m * 64 + mi * 16 + (lane >> 2);
            int c  = warp_n * 32 + ni * 8 + (lane & 3) * 2;
            *(float2*)&st[r0 * ST_STRIDE + c]       = make_float2(acc[mi][ni][0], acc[mi][ni][1]);
            *(float2*)&st[(r0 + 8) * ST_STRIDE + c] = make_float2(acc[mi][ni][2], acc[mi][ni][3]);
        }
    }
    __syncthreads();

    const int head = nloc >> 7;                 // head (Q) or group (K)
    const float* scp = (seg == 0) ? qsc : ksc;
    float4 sc = *(const float4*)&scp[lane * 4];
    const float qk_scale = 0.088388347648318447f;

    for (int rr = 0; rr < 16; rr++) {
        int r = wid * 16 + rr;
        int s = m0 + r;
        float4 y = *(float4*)&st[r * ST_STRIDE + lane * 4];
        float ss = y.x * y.x + y.y * y.y + y.z * y.z + y.w * y.w;
        #pragma unroll
        for (int off = 16; off; off >>= 1) ss += __shfl_xor_sync(0xffffffffu, ss, off);
        float inv = rsqrtf(ss * (1.0f / HD) + 1e-6f);
        float y0 = y.x * inv * sc.x, y1 = y.y * inv * sc.y;
        float y2 = y.z * inv * sc.z, y3 = y.w * inv * sc.w;
        // RoPE partner: d = lane*4 + j ; d +/- 64 <=> lane ^ 16
        float p0 = __shfl_xor_sync(0xffffffffu, y0, 16);
        float p1 = __shfl_xor_sync(0xffffffffu, y1, 16);
        float p2 = __shfl_xor_sync(0xffffffffu, y2, 16);
        float p3 = __shfl_xor_sync(0xffffffffu, y3, 16);
        float sgn = (lane < 16) ? -1.f : 1.f;
        float4 cs = *(const float4*)&cosp[s * HD + lane * 4];
        float4 sn = *(const float4*)&sinp[s * HD + lane * 4];
        float r0 = fmaf(y0, cs.x, sgn * p0 * sn.x);
        float r1 = fmaf(y1, cs.y, sgn * p1 * sn.y);
        float r2 = fmaf(y2, cs.z, sgn * p2 * sn.z);
        float r3 = fmaf(y3, cs.w, sgn * p3 * sn.w);
        size_t o = ((size_t)head * S_LEN + s) * HD + lane * 4;
        if (seg == 0) {
            r0 *= qk_scale; r1 *= qk_scale; r2 *= qk_scale; r3 *= qk_scale;
            ((uint2*)Qf)[o >> 2] = make_uint2(pack_f16x2(r0, r1), pack_f16x2(r2, r3));
        } else {
            *(float4*)&Kout[o] = make_float4(r0, r1, r2, r3);
            ((uint2*)Kh)[o >> 2] = make_uint2(pack_f16x2(r0, r1), pack_f16x2(r2, r3));
        }
    }
}

// ---- Wo GEMM ----
__global__ __launch_bounds__(256, 2) void gemm_wo_kernel(
    const __half* __restrict__ A, const __half* __restrict__ BP,
    float* __restrict__ C, int N, int K)
{
    extern __shared__ __align__(128) char smem[];
    const uint32_t sb = smem_u32(smem);
    const int tid  = threadIdx.x;
    const int wid  = tid >> 5;
    const int lane = tid & 31;
    const int warp_m = wid >> 2;
    const int warp_n = wid & 3;
    const int m0 = blockIdx.y * 128;
    const int n0 = blockIdx.x * 128;
    const __half* Bp = BP + (size_t)n0 * K;

    GEMM_MAINLOOP(A, Bp, K, m0)

    #pragma unroll
    for (int mi = 0; mi < 4; mi++) {
        #pragma unroll
        for (int ni = 0; ni < 4; ni++) {
            int r0 = m0 + warp_m * 64 + mi * 16 + (lane >> 2);
            int c0 = n0 + warp_n * 32 + ni * 8 + (lane & 3) * 2;
            *(float2*)(C + (size_t)r0 * N + c0)       = make_float2(acc[mi][ni][0], acc[mi][ni][1]);
            *(float2*)(C + (size_t)(r0 + 8) * N + c0) = make_float2(acc[mi][ni][2], acc[mi][ni][3]);
        }
    }
}

// ------------------------- conversion kernels ------------------------------
__global__ __launch_bounds__(256) void split_f16_kernel(
    const float4* __restrict__ in, ushort4* __restrict__ o16, int n4)
{
    int i = blockIdx.x * 256 + threadIdx.x;
    if (i >= n4) return;
    float4 v = in[i];
    o16[i] = make_ushort4(__half_as_ushort(__float2half_rn(v.x)),
                          __half_as_ushort(__float2half_rn(v.y)),
                          __half_as_ushort(__float2half_rn(v.z)),
                          __half_as_ushort(__float2half_rn(v.w)));
}

__global__ __launch_bounds__(256) void transpose_f16_kernel(
    const float* __restrict__ W, __half* __restrict__ T, int K, int N)
{
    __shared__ float t[32][33];
    const int bn = blockIdx.x * 32, bk = blockIdx.y * 32;
    const int tx = threadIdx.x, ty = threadIdx.y;
    #pragma unroll
    for (int j = 0; j < 32; j += 8)
        t[ty + j][tx] = W[(size_t)(bk + ty + j) * N + bn + tx];
    __syncthreads();
    #pragma unroll
    for (int j = 0; j < 32; j += 8) {
        float v = t[tx][ty + j];
        T[(size_t)(bn + ty + j) * K + bk + tx] = __float2half_rn(v);
    }
}

// ---------------------------------------------------------------------------
// Tensor-core flash attention: Q single fp16 x K single fp16;
// P single fp16 x (Vh + Vl). fp32 softmax.
// ---------------------------------------------------------------------------
#define SQA      272
#define Q_BYTES  (128*SQA)
#define KV_TILE  (64*SQA)
#define ATT_SMEM (Q_BYTES + 2*3*KV_TILE)   /* 139264 */

__global__ __launch_bounds__(256) void attn_mma_kernel(
    const __half* __restrict__ Qf, const __half* __restrict__ Kh,
    const __half* __restrict__ Vh, const __half* __restrict__ Vl,
    __half* __restrict__ Cf)
{
    extern __shared__ __align__(128) char smem[];
    const uint32_t sb = smem_u32(smem);
    const int h  = blockIdx.y;
    const int g  = h >> 2;
    const int qt = gridDim.x - 1 - blockIdx.x;
    const int tid = threadIdx.x, wid = tid >> 5, lane = tid & 31;
    const int qbase = qt * 128;

    const uint32_t sQf = sb;
    const uint32_t sKV0 = sb + Q_BYTES;

    {
        const __half* bq = Qf + ((size_t)h * S_LEN + qbase) * HD;
        #pragma unroll
        for (int i = 0; i < 8; i++) {
            int c = tid + (i << 8);
            int r = c >> 4, ch = c & 15;
            cp16(sQf + r * SQA + ch * 16, bq + r * HD + ch * 8);
        }
    }
    auto load_kv = [&](int kt, int buf) {
        uint32_t base = sKV0 + buf * 3 * KV_TILE;
        const size_t gb = ((size_t)g * S_LEN + kt * 64) * HD;
        #pragma unroll
        for (int i = 0; i < 12; i++) {
            int c = tid + (i << 8);
            int arr = c >> 10, w = c & 1023, r = w >> 4, ch = w & 15;
            const __half* src =
                (arr == 0 ? Kh : arr == 1 ? Vh : Vl) + gb + r * HD + ch * 8;
            cp16(base + arr * KV_TILE + r * SQA + ch * 16, src);
        }
    };
    load_kv(0, 0);
    cp_commit();

    float o[16][4];
    #pragma unroll
    for (int nj = 0; nj < 16; nj++)
        #pragma unroll
        for (int q = 0; q < 4; q++) o[nj][q] = 0.f;
    float mA = -1e30f, mB = -1e30f, lA = 0.f, lB = 0.f;

    const int rA = lane >> 2;
    const int colq = (lane & 3) * 2;
    const int ktmax = 2 * qt + 1;

    for (int kt = 0; kt <= ktmax; kt++) {
        if (kt < ktmax) { load_kv(kt + 1, (kt + 1) & 1); cp_commit(); cp_wait<1>(); }
        else            { cp_wait<0>(); }
        __syncthreads();

        const uint32_t bKh = sKV0 + (kt & 1) * 3 * KV_TILE;
        const uint32_t bVh = bKh + KV_TILE;
        const uint32_t bVl = bKh + 2 * KV_TILE;

        float acc[8][4];
        #pragma unroll
        for (int ni = 0; ni < 8; ni++)
            #pragma unroll
            for (int q = 0; q < 4; q++) acc[ni][q] = 0.f;

        // ---- QK^T: single-term ----
        #pragma unroll
        for (int ks = 0; ks < 8; ks++) {
            uint32_t a[4];
            {
                int row = wid * 16 + (lane & 15);
                LDSM4(a, sQf + row * SQA + (ks * 2 + (lane >> 4)) * 16);
            }
            #pragma unroll
            for (int nb = 0; nb < 4; nb++) {
                uint32_t bh[4];
                int row = nb * 16 + (lane & 7) + ((lane >> 4) << 3);
                LDSM4(bh, bKh + row * SQA + (ks * 2 + ((lane >> 3) & 1)) * 16);
                MMA_F16(acc[2*nb],   a, bh[0], bh[1]);
                MMA_F16(acc[2*nb+1], a, bh[2], bh[3]);
            }
        }

        if (kt >= 2 * qt) {
            int qrA = qbase + wid * 16 + rA;
            #pragma unroll
            for (int ni = 0; ni < 8; ni++) {
                int key = kt * 64 + ni * 8 + colq;
                if (key     > qrA)     acc[ni][0] = -1e30f;
                if (key + 1 > qrA)     acc[ni][1] = -1e30f;
                if (key     > qrA + 8) acc[ni][2] = -1e30f;
                if (key + 1 > qrA + 8) acc[ni][3] = -1e30f;
            }
        }

        float mxA = -1e30f, mxB = -1e30f;
        #pragma unroll
        for (int ni = 0; ni < 8; ni++) {
            mxA = fmaxf(mxA, fmaxf(acc[ni][0], acc[ni][1]));
            mxB = fmaxf(mxB, fmaxf(acc[ni][2], acc[ni][3]));
        }
        mxA = fmaxf(mxA, __shfl_xor_sync(0xffffffffu, mxA, 1));
        mxA = fmaxf(mxA, __shfl_xor_sync(0xffffffffu, mxA, 2));
        mxB = fmaxf(mxB, __shfl_xor_sync(0xffffffffu, mxB, 1));
        mxB = fmaxf(mxB, __shfl_xor_sync(0xffffffffu, mxB, 2));
        float nmA = fmaxf(mA, mxA), nmB = fmaxf(mB, mxB);
        float aA = __expf(mA - nmA), aB = __expf(mB - nmB);
        mA = nmA; mB = nmB;
        float sA = 0.f, sB = 0.f;
        #pragma unroll
        for (int ni = 0; ni < 8; ni++) {
            acc[ni][0] = __expf(acc[ni][0] - nmA);
            acc[ni][1] = __expf(acc[ni][1] - nmA);
            acc[ni][2] = __expf(acc[ni][2] - nmB);
            acc[ni][3] = __expf(acc[ni][3] - nmB);
            sA += acc[ni][0] + acc[ni][1];
            sB += acc[ni][2] + acc[ni][3];
        }
        lA = lA * aA + sA;
        lB = lB * aB + sB;
        #pragma unroll
        for (int nj = 0; nj < 16; nj++) {
            o[nj][0] *= aA; o[nj][1] *= aA;
            o[nj][2] *= aB; o[nj][3] *= aB;
        }

        // ---- PV: P single fp16 x (Vh + Vl) ----
        #pragma unroll
        for (int ks = 0; ks < 4; ks++) {
            uint32_t p[4];
            #pragma unroll
            for (int j = 0; j < 4; j++) {
                const float* pr = acc[2 * ks + (j >> 1)];
                p[j] = pack_f16x2(pr[(j & 1) ? 2 : 0], pr[(j & 1) ? 3 : 1]);
            }
            #pragma unroll
            for (int nj = 0; nj < 8; nj++) {
                uint32_t vh[4], vl[4];
                int row = ks * 16 + (lane & 7) + (((lane >> 3) & 1) << 3);
                uint32_t off = row * SQA + nj * 32 + (lane >> 4) * 16;
                LDSM4T(vh, bVh + off);
                LDSM4T(vl, bVl + off);
                MMA_F16(o[2*nj],   p, vh[0], vh[1]);
                MMA_F16(o[2*nj],   p, vl[0], vl[1]);
                MMA_F16(o[2*nj+1], p, vh[2], vh[3]);
                MMA_F16(o[2*nj+1], p, vl[2], vl[3]);
            }
        }
        __syncthreads();
    }

    float lAt = lA + __shfl_xor_sync(0xffffffffu, lA, 1);
    lAt += __shfl_xor_sync(0xffffffffu, lAt, 2);
    float lBt = lB + __shfl_xor_sync(0xffffffffu, lB, 1);
    lBt += __shfl_xor_sync(0xffffffffu, lBt, 2);
    float invA = 1.f / lAt, invB = 1.f / lBt;

    const int rowA = qbase + wid * 16 + rA;
    uint32_t* C32 = (uint32_t*)Cf;
    #pragma unroll
    for (int nj = 0; nj < 16; nj++) {
        int col = h * HD + nj * 8 + colq;
        float v0 = o[nj][0] * invA, v1 = o[nj][1] * invA;
        float v2 = o[nj][2] * invB, v3 = o[nj][3] * invB;
        C32[(size_t)rowA * (DOUT/2) + (col >> 1)]       = pack_f16x2(v0, v1);
        C32[(size_t)(rowA + 8) * (DOUT/2) + (col >> 1)] = pack_f16x2(v2, v3);
    }
}

// ---------------------------------------------------------------------------
extern "C" void kernel_launch(void* const* d_in, const int* in_sizes, int n_in,
                              void* d_out, int out_size)
{
    const float* x    = (const float*)d_in[0];
    const float* cosp = (const float*)d_in[2];
    const float* sinp = (const float*)d_in[3];
    const float* Wq   = (const float*)d_in[4];
    const float* Wk   = (const float*)d_in[5];
    const float* Wv   = (const float*)d_in[6];
    const float* Wo   = (const float*)d_in[7];
    const float* qsc  = (const float*)d_in[8];
    const float* ksc  = (const float*)d_in[9];

    float* out  = (float*)d_out;
    float* kout = out  + (size_t)S_LEN * DIN;
    float* vout = kout + (size_t)G_KV * S_LEN * HD;

    __half *xf, *cf, *wq16, *wk16, *wv16, *wo16;
    __half *qf, *kh, *vh, *vl;
    cudaGetSymbolAddress((void**)&xf,   g_xf16);
    cudaGetSymbolAddress((void**)&cf,   g_cf16);
    cudaGetSymbolAddress((void**)&wq16, g_wqt);
    cudaGetSymbolAddress((void**)&wk16, g_wkt);
    cudaGetSymbolAddress((void**)&wv16, g_wvt);
    cudaGetSymbolAddress((void**)&wo16, g_wot);
    cudaGetSymbolAddress((void**)&qf,   g_qf);
    cudaGetSymbolAddress((void**)&kh,   g_kh);
    cudaGetSymbolAddress((void**)&vh,   g_vh);
    cudaGetSymbolAddress((void**)&vl,   g_vl);

    cudaFuncSetAttribute(gemm_qkv_kernel, cudaFuncAttributeMaxDynamicSharedMemorySize, GEMM_SMEM);
    cudaFuncSetAttribute(gemm_wo_kernel,  cudaFuncAttributeMaxDynamicSharedMemorySize, GEMM_SMEM);
    cudaFuncSetAttribute(attn_mma_kernel, cudaFuncAttributeMaxDynamicSharedMemorySize, ATT_SMEM);

    dim3 tb(32, 8);

    {
        int n4 = S_LEN * DIN / 4;
        split_f16_kernel<<<(n4 + 255) / 256, 256>>>((const float4*)x, (ushort4*)xf, n4);
    }
    transpose_f16_kernel<<<dim3(DOUT/32, DIN/32),  tb>>>(Wq, wq16, DIN,  DOUT);
    transpose_f16_kernel<<<dim3(GKD /32, DIN/32),  tb>>>(Wk, wk16, DIN,  GKD);
    transpose_f16_kernel<<<dim3(GKD /32, DIN/32),  tb>>>(Wv, wv16, DIN,  GKD);
    transpose_f16_kernel<<<dim3(DIN /32, DOUT/32), tb>>>(Wo, wo16, DOUT, DIN);

    // QKV projections with fused norm+rope epilogues
    gemm_qkv_kernel<<<dim3(QKV_N/128, S_LEN/128), 256, GEMM_SMEM>>>(
        xf, wq16, wk16, wv16, qsc, ksc, cosp, sinp,
        qf, kout, kh, vout, vh, vl);

    attn_mma_kernel<<<dim3(S_LEN/128, H_Q), 256, ATT_SMEM>>>(qf, kh, vh, vl, cf);

    gemm_wo_kernel<<<dim3(DIN/128, S_LEN/128), 256, GEMM_SMEM>>>(cf, wo16, out, DIN, DOUT);
}

// round 10
// speedup vs baseline: 9.6669x; 1.1492x over previous
#include <cuda_runtime.h>
#include <cuda_bf16.h>
#include <cuda_fp16.h>
#include <math.h>
#include <stdint.h>

#define S_LEN 2048
#define DIN   2048
#define H_Q   32
#define G_KV  8
#define HD    128
#define DOUT  (H_Q*HD)   /* 4096 */
#define GKD   (G_KV*HD)  /* 1024 */
#define QKV_N (DOUT + 2*GKD)  /* 6144 */

// ---------------- scratch (__device__ globals; no runtime alloc) ------------
__device__ __half g_xf16 [S_LEN * (size_t)DIN];
__device__ __half g_cf16 [S_LEN * (size_t)DOUT];
__device__ __half g_wqt [(size_t)DOUT * DIN];
__device__ __half g_wkt [(size_t)GKD  * DIN];
__device__ __half g_wvt [(size_t)GKD  * DIN];
__device__ __half g_wot [(size_t)DIN  * DOUT];

// attention operands (single-rounded fp16)
__device__ __half g_qf [(size_t)H_Q * S_LEN * HD];
__device__ __half g_kh [(size_t)G_KV * S_LEN * HD];
__device__ __half g_vh [(size_t)G_KV * S_LEN * HD];

// ---------------------------- PTX helpers (compute_103-safe) ---------------
__device__ __forceinline__ uint32_t smem_u32(const void* p) {
    uint32_t a;
    asm("{ .reg .u64 t; cvta.to.shared.u64 t, %1; cvt.u32.u64 %0, t; }" : "=r"(a) : "l"(p));
    return a;
}
__device__ __forceinline__ void cp16(uint32_t dst, const void* src) {
    asm volatile("cp.async.cg.shared.global [%0], [%1], 16;\n"
                 :: "r"(dst), "l"(__cvta_generic_to_global(src)));
}
__device__ __forceinline__ void cp_commit() {
    asm volatile("cp.async.commit_group;" ::: "memory");
}
template<int N> __device__ __forceinline__ void cp_wait() {
    asm volatile("cp.async.wait_group %0;" :: "n"(N) : "memory");
}
#define LDSM4(r, addr) \
    asm volatile("ldmatrix.sync.aligned.m8n8.x4.shared.b16 {%0,%1,%2,%3}, [%4];" \
        : "=r"((r)[0]), "=r"((r)[1]), "=r"((r)[2]), "=r"((r)[3]) : "r"(addr))
#define LDSM4T(r, addr) \
    asm volatile("ldmatrix.sync.aligned.m8n8.x4.trans.shared.b16 {%0,%1,%2,%3}, [%4];" \
        : "=r"((r)[0]), "=r"((r)[1]), "=r"((r)[2]), "=r"((r)[3]) : "r"(addr))
#define MMA_F16(d, a, b0, b1) \
    asm volatile("mma.sync.aligned.m16n8k16.row.col.f32.f16.f16.f32 " \
        "{%0,%1,%2,%3}, {%4,%5,%6,%7}, {%8,%9}, {%0,%1,%2,%3};" \
        : "+f"((d)[0]), "+f"((d)[1]), "+f"((d)[2]), "+f"((d)[3]) \
        : "r"((a)[0]), "r"((a)[1]), "r"((a)[2]), "r"((a)[3]), "r"(b0), "r"(b1))

__device__ __forceinline__ uint32_t pack_f16x2(float lo, float hi) {
    uint32_t r;
    asm("cvt.rn.f16x2.f32 %0, %1, %2;" : "=r"(r) : "f"(hi), "f"(lo));
    return r;
}

// ---------------------------------------------------------------------------
// fp16 single-term GEMM core: C = A @ B^T. Tile 128x128x32, 256 thr,
// warp tile 64x32. 4-stage cp.async ring (prefetch 3), one sync per stage.
// ---------------------------------------------------------------------------
#define TILE_B   10240             /* 128 rows * 80 B */
#define STAGE_B  (2*TILE_B)        /* A, B */
#define GEMM_SMEM (4*STAGE_B)      /* 81920 */

#define GEMM_MAINLOOP(Aptr, Bptr, Kdim, m0v)                                        \
    float acc[4][4][4];                                                             \
    _Pragma("unroll")                                                               \
    for (int mi = 0; mi < 4; mi++)                                                  \
        _Pragma("unroll")                                                           \
        for (int ni = 0; ni < 4; ni++)                                              \
            _Pragma("unroll")                                                       \
            for (int q = 0; q < 4; q++) acc[mi][ni][q] = 0.f;                       \
    auto load_stage = [&](int k0, int buf) {                                        \
        uint32_t base = sb + buf * STAGE_B;                                         \
        _Pragma("unroll")                                                           \
        for (int i = 0; i < 4; i++) {                                               \
            int c = tid + (i << 8);                                                 \
            int tile = c >> 9, w = c & 511, row = w >> 2, ch = w & 3;               \
            const __half* gp;                                                       \
            if (tile == 0) gp = (Aptr) + (size_t)((m0v) + row) * (Kdim) + k0 + (ch << 3); \
            else           gp = (Bptr) + (size_t)row * (Kdim) + k0 + (ch << 3);     \
            cp16(base + tile * TILE_B + row * 80 + (ch << 4), gp);                  \
        }                                                                           \
        cp_commit();                                                                \
    };                                                                              \
    auto compute_stage = [&](int buf) {                                             \
        uint32_t base = sb + buf * STAGE_B;                                         \
        uint32_t sA = base, sB = base + TILE_B;                                     \
        _Pragma("unroll")                                                           \
        for (int kk = 0; kk < 2; kk++) {                                            \
            const int kb = kk * 2;                                                  \
            uint32_t a[4][4], b[2][4];                                              \
            _Pragma("unroll")                                                       \
            for (int mi = 0; mi < 4; mi++) {                                        \
                int row = warp_m * 64 + mi * 16 + (lane & 15);                      \
                LDSM4(a[mi], sA + row * 80 + (kb + (lane >> 4)) * 16);              \
            }                                                                       \
            _Pragma("unroll")                                                       \
            for (int bi = 0; bi < 2; bi++) {                                        \
                int row = warp_n * 32 + bi * 16 + (lane & 7) + ((lane >> 4) << 3);  \
                LDSM4(b[bi], sB + row * 80 + (kb + ((lane >> 3) & 1)) * 16);        \
            }                                                                       \
            _Pragma("unroll")                                                       \
            for (int mi = 0; mi < 4; mi++)                                          \
                _Pragma("unroll")                                                   \
                for (int ni = 0; ni < 4; ni++) {                                    \
                    uint32_t* Bp = &b[ni >> 1][(ni & 1) * 2];                       \
                    MMA_F16(acc[mi][ni], a[mi], Bp[0], Bp[1]);                      \
                }                                                                   \
        }                                                                           \
    };                                                                              \
    const int NS = (Kdim) >> 5;                                                     \
    load_stage(0, 0);                                                               \
    load_stage(32, 1);                                                              \
    load_stage(64, 2);                                                              \
    for (int t = 0; t < NS; t++) {                                                  \
        if (t + 2 < NS) cp_wait<2>();                                               \
        else if (t + 1 < NS) cp_wait<1>();                                          \
        else cp_wait<0>();                                                          \
        __syncthreads();                                                            \
        compute_stage(t & 3);                                                       \
        if (t + 3 < NS) load_stage((t + 3) << 5, (t + 3) & 3);                      \
    }

// ---- merged QKV projection with FUSED RMSNorm+RoPE epilogue ----------------
#define ST_STRIDE 132   /* fp32 staging row stride (floats) */

__global__ __launch_bounds__(256, 2) void gemm_qkv_kernel(
    const __half* __restrict__ A,
    const __half* __restrict__ Wq16, const __half* __restrict__ Wk16,
    const __half* __restrict__ Wv16,
    const float* __restrict__ qsc, const float* __restrict__ ksc,
    const float* __restrict__ cosp, const float* __restrict__ sinp,
    __half* __restrict__ Qf, float* __restrict__ Kout, __half* __restrict__ Kh,
    float* __restrict__ Cv, __half* __restrict__ Vh)
{
    extern __shared__ __align__(128) char smem[];
    const uint32_t sb = smem_u32(smem);
    const int tid  = threadIdx.x;
    const int wid  = tid >> 5;
    const int lane = tid & 31;
    const int warp_m = wid >> 2;
    const int warp_n = wid & 3;
    const int m0 = blockIdx.y * 128;
    const int n0g = blockIdx.x * 128;

    int seg, nloc;
    const __half* Bp;
    if (n0g < DOUT)            { seg = 0; nloc = n0g;              Bp = Wq16 + (size_t)nloc * DIN; }
    else if (n0g < DOUT + GKD) { seg = 1; nloc = n0g - DOUT;       Bp = Wk16 + (size_t)nloc * DIN; }
    else                       { seg = 2; nloc = n0g - DOUT - GKD; Bp = Wv16 + (size_t)nloc * DIN; }

    GEMM_MAINLOOP(A, Bp, DIN, m0)

    if (seg == 2) {
        #pragma unroll
        for (int mi = 0; mi < 4; mi++) {
            #pragma unroll
            for (int ni = 0; ni < 4; ni++) {
                int r0 = m0 + warp_m * 64 + mi * 16 + (lane >> 2);
                int cl = nloc + warp_n * 32 + ni * 8 + (lane & 3) * 2;
                float2 v01 = make_float2(acc[mi][ni][0], acc[mi][ni][1]);
                float2 v23 = make_float2(acc[mi][ni][2], acc[mi][ni][3]);
                size_t gb = (size_t)(cl >> 7) * S_LEN * HD;
                int cc = cl & 127;
                size_t iA = gb + (size_t)r0 * HD + cc;
                size_t iB = gb + (size_t)(r0 + 8) * HD + cc;
                *(float2*)(Cv + iA) = v01;
                *(float2*)(Cv + iB) = v23;
                ((uint32_t*)Vh)[iA >> 1] = pack_f16x2(v01.x, v01.y);
                ((uint32_t*)Vh)[iB >> 1] = pack_f16x2(v23.x, v23.y);
            }
        }
        return;
    }

    // Q/K: fused RMSNorm + RoPE through fp32 smem staging
    float* st = (float*)smem;
    __syncthreads();
    #pragma unroll
    for (int mi = 0; mi < 4; mi++) {
        #pragma unroll
        for (int ni = 0; ni < 4; ni++) {
            int r0 = warp_m * 64 + mi * 16 + (lane >> 2);
            int c  = warp_n * 32 + ni * 8 + (lane & 3) * 2;
            *(float2*)&st[r0 * ST_STRIDE + c]       = make_float2(acc[mi][ni][0], acc[mi][ni][1]);
            *(float2*)&st[(r0 + 8) * ST_STRIDE + c] = make_float2(acc[mi][ni][2], acc[mi][ni][3]);
        }
    }
    __syncthreads();

    const int head = nloc >> 7;
    const float* scp = (seg == 0) ? qsc : ksc;
    float4 sc = *(const float4*)&scp[lane * 4];
    const float qk_scale = 0.088388347648318447f;

    for (int rr = 0; rr < 16; rr++) {
        int r = wid * 16 + rr;
        int s = m0 + r;
        float4 y = *(float4*)&st[r * ST_STRIDE + lane * 4];
        float ss = y.x * y.x + y.y * y.y + y.z * y.z + y.w * y.w;
        #pragma unroll
        for (int off = 16; off; off >>= 1) ss += __shfl_xor_sync(0xffffffffu, ss, off);
        float inv = rsqrtf(ss * (1.0f / HD) + 1e-6f);
        float y0 = y.x * inv * sc.x, y1 = y.y * inv * sc.y;
        float y2 = y.z * inv * sc.z, y3 = y.w * inv * sc.w;
        float p0 = __shfl_xor_sync(0xffffffffu, y0, 16);
        float p1 = __shfl_xor_sync(0xffffffffu, y1, 16);
        float p2 = __shfl_xor_sync(0xffffffffu, y2, 16);
        float p3 = __shfl_xor_sync(0xffffffffu, y3, 16);
        float sgn = (lane < 16) ? -1.f : 1.f;
        float4 cs = *(const float4*)&cosp[s * HD + lane * 4];
        float4 sn = *(const float4*)&sinp[s * HD + lane * 4];
        float r0 = fmaf(y0, cs.x, sgn * p0 * sn.x);
        float r1 = fmaf(y1, cs.y, sgn * p1 * sn.y);
        float r2 = fmaf(y2, cs.z, sgn * p2 * sn.z);
        float r3 = fmaf(y3, cs.w, sgn * p3 * sn.w);
        size_t o = ((size_t)head * S_LEN + s) * HD + lane * 4;
        if (seg == 0) {
            r0 *= qk_scale; r1 *= qk_scale; r2 *= qk_scale; r3 *= qk_scale;
            ((uint2*)Qf)[o >> 2] = make_uint2(pack_f16x2(r0, r1), pack_f16x2(r2, r3));
        } else {
            *(float4*)&Kout[o] = make_float4(r0, r1, r2, r3);
            ((uint2*)Kh)[o >> 2] = make_uint2(pack_f16x2(r0, r1), pack_f16x2(r2, r3));
        }
    }
}

// ---- Wo GEMM ----
__global__ __launch_bounds__(256, 2) void gemm_wo_kernel(
    const __half* __restrict__ A, const __half* __restrict__ BP,
    float* __restrict__ C, int N, int K)
{
    extern __shared__ __align__(128) char smem[];
    const uint32_t sb = smem_u32(smem);
    const int tid  = threadIdx.x;
    const int wid  = tid >> 5;
    const int lane = tid & 31;
    const int warp_m = wid >> 2;
    const int warp_n = wid & 3;
    const int m0 = blockIdx.y * 128;
    const int n0 = blockIdx.x * 128;
    const __half* Bp = BP + (size_t)n0 * K;

    GEMM_MAINLOOP(A, Bp, K, m0)

    #pragma unroll
    for (int mi = 0; mi < 4; mi++) {
        #pragma unroll
        for (int ni = 0; ni < 4; ni++) {
            int r0 = m0 + warp_m * 64 + mi * 16 + (lane >> 2);
            int c0 = n0 + warp_n * 32 + ni * 8 + (lane & 3) * 2;
            *(float2*)(C + (size_t)r0 * N + c0)       = make_float2(acc[mi][ni][0], acc[mi][ni][1]);
            *(float2*)(C + (size_t)(r0 + 8) * N + c0) = make_float2(acc[mi][ni][2], acc[mi][ni][3]);
        }
    }
}

// ------------------------- conversion kernels ------------------------------
__global__ __launch_bounds__(256) void split_f16_kernel(
    const float4* __restrict__ in, ushort4* __restrict__ o16, int n4)
{
    int i = blockIdx.x * 256 + threadIdx.x;
    if (i >= n4) return;
    float4 v = in[i];
    o16[i] = make_ushort4(__half_as_ushort(__float2half_rn(v.x)),
                          __half_as_ushort(__float2half_rn(v.y)),
                          __half_as_ushort(__float2half_rn(v.z)),
                          __half_as_ushort(__float2half_rn(v.w)));
}

// All 4 weight transposes in ONE launch; segment decode on blockIdx.x.
// seg layout (32x32 tiles): Wq 128x64 | Wk 32x64 | Wv 32x64 | Wo 64x128
__global__ __launch_bounds__(256) void transpose_all_kernel(
    const float* __restrict__ Wq, const float* __restrict__ Wk,
    const float* __restrict__ Wv, const float* __restrict__ Wo,
    __half* __restrict__ Tq, __half* __restrict__ Tk,
    __half* __restrict__ Tv, __half* __restrict__ To)
{
    __shared__ float t[32][33];
    int bid = blockIdx.x;
    const float* W; __half* T; int K, N, nbx;
    if (bid < 8192)       { W = Wq; T = Tq; K = DIN;  N = DOUT; nbx = 128; }
    else if (bid < 10240) { W = Wk; T = Tk; K = DIN;  N = GKD;  nbx = 32;  bid -= 8192; }
    else if (bid < 12288) { W = Wv; T = Tv; K = DIN;  N = GKD;  nbx = 32;  bid -= 10240; }
    else                  { W = Wo; T = To; K = DOUT; N = DIN;  nbx = 64;  bid -= 12288; }
    const int bn = (bid % nbx) * 32, bk = (bid / nbx) * 32;
    const int tx = threadIdx.x & 31, ty = (threadIdx.x >> 5) * 4;
    #pragma unroll
    for (int j = 0; j < 4; j++)
        t[ty + j][tx] = W[(size_t)(bk + ty + j) * N + bn + tx];
    __syncthreads();
    #pragma unroll
    for (int j = 0; j < 4; j++) {
        float v = t[tx][ty + j];
        T[(size_t)(bn + ty + j) * K + bk + tx] = __float2half_rn(v);
    }
}

// ---------------------------------------------------------------------------
// Tensor-core flash attention, all-single-term fp16 (Q.K, P.V), fp32 softmax.
// 104 KB smem -> 2 CTAs/SM.
// ---------------------------------------------------------------------------
#define SQA      272
#define Q_BYTES  (128*SQA)
#define KV_TILE  (64*SQA)
#define ATT_SMEM (Q_BYTES + 2*2*KV_TILE)   /* 104448 */

__global__ __launch_bounds__(256, 2) void attn_mma_kernel(
    const __half* __restrict__ Qf, const __half* __restrict__ Kh,
    const __half* __restrict__ Vh, __half* __restrict__ Cf)
{
    extern __shared__ __align__(128) char smem[];
    const uint32_t sb = smem_u32(smem);
    const int h  = blockIdx.y;
    const int g  = h >> 2;
    const int qt = gridDim.x - 1 - blockIdx.x;
    const int tid = threadIdx.x, wid = tid >> 5, lane = tid & 31;
    const int qbase = qt * 128;

    const uint32_t sQf = sb;
    const uint32_t sKV0 = sb + Q_BYTES;

    {
        const __half* bq = Qf + ((size_t)h * S_LEN + qbase) * HD;
        #pragma unroll
        for (int i = 0; i < 8; i++) {
            int c = tid + (i << 8);
            int r = c >> 4, ch = c & 15;
            cp16(sQf + r * SQA + ch * 16, bq + r * HD + ch * 8);
        }
    }
    auto load_kv = [&](int kt, int buf) {
        uint32_t base = sKV0 + buf * 2 * KV_TILE;
        const size_t gb = ((size_t)g * S_LEN + kt * 64) * HD;
        #pragma unroll
        for (int i = 0; i < 8; i++) {
            int c = tid + (i << 8);
            int arr = c >> 10, w = c & 1023, r = w >> 4, ch = w & 15;
            const __half* src = (arr == 0 ? Kh : Vh) + gb + r * HD + ch * 8;
            cp16(base + arr * KV_TILE + r * SQA + ch * 16, src);
        }
    };
    load_kv(0, 0);
    cp_commit();

    float o[16][4];
    #pragma unroll
    for (int nj = 0; nj < 16; nj++)
        #pragma unroll
        for (int q = 0; q < 4; q++) o[nj][q] = 0.f;
    float mA = -1e30f, mB = -1e30f, lA = 0.f, lB = 0.f;

    const int rA = lane >> 2;
    const int colq = (lane & 3) * 2;
    const int ktmax = 2 * qt + 1;

    for (int kt = 0; kt <= ktmax; kt++) {
        if (kt < ktmax) { load_kv(kt + 1, (kt + 1) & 1); cp_commit(); cp_wait<1>(); }
        else            { cp_wait<0>(); }
        __syncthreads();

        const uint32_t bKh = sKV0 + (kt & 1) * 2 * KV_TILE;
        const uint32_t bVh = bKh + KV_TILE;

        float acc[8][4];
        #pragma unroll
        for (int ni = 0; ni < 8; ni++)
            #pragma unroll
            for (int q = 0; q < 4; q++) acc[ni][q] = 0.f;

        #pragma unroll
        for (int ks = 0; ks < 8; ks++) {
            uint32_t a[4];
            {
                int row = wid * 16 + (lane & 15);
                LDSM4(a, sQf + row * SQA + (ks * 2 + (lane >> 4)) * 16);
            }
            #pragma unroll
            for (int nb = 0; nb < 4; nb++) {
                uint32_t bh[4];
                int row = nb * 16 + (lane & 7) + ((lane >> 4) << 3);
                LDSM4(bh, bKh + row * SQA + (ks * 2 + ((lane >> 3) & 1)) * 16);
                MMA_F16(acc[2*nb],   a, bh[0], bh[1]);
                MMA_F16(acc[2*nb+1], a, bh[2], bh[3]);
            }
        }

        if (kt >= 2 * qt) {
            int qrA = qbase + wid * 16 + rA;
            #pragma unroll
            for (int ni = 0; ni < 8; ni++) {
                int key = kt * 64 + ni * 8 + colq;
                if (key     > qrA)     acc[ni][0] = -1e30f;
                if (key + 1 > qrA)     acc[ni][1] = -1e30f;
                if (key     > qrA + 8) acc[ni][2] = -1e30f;
                if (key + 1 > qrA + 8) acc[ni][3] = -1e30f;
            }
        }

        float mxA = -1e30f, mxB = -1e30f;
        #pragma unroll
        for (int ni = 0; ni < 8; ni++) {
            mxA = fmaxf(mxA, fmaxf(acc[ni][0], acc[ni][1]));
            mxB = fmaxf(mxB, fmaxf(acc[ni][2], acc[ni][3]));
        }
        mxA = fmaxf(mxA, __shfl_xor_sync(0xffffffffu, mxA, 1));
        mxA = fmaxf(mxA, __shfl_xor_sync(0xffffffffu, mxA, 2));
        mxB = fmaxf(mxB, __shfl_xor_sync(0xffffffffu, mxB, 1));
        mxB = fmaxf(mxB, __shfl_xor_sync(0xffffffffu, mxB, 2));
        float nmA = fmaxf(mA, mxA), nmB = fmaxf(mB, mxB);
        float aA = __expf(mA - nmA), aB = __expf(mB - nmB);
        mA = nmA; mB = nmB;
        float sA = 0.f, sB = 0.f;
        #pragma unroll
        for (int ni = 0; ni < 8; ni++) {
            acc[ni][0] = __expf(acc[ni][0] - nmA);
            acc[ni][1] = __expf(acc[ni][1] - nmA);
            acc[ni][2] = __expf(acc[ni][2] - nmB);
            acc[ni][3] = __expf(acc[ni][3] - nmB);
            sA += acc[ni][0] + acc[ni][1];
            sB += acc[ni][2] + acc[ni][3];
        }
        lA = lA * aA + sA;
        lB = lB * aB + sB;
        #pragma unroll
        for (int nj = 0; nj < 16; nj++) {
            o[nj][0] *= aA; o[nj][1] *= aA;
            o[nj][2] *= aB; o[nj][3] *= aB;
        }

        #pragma unroll
        for (int ks = 0; ks < 4; ks++) {
            uint32_t p[4];
            #pragma unroll
            for (int j = 0; j < 4; j++) {
                const float* pr = acc[2 * ks + (j >> 1)];
                p[j] = pack_f16x2(pr[(j & 1) ? 2 : 0], pr[(j & 1) ? 3 : 1]);
            }
            #pragma unroll
            for (int nj = 0; nj < 8; nj++) {
                uint32_t vh[4];
                int row = ks * 16 + (lane & 7) + (((lane >> 3) & 1) << 3);
                LDSM4T(vh, bVh + row * SQA + nj * 32 + (lane >> 4) * 16);
                MMA_F16(o[2*nj],   p, vh[0], vh[1]);
                MMA_F16(o[2*nj+1], p, vh[2], vh[3]);
            }
        }
        __syncthreads();
    }

    float lAt = lA + __shfl_xor_sync(0xffffffffu, lA, 1);
    lAt += __shfl_xor_sync(0xffffffffu, lAt, 2);
    float lBt = lB + __shfl_xor_sync(0xffffffffu, lB, 1);
    lBt += __shfl_xor_sync(0xffffffffu, lBt, 2);
    float invA = 1.f / lAt, invB = 1.f / lBt;

    const int rowA = qbase + wid * 16 + rA;
    uint32_t* C32 = (uint32_t*)Cf;
    #pragma unroll
    for (int nj = 0; nj < 16; nj++) {
        int col = h * HD + nj * 8 + colq;
        float v0 = o[nj][0] * invA, v1 = o[nj][1] * invA;
        float v2 = o[nj][2] * invB, v3 = o[nj][3] * invB;
        C32[(size_t)rowA * (DOUT/2) + (col >> 1)]       = pack_f16x2(v0, v1);
        C32[(size_t)(rowA + 8) * (DOUT/2) + (col >> 1)] = pack_f16x2(v2, v3);
    }
}

// ---------------------------------------------------------------------------
extern "C" void kernel_launch(void* const* d_in, const int* in_sizes, int n_in,
                              void* d_out, int out_size)
{
    const float* x    = (const float*)d_in[0];
    const float* cosp = (const float*)d_in[2];
    const float* sinp = (const float*)d_in[3];
    const float* Wq   = (const float*)d_in[4];
    const float* Wk   = (const float*)d_in[5];
    const float* Wv   = (const float*)d_in[6];
    const float* Wo   = (const float*)d_in[7];
    const float* qsc  = (const float*)d_in[8];
    const float* ksc  = (const float*)d_in[9];

    float* out  = (float*)d_out;
    float* kout = out  + (size_t)S_LEN * DIN;
    float* vout = kout + (size_t)G_KV * S_LEN * HD;

    __half *xf, *cf, *wq16, *wk16, *wv16, *wo16;
    __half *qf, *kh, *vh;
    cudaGetSymbolAddress((void**)&xf,   g_xf16);
    cudaGetSymbolAddress((void**)&cf,   g_cf16);
    cudaGetSymbolAddress((void**)&wq16, g_wqt);
    cudaGetSymbolAddress((void**)&wk16, g_wkt);
    cudaGetSymbolAddress((void**)&wv16, g_wvt);
    cudaGetSymbolAddress((void**)&wo16, g_wot);
    cudaGetSymbolAddress((void**)&qf,   g_qf);
    cudaGetSymbolAddress((void**)&kh,   g_kh);
    cudaGetSymbolAddress((void**)&vh,   g_vh);

    cudaFuncSetAttribute(gemm_qkv_kernel, cudaFuncAttributeMaxDynamicSharedMemorySize, GEMM_SMEM);
    cudaFuncSetAttribute(gemm_wo_kernel,  cudaFuncAttributeMaxDynamicSharedMemorySize, GEMM_SMEM);
    cudaFuncSetAttribute(attn_mma_kernel, cudaFuncAttributeMaxDynamicSharedMemorySize, ATT_SMEM);

    {
        int n4 = S_LEN * DIN / 4;
        split_f16_kernel<<<(n4 + 255) / 256, 256>>>((const float4*)x, (ushort4*)xf, n4);
    }
    transpose_all_kernel<<<20480, 256>>>(Wq, Wk, Wv, Wo, wq16, wk16, wv16, wo16);

    gemm_qkv_kernel<<<dim3(QKV_N/128, S_LEN/128), 256, GEMM_SMEM>>>(
        xf, wq16, wk16, wv16, qsc, ksc, cosp, sinp,
        qf, kout, kh, vout, vh);

    attn_mma_kernel<<<dim3(S_LEN/128, H_Q), 256, ATT_SMEM>>>(qf, kh, vh, cf);

    gemm_wo_kernel<<<dim3(DIN/128, S_LEN/128), 256, GEMM_SMEM>>>(cf, wo16, out, DIN, DOUT);
}

// round 11
// speedup vs baseline: 10.9065x; 1.1282x over previous
#include <cuda_runtime.h>
#include <cuda_bf16.h>
#include <cuda_fp16.h>
#include <math.h>
#include <stdint.h>

#define S_LEN 2048
#define DIN   2048
#define H_Q   32
#define G_KV  8
#define HD    128
#define DOUT  (H_Q*HD)   /* 4096 */
#define GKD   (G_KV*HD)  /* 1024 */
#define QKV_N (DOUT + 2*GKD)  /* 6144 */

// ---------------- scratch (__device__ globals; no runtime alloc) ------------
__device__ __half g_xf16 [S_LEN * (size_t)DIN];
__device__ __half g_cf16 [S_LEN * (size_t)DOUT];
__device__ __half g_wqt [(size_t)DOUT * DIN];
__device__ __half g_wkt [(size_t)GKD  * DIN];
__device__ __half g_wvt [(size_t)GKD  * DIN];
__device__ __half g_wot [(size_t)DIN  * DOUT];

// attention operands (single-rounded fp16)
__device__ __half g_qf [(size_t)H_Q * S_LEN * HD];
__device__ __half g_kh [(size_t)G_KV * S_LEN * HD];
__device__ __half g_vh [(size_t)G_KV * S_LEN * HD];

// ---------------------------- PTX helpers (compute_103-safe) ---------------
__device__ __forceinline__ uint32_t smem_u32(const void* p) {
    uint32_t a;
    asm("{ .reg .u64 t; cvta.to.shared.u64 t, %1; cvt.u32.u64 %0, t; }" : "=r"(a) : "l"(p));
    return a;
}
__device__ __forceinline__ void cp16(uint32_t dst, const void* src) {
    asm volatile("cp.async.cg.shared.global [%0], [%1], 16;\n"
                 :: "r"(dst), "l"(__cvta_generic_to_global(src)));
}
__device__ __forceinline__ void cp_commit() {
    asm volatile("cp.async.commit_group;" ::: "memory");
}
template<int N> __device__ __forceinline__ void cp_wait() {
    asm volatile("cp.async.wait_group %0;" :: "n"(N) : "memory");
}
#define LDSM4(r, addr) \
    asm volatile("ldmatrix.sync.aligned.m8n8.x4.shared.b16 {%0,%1,%2,%3}, [%4];" \
        : "=r"((r)[0]), "=r"((r)[1]), "=r"((r)[2]), "=r"((r)[3]) : "r"(addr))
#define LDSM4T(r, addr) \
    asm volatile("ldmatrix.sync.aligned.m8n8.x4.trans.shared.b16 {%0,%1,%2,%3}, [%4];" \
        : "=r"((r)[0]), "=r"((r)[1]), "=r"((r)[2]), "=r"((r)[3]) : "r"(addr))
#define MMA_F16(d, a, b0, b1) \
    asm volatile("mma.sync.aligned.m16n8k16.row.col.f32.f16.f16.f32 " \
        "{%0,%1,%2,%3}, {%4,%5,%6,%7}, {%8,%9}, {%0,%1,%2,%3};" \
        : "+f"((d)[0]), "+f"((d)[1]), "+f"((d)[2]), "+f"((d)[3]) \
        : "r"((a)[0]), "r"((a)[1]), "r"((a)[2]), "r"((a)[3]), "r"(b0), "r"(b1))

__device__ __forceinline__ uint32_t pack_f16x2(float lo, float hi) {
    uint32_t r;
    asm("cvt.rn.f16x2.f32 %0, %1, %2;" : "=r"(r) : "f"(hi), "f"(lo));
    return r;
}

// ---------------------------------------------------------------------------
// fp16 single-term GEMM core: C = A @ B^T. Tile 128x128x32, 256 thr,
// warp tile 64x32. 4-stage cp.async ring (prefetch 3), one sync per stage.
// ---------------------------------------------------------------------------
#define TILE_B   10240             /* 128 rows * 80 B */
#define STAGE_B  (2*TILE_B)        /* A, B */
#define GEMM_SMEM (4*STAGE_B)      /* 81920 */

#define GEMM_MAINLOOP(Aptr, Bptr, Kdim, m0v)                                        \
    float acc[4][4][4];                                                             \
    _Pragma("unroll")                                                               \
    for (int mi = 0; mi < 4; mi++)                                                  \
        _Pragma("unroll")                                                           \
        for (int ni = 0; ni < 4; ni++)                                              \
            _Pragma("unroll")                                                       \
            for (int q = 0; q < 4; q++) acc[mi][ni][q] = 0.f;                       \
    auto load_stage = [&](int k0, int buf) {                                        \
        uint32_t base = sb + buf * STAGE_B;                                         \
        _Pragma("unroll")                                                           \
        for (int i = 0; i < 4; i++) {                                               \
            int c = tid + (i << 8);                                                 \
            int tile = c >> 9, w = c & 511, row = w >> 2, ch = w & 3;               \
            const __half* gp;                                                       \
            if (tile == 0) gp = (Aptr) + (size_t)((m0v) + row) * (Kdim) + k0 + (ch << 3); \
            else           gp = (Bptr) + (size_t)row * (Kdim) + k0 + (ch << 3);     \
            cp16(base + tile * TILE_B + row * 80 + (ch << 4), gp);                  \
        }                                                                           \
        cp_commit();                                                                \
    };                                                                              \
    auto compute_stage = [&](int buf) {                                             \
        uint32_t base = sb + buf * STAGE_B;                                         \
        uint32_t sA = base, sB = base + TILE_B;                                     \
        _Pragma("unroll")                                                           \
        for (int kk = 0; kk < 2; kk++) {                                            \
            const int kb = kk * 2;                                                  \
            uint32_t a[4][4], b[2][4];                                              \
            _Pragma("unroll")                                                       \
            for (int mi = 0; mi < 4; mi++) {                                        \
                int row = warp_m * 64 + mi * 16 + (lane & 15);                      \
                LDSM4(a[mi], sA + row * 80 + (kb + (lane >> 4)) * 16);              \
            }                                                                       \
            _Pragma("unroll")                                                       \
            for (int bi = 0; bi < 2; bi++) {                                        \
                int row = warp_n * 32 + bi * 16 + (lane & 7) + ((lane >> 4) << 3);  \
                LDSM4(b[bi], sB + row * 80 + (kb + ((lane >> 3) & 1)) * 16);        \
            }                                                                       \
            _Pragma("unroll")                                                       \
            for (int mi = 0; mi < 4; mi++)                                          \
                _Pragma("unroll")                                                   \
                for (int ni = 0; ni < 4; ni++) {                                    \
                    uint32_t* Bp = &b[ni >> 1][(ni & 1) * 2];                       \
                    MMA_F16(acc[mi][ni], a[mi], Bp[0], Bp[1]);                      \
                }                                                                   \
        }                                                                           \
    };                                                                              \
    const int NS = (Kdim) >> 5;                                                     \
    load_stage(0, 0);                                                               \
    load_stage(32, 1);                                                              \
    load_stage(64, 2);                                                              \
    for (int t = 0; t < NS; t++) {                                                  \
        if (t + 2 < NS) cp_wait<2>();                                               \
        else if (t + 1 < NS) cp_wait<1>();                                          \
        else cp_wait<0>();                                                          \
        __syncthreads();                                                            \
        compute_stage(t & 3);                                                       \
        if (t + 3 < NS) load_stage((t + 3) << 5, (t + 3) & 3);                      \
    }

// ---- merged QKV projection with FUSED RMSNorm+RoPE epilogue ----------------
#define ST_STRIDE 132   /* fp32 staging row stride (floats) */

__global__ __launch_bounds__(256, 2) void gemm_qkv_kernel(
    const __half* __restrict__ A,
    const __half* __restrict__ Wq16, const __half* __restrict__ Wk16,
    const __half* __restrict__ Wv16,
    const float* __restrict__ qsc, const float* __restrict__ ksc,
    const float* __restrict__ cosp, const float* __restrict__ sinp,
    __half* __restrict__ Qf, float* __restrict__ Kout, __half* __restrict__ Kh,
    float* __restrict__ Cv, __half* __restrict__ Vh)
{
    extern __shared__ __align__(128) char smem[];
    const uint32_t sb = smem_u32(smem);
    const int tid  = threadIdx.x;
    const int wid  = tid >> 5;
    const int lane = tid & 31;
    const int warp_m = wid >> 2;
    const int warp_n = wid & 3;
    const int m0 = blockIdx.y * 128;
    const int n0g = blockIdx.x * 128;

    int seg, nloc;
    const __half* Bp;
    if (n0g < DOUT)            { seg = 0; nloc = n0g;              Bp = Wq16 + (size_t)nloc * DIN; }
    else if (n0g < DOUT + GKD) { seg = 1; nloc = n0g - DOUT;       Bp = Wk16 + (size_t)nloc * DIN; }
    else                       { seg = 2; nloc = n0g - DOUT - GKD; Bp = Wv16 + (size_t)nloc * DIN; }

    GEMM_MAINLOOP(A, Bp, DIN, m0)

    if (seg == 2) {
        #pragma unroll
        for (int mi = 0; mi < 4; mi++) {
            #pragma unroll
            for (int ni = 0; ni < 4; ni++) {
                int r0 = m0 + warp_m * 64 + mi * 16 + (lane >> 2);
                int cl = nloc + warp_n * 32 + ni * 8 + (lane & 3) * 2;
                float2 v01 = make_float2(acc[mi][ni][0], acc[mi][ni][1]);
                float2 v23 = make_float2(acc[mi][ni][2], acc[mi][ni][3]);
                size_t gb = (size_t)(cl >> 7) * S_LEN * HD;
                int cc = cl & 127;
                size_t iA = gb + (size_t)r0 * HD + cc;
                size_t iB = gb + (size_t)(r0 + 8) * HD + cc;
                *(float2*)(Cv + iA) = v01;
                *(float2*)(Cv + iB) = v23;
                ((uint32_t*)Vh)[iA >> 1] = pack_f16x2(v01.x, v01.y);
                ((uint32_t*)Vh)[iB >> 1] = pack_f16x2(v23.x, v23.y);
            }
        }
        return;
    }

    // Q/K: fused RMSNorm + RoPE through fp32 smem staging
    float* st = (float*)smem;
    __syncthreads();
    #pragma unroll
    for (int mi = 0; mi < 4; mi++) {
        #pragma unroll
        for (int ni = 0; ni < 4; ni++) {
            int r0 = warp_m * 64 + mi * 16 + (lane >> 2);
            int c  = warp_n * 32 + ni * 8 + (lane & 3) * 2;
            *(float2*)&st[r0 * ST_STRIDE + c]       = make_float2(acc[mi][ni][0], acc[mi][ni][1]);
            *(float2*)&st[(r0 + 8) * ST_STRIDE + c] = make_float2(acc[mi][ni][2], acc[mi][ni][3]);
        }
    }
    __syncthreads();

    const int head = nloc >> 7;
    const float* scp = (seg == 0) ? qsc : ksc;
    float4 sc = *(const float4*)&scp[lane * 4];
    const float qk_scale = 0.088388347648318447f;

    for (int rr = 0; rr < 16; rr++) {
        int r = wid * 16 + rr;
        int s = m0 + r;
        float4 y = *(float4*)&st[r * ST_STRIDE + lane * 4];
        float ss = y.x * y.x + y.y * y.y + y.z * y.z + y.w * y.w;
        #pragma unroll
        for (int off = 16; off; off >>= 1) ss += __shfl_xor_sync(0xffffffffu, ss, off);
        float inv = rsqrtf(ss * (1.0f / HD) + 1e-6f);
        float y0 = y.x * inv * sc.x, y1 = y.y * inv * sc.y;
        float y2 = y.z * inv * sc.z, y3 = y.w * inv * sc.w;
        float p0 = __shfl_xor_sync(0xffffffffu, y0, 16);
        float p1 = __shfl_xor_sync(0xffffffffu, y1, 16);
        float p2 = __shfl_xor_sync(0xffffffffu, y2, 16);
        float p3 = __shfl_xor_sync(0xffffffffu, y3, 16);
        float sgn = (lane < 16) ? -1.f : 1.f;
        float4 cs = *(const float4*)&cosp[s * HD + lane * 4];
        float4 sn = *(const float4*)&sinp[s * HD + lane * 4];
        float r0 = fmaf(y0, cs.x, sgn * p0 * sn.x);
        float r1 = fmaf(y1, cs.y, sgn * p1 * sn.y);
        float r2 = fmaf(y2, cs.z, sgn * p2 * sn.z);
        float r3 = fmaf(y3, cs.w, sgn * p3 * sn.w);
        size_t o = ((size_t)head * S_LEN + s) * HD + lane * 4;
        if (seg == 0) {
            r0 *= qk_scale; r1 *= qk_scale; r2 *= qk_scale; r3 *= qk_scale;
            ((uint2*)Qf)[o >> 2] = make_uint2(pack_f16x2(r0, r1), pack_f16x2(r2, r3));
        } else {
            *(float4*)&Kout[o] = make_float4(r0, r1, r2, r3);
            ((uint2*)Kh)[o >> 2] = make_uint2(pack_f16x2(r0, r1), pack_f16x2(r2, r3));
        }
    }
}

// ---- Wo GEMM ----
__global__ __launch_bounds__(256, 2) void gemm_wo_kernel(
    const __half* __restrict__ A, const __half* __restrict__ BP,
    float* __restrict__ C, int N, int K)
{
    extern __shared__ __align__(128) char smem[];
    const uint32_t sb = smem_u32(smem);
    const int tid  = threadIdx.x;
    const int wid  = tid >> 5;
    const int lane = tid & 31;
    const int warp_m = wid >> 2;
    const int warp_n = wid & 3;
    const int m0 = blockIdx.y * 128;
    const int n0 = blockIdx.x * 128;
    const __half* Bp = BP + (size_t)n0 * K;

    GEMM_MAINLOOP(A, Bp, K, m0)

    #pragma unroll
    for (int mi = 0; mi < 4; mi++) {
        #pragma unroll
        for (int ni = 0; ni < 4; ni++) {
            int r0 = m0 + warp_m * 64 + mi * 16 + (lane >> 2);
            int c0 = n0 + warp_n * 32 + ni * 8 + (lane & 3) * 2;
            *(float2*)(C + (size_t)r0 * N + c0)       = make_float2(acc[mi][ni][0], acc[mi][ni][1]);
            *(float2*)(C + (size_t)(r0 + 8) * N + c0) = make_float2(acc[mi][ni][2], acc[mi][ni][3]);
        }
    }
}

// ------------------------- combined prep kernel -----------------------------
// blocks [0,4096):          x fp32 -> fp16 split (4096*256 float4)
// blocks [4096, 4096+20480): weight transposes (32x32 tiles)
__global__ __launch_bounds__(256) void prep_kernel(
    const float4* __restrict__ xin, ushort4* __restrict__ xf16,
    const float* __restrict__ Wq, const float* __restrict__ Wk,
    const float* __restrict__ Wv, const float* __restrict__ Wo,
    __half* __restrict__ Tq, __half* __restrict__ Tk,
    __half* __restrict__ Tv, __half* __restrict__ To)
{
    __shared__ float t[32][33];
    int bid = blockIdx.x;
    if (bid < 4096) {
        int i = bid * 256 + threadIdx.x;
        float4 v = xin[i];
        xf16[i] = make_ushort4(__half_as_ushort(__float2half_rn(v.x)),
                               __half_as_ushort(__float2half_rn(v.y)),
                               __half_as_ushort(__float2half_rn(v.z)),
                               __half_as_ushort(__float2half_rn(v.w)));
        return;
    }
    bid -= 4096;
    const float* W; __half* T; int K, N, nbx;
    if (bid < 8192)       { W = Wq; T = Tq; K = DIN;  N = DOUT; nbx = 128; }
    else if (bid < 10240) { W = Wk; T = Tk; K = DIN;  N = GKD;  nbx = 32;  bid -= 8192; }
    else if (bid < 12288) { W = Wv; T = Tv; K = DIN;  N = GKD;  nbx = 32;  bid -= 10240; }
    else                  { W = Wo; T = To; K = DOUT; N = DIN;  nbx = 64;  bid -= 12288; }
    const int bn = (bid % nbx) * 32, bk = (bid / nbx) * 32;
    const int tx = threadIdx.x & 31, ty = (threadIdx.x >> 5) * 4;
    #pragma unroll
    for (int j = 0; j < 4; j++)
        t[ty + j][tx] = W[(size_t)(bk + ty + j) * N + bn + tx];
    __syncthreads();
    #pragma unroll
    for (int j = 0; j < 4; j++) {
        float v = t[tx][ty + j];
        T[(size_t)(bn + ty + j) * K + bk + tx] = __float2half_rn(v);
    }
}

// ---------------------------------------------------------------------------
// Tensor-core flash attention, all-single-term fp16, fp32 softmax.
// 104 KB smem -> 2 CTAs/SM. Single barrier per KV tile; load issued
// immediately after the barrier for max overlap. Grid (head, qt-reversed)
// gives LPT scheduling (largest blocks first).
// ---------------------------------------------------------------------------
#define SQA      272
#define Q_BYTES  (128*SQA)
#define KV_TILE  (64*SQA)
#define ATT_SMEM (Q_BYTES + 2*2*KV_TILE)   /* 104448 */

__global__ __launch_bounds__(256, 2) void attn_mma_kernel(
    const __half* __restrict__ Qf, const __half* __restrict__ Kh,
    const __half* __restrict__ Vh, __half* __restrict__ Cf)
{
    extern __shared__ __align__(128) char smem[];
    const uint32_t sb = smem_u32(smem);
    const int h  = blockIdx.x;                     // head
    const int g  = h >> 2;
    const int qt = gridDim.y - 1 - blockIdx.y;     // largest q-tiles first (LPT)
    const int tid = threadIdx.x, wid = tid >> 5, lane = tid & 31;
    const int qbase = qt * 128;

    const uint32_t sQf = sb;
    const uint32_t sKV0 = sb + Q_BYTES;

    {
        const __half* bq = Qf + ((size_t)h * S_LEN + qbase) * HD;
        #pragma unroll
        for (int i = 0; i < 8; i++) {
            int c = tid + (i << 8);
            int r = c >> 4, ch = c & 15;
            cp16(sQf + r * SQA + ch * 16, bq + r * HD + ch * 8);
        }
    }
    auto load_kv = [&](int kt, int buf) {
        uint32_t base = sKV0 + buf * 2 * KV_TILE;
        const size_t gb = ((size_t)g * S_LEN + kt * 64) * HD;
        #pragma unroll
        for (int i = 0; i < 8; i++) {
            int c = tid + (i << 8);
            int arr = c >> 10, w = c & 1023, r = w >> 4, ch = w & 15;
            const __half* src = (arr == 0 ? Kh : Vh) + gb + r * HD + ch * 8;
            cp16(base + arr * KV_TILE + r * SQA + ch * 16, src);
        }
        cp_commit();
    };
    load_kv(0, 0);
    cp_commit();

    float o[16][4];
    #pragma unroll
    for (int nj = 0; nj < 16; nj++)
        #pragma unroll
        for (int q = 0; q < 4; q++) o[nj][q] = 0.f;
    float mA = -1e30f, mB = -1e30f, lA = 0.f, lB = 0.f;

    const int rA = lane >> 2;
    const int colq = (lane & 3) * 2;
    const int ktmax = 2 * qt + 1;

    for (int kt = 0; kt <= ktmax; kt++) {
        cp_wait<0>();
        __syncthreads();                    // single barrier per tile
        if (kt < ktmax) load_kv(kt + 1, (kt + 1) & 1);   // overlaps compute(kt)

        const uint32_t bKh = sKV0 + (kt & 1) * 2 * KV_TILE;
        const uint32_t bVh = bKh + KV_TILE;

        float acc[8][4];
        #pragma unroll
        for (int ni = 0; ni < 8; ni++)
            #pragma unroll
            for (int q = 0; q < 4; q++) acc[ni][q] = 0.f;

        #pragma unroll
        for (int ks = 0; ks < 8; ks++) {
            uint32_t a[4];
            {
                int row = wid * 16 + (lane & 15);
                LDSM4(a, sQf + row * SQA + (ks * 2 + (lane >> 4)) * 16);
            }
            #pragma unroll
            for (int nb = 0; nb < 4; nb++) {
                uint32_t bh[4];
                int row = nb * 16 + (lane & 7) + ((lane >> 4) << 3);
                LDSM4(bh, bKh + row * SQA + (ks * 2 + ((lane >> 3) & 1)) * 16);
                MMA_F16(acc[2*nb],   a, bh[0], bh[1]);
                MMA_F16(acc[2*nb+1], a, bh[2], bh[3]);
            }
        }

        if (kt >= 2 * qt) {
            int qrA = qbase + wid * 16 + rA;
            #pragma unroll
            for (int ni = 0; ni < 8; ni++) {
                int key = kt * 64 + ni * 8 + colq;
                if (key     > qrA)     acc[ni][0] = -1e30f;
                if (key + 1 > qrA)     acc[ni][1] = -1e30f;
                if (key     > qrA + 8) acc[ni][2] = -1e30f;
                if (key + 1 > qrA + 8) acc[ni][3] = -1e30f;
            }
        }

        float mxA = -1e30f, mxB = -1e30f;
        #pragma unroll
        for (int ni = 0; ni < 8; ni++) {
            mxA = fmaxf(mxA, fmaxf(acc[ni][0], acc[ni][1]));
            mxB = fmaxf(mxB, fmaxf(acc[ni][2], acc[ni][3]));
        }
        mxA = fmaxf(mxA, __shfl_xor_sync(0xffffffffu, mxA, 1));
        mxA = fmaxf(mxA, __shfl_xor_sync(0xffffffffu, mxA, 2));
        mxB = fmaxf(mxB, __shfl_xor_sync(0xffffffffu, mxB, 1));
        mxB = fmaxf(mxB, __shfl_xor_sync(0xffffffffu, mxB, 2));
        float nmA = fmaxf(mA, mxA), nmB = fmaxf(mB, mxB);
        float aA = __expf(mA - nmA), aB = __expf(mB - nmB);
        mA = nmA; mB = nmB;
        float sA = 0.f, sB = 0.f;
        #pragma unroll
        for (int ni = 0; ni < 8; ni++) {
            acc[ni][0] = __expf(acc[ni][0] - nmA);
            acc[ni][1] = __expf(acc[ni][1] - nmA);
            acc[ni][2] = __expf(acc[ni][2] - nmB);
            acc[ni][3] = __expf(acc[ni][3] - nmB);
            sA += acc[ni][0] + acc[ni][1];
            sB += acc[ni][2] + acc[ni][3];
        }
        lA = lA * aA + sA;
        lB = lB * aB + sB;
        #pragma unroll
        for (int nj = 0; nj < 16; nj++) {
            o[nj][0] *= aA; o[nj][1] *= aA;
            o[nj][2] *= aB; o[nj][3] *= aB;
        }

        #pragma unroll
        for (int ks = 0; ks < 4; ks++) {
            uint32_t p[4];
            #pragma unroll
            for (int j = 0; j < 4; j++) {
                const float* pr = acc[2 * ks + (j >> 1)];
                p[j] = pack_f16x2(pr[(j & 1) ? 2 : 0], pr[(j & 1) ? 3 : 1]);
            }
            #pragma unroll
            for (int nj = 0; nj < 8; nj++) {
                uint32_t vh[4];
                int row = ks * 16 + (lane & 7) + (((lane >> 3) & 1) << 3);
                LDSM4T(vh, bVh + row * SQA + nj * 32 + (lane >> 4) * 16);
                MMA_F16(o[2*nj],   p, vh[0], vh[1]);
                MMA_F16(o[2*nj+1], p, vh[2], vh[3]);
            }
        }
    }

    float lAt = lA + __shfl_xor_sync(0xffffffffu, lA, 1);
    lAt += __shfl_xor_sync(0xffffffffu, lAt, 2);
    float lBt = lB + __shfl_xor_sync(0xffffffffu, lB, 1);
    lBt += __shfl_xor_sync(0xffffffffu, lBt, 2);
    float invA = 1.f / lAt, invB = 1.f / lBt;

    const int rowA = qbase + wid * 16 + rA;
    uint32_t* C32 = (uint32_t*)Cf;
    #pragma unroll
    for (int nj = 0; nj < 16; nj++) {
        int col = h * HD + nj * 8 + colq;
        float v0 = o[nj][0] * invA, v1 = o[nj][1] * invA;
        float v2 = o[nj][2] * invB, v3 = o[nj][3] * invB;
        C32[(size_t)rowA * (DOUT/2) + (col >> 1)]       = pack_f16x2(v0, v1);
        C32[(size_t)(rowA + 8) * (DOUT/2) + (col >> 1)] = pack_f16x2(v2, v3);
    }
}

// ---------------------------------------------------------------------------
extern "C" void kernel_launch(void* const* d_in, const int* in_sizes, int n_in,
                              void* d_out, int out_size)
{
    const float* x    = (const float*)d_in[0];
    const float* cosp = (const float*)d_in[2];
    const float* sinp = (const float*)d_in[3];
    const float* Wq   = (const float*)d_in[4];
    const float* Wk   = (const float*)d_in[5];
    const float* Wv   = (const float*)d_in[6];
    const float* Wo   = (const float*)d_in[7];
    const float* qsc  = (const float*)d_in[8];
    const float* ksc  = (const float*)d_in[9];

    float* out  = (float*)d_out;
    float* kout = out  + (size_t)S_LEN * DIN;
    float* vout = kout + (size_t)G_KV * S_LEN * HD;

    __half *xf, *cf, *wq16, *wk16, *wv16, *wo16;
    __half *qf, *kh, *vh;
    cudaGetSymbolAddress((void**)&xf,   g_xf16);
    cudaGetSymbolAddress((void**)&cf,   g_cf16);
    cudaGetSymbolAddress((void**)&wq16, g_wqt);
    cudaGetSymbolAddress((void**)&wk16, g_wkt);
    cudaGetSymbolAddress((void**)&wv16, g_wvt);
    cudaGetSymbolAddress((void**)&wo16, g_wot);
    cudaGetSymbolAddress((void**)&qf,   g_qf);
    cudaGetSymbolAddress((void**)&kh,   g_kh);
    cudaGetSymbolAddress((void**)&vh,   g_vh);

    cudaFuncSetAttribute(gemm_qkv_kernel, cudaFuncAttributeMaxDynamicSharedMemorySize, GEMM_SMEM);
    cudaFuncSetAttribute(gemm_wo_kernel,  cudaFuncAttributeMaxDynamicSharedMemorySize, GEMM_SMEM);
    cudaFuncSetAttribute(attn_mma_kernel, cudaFuncAttributeMaxDynamicSharedMemorySize, ATT_SMEM);

    prep_kernel<<<4096 + 20480, 256>>>((const float4*)x, (ushort4*)xf,
                                       Wq, Wk, Wv, Wo, wq16, wk16, wv16, wo16);

    gemm_qkv_kernel<<<dim3(QKV_N/128, S_LEN/128), 256, GEMM_SMEM>>>(
        xf, wq16, wk16, wv16, qsc, ksc, cosp, sinp,
        qf, kout, kh, vout, vh);

    attn_mma_kernel<<<dim3(H_Q, S_LEN/128), 256, ATT_SMEM>>>(qf, kh, vh, cf);

    gemm_wo_kernel<<<dim3(DIN/128, S_LEN/128), 256, GEMM_SMEM>>>(cf, wo16, out, DIN, DOUT);
}